// round 11
// baseline (speedup 1.0000x reference)
#include <cuda_runtime.h>
#include <cuda_bf16.h>
#include <math.h>
#include <stdint.h>

typedef unsigned long long ull;

#define N_NODES 10000
#define N_EDGES 160000
#define HDIM    128
#define NLAYERS 3
#define BN_EPS  1e-5f

#define EDGE_CTA   128
#define EDGE_TILES (N_EDGES / EDGE_CTA)   // 1250
#define NODE_TILES ((N_NODES + 63) / 64)  // 157

// bf16 tile row stride: 136 bf16 = 272 B
#define TROW 272
#define TILE_BYTES (128 * TROW)           // 34816

// ---------------- device scratch ----------------
__device__ float g_coords[N_NODES * 3];
__device__ float g_V[N_NODES * HDIM];
__device__ float g_Vraw[N_NODES * HDIM];   // Pd during edge phase
__device__ float g_VH[N_NODES * HDIM];     // Ps during edge phase
__device__ float g_mi[N_NODES * HDIM];
__device__ float g_accum[N_NODES * 3];
__device__ float g_mij[N_EDGES * HDIM];
__device__ float g_partE[2 * EDGE_TILES * HDIM];
__device__ float g_partN[2 * 160 * HDIM];
__device__ float g_muinv[2 * HDIM];
// bf16 weight images, [layer][mat(We2t,Wx1t)][n*128+k] (row-major [n][k])
__device__ __nv_bfloat16 g_wbhi[NLAYERS * 2 * 16384];
__device__ __nv_bfloat16 g_wblo[NLAYERS * 2 * 16384];

__device__ __forceinline__ float silu_f(float x) { return x / (1.0f + expf(-x)); }
__device__ __forceinline__ float elu_f(float x)  { return x > 0.0f ? x : (expf(x) - 1.0f); }

__device__ __forceinline__ ull fma2(ull a, ull b, ull c) {
    ull d;
    asm("fma.rn.f32x2 %0, %1, %2, %3;" : "=l"(d) : "l"(a), "l"(b), "l"(c));
    return d;
}
__device__ __forceinline__ float2 unpk(ull v) {
    unsigned lo, hi;
    asm("mov.b64 {%0,%1}, %2;" : "=r"(lo), "=r"(hi) : "l"(v));
    return make_float2(__uint_as_float(lo), __uint_as_float(hi));
}
__device__ __forceinline__ ull dup2(float a) {
    ull d;
    asm("mov.b64 %0, {%1,%1};" : "=l"(d) : "f"(a));
    return d;
}
__device__ __forceinline__ void red_add_v2(float* addr, float x, float y) {
    asm volatile("red.global.add.v2.f32 [%0], {%1,%2};"
                 :: "l"(addr), "f"(x), "f"(y) : "memory");
}

__device__ __forceinline__ uint32_t pk_bf2(float x, float y) {
    __nv_bfloat162 t = __floats2bfloat162_rn(x, y);
    return *(uint32_t*)&t;
}
__device__ __forceinline__ float bf_hi(float x) {
    return __bfloat162float(__float2bfloat16(x));
}

// mma.sync m16n8k16 bf16
__device__ __forceinline__ void mma16816(float* d, uint32_t a0, uint32_t a1,
                                         uint32_t a2, uint32_t a3,
                                         uint32_t b0, uint32_t b1) {
    asm("mma.sync.aligned.m16n8k16.row.col.f32.bf16.bf16.f32 "
        "{%0,%1,%2,%3}, {%4,%5,%6,%7}, {%8,%9}, {%0,%1,%2,%3};"
        : "+f"(d[0]), "+f"(d[1]), "+f"(d[2]), "+f"(d[3])
        : "r"(a0), "r"(a1), "r"(a2), "r"(a3), "r"(b0), "r"(b1));
}

// warp GEMM: 32 rows (two m16 frags) x 64 cols (8 n-tiles), bf16 split-3.
// Per ks-step: 8 A-LDS + 16 B-LDS feed 16 HMMAs. acc = 64 regs.
// abase = (rowgroup*32 + g)*TROW + q*4 ; bbase = (colhalf*64 + g)*TROW + q*4.
__device__ __forceinline__ void warp_gemm3h(float (&acc)[2][8][4],
                                            const char* Ah, const char* Al,
                                            const char* Bh, const char* Bl,
                                            int abase, int bbase)
{
#pragma unroll
    for (int mt = 0; mt < 2; mt++)
#pragma unroll
        for (int i = 0; i < 8; i++)
#pragma unroll
            for (int j = 0; j < 4; j++) acc[mt][i][j] = 0.f;

#pragma unroll 1
    for (int sp = 0; sp < 3; sp++) {
        const char* A = (sp == 1) ? Al : Ah;
        const char* B = (sp == 2) ? Bl : Bh;
#pragma unroll 2
        for (int ks = 0; ks < 8; ks++) {
            const char* ap = A + abase + ks * 32;
            uint32_t a00 = *(const uint32_t*)(ap);
            uint32_t a02 = *(const uint32_t*)(ap + 16);
            uint32_t a01 = *(const uint32_t*)(ap + 8 * TROW);
            uint32_t a03 = *(const uint32_t*)(ap + 8 * TROW + 16);
            uint32_t a10 = *(const uint32_t*)(ap + 16 * TROW);
            uint32_t a12 = *(const uint32_t*)(ap + 16 * TROW + 16);
            uint32_t a11 = *(const uint32_t*)(ap + 24 * TROW);
            uint32_t a13 = *(const uint32_t*)(ap + 24 * TROW + 16);
            const char* bp = B + bbase + ks * 32;
#pragma unroll
            for (int nt = 0; nt < 8; nt++) {
                uint32_t b0 = *(const uint32_t*)(bp + nt * 8 * TROW);
                uint32_t b1 = *(const uint32_t*)(bp + nt * 8 * TROW + 16);
                mma16816(acc[0][nt], a00, a01, a02, a03, b0, b1);
                mma16816(acc[1][nt], a10, a11, a12, a13, b0, b1);
            }
        }
    }
}

// ---------------- weight pre-convert: W[k][n] f32 -> bf16 hi/lo [n][k] ------
__global__ void convw_k(const float* __restrict__ We2, const float* __restrict__ Wx1)
{
    int idx = blockIdx.x * 256 + threadIdx.x;
    if (idx >= NLAYERS * 2 * 16384) return;
    int l = idx / 32768;
    int rest = idx % 32768;
    int m = rest >> 14;
    int e = rest & 16383;
    int n = e >> 7, k = e & 127;
    const float* W = m ? (Wx1 + (size_t)l * 16384) : (We2 + (size_t)l * 16384);
    float x = W[k * 128 + n];
    __nv_bfloat16 h = __float2bfloat16(x);
    __nv_bfloat16 lo = __float2bfloat16(x - __bfloat162float(h));
    g_wbhi[(l * 2 + m) * 16384 + n * 128 + k] = h;
    g_wblo[(l * 2 + m) * 16384 + n * 128 + k] = lo;
}

// ---------------- fused edge pipeline: 128 edges/CTA, warp = 32r x 64c ------
// smem float offsets:
//  diffs 0 (384) | dists 384 (128) | dsts 512 (128) | ee0s 640 | ee1s 768
//  wex 896 (384) | be1s 1280 | be2s 1408 | bx1s 1536 | wx2s 1664 (384)
//  bx2s 2048 (4) | es 2052 (256) | end 2308 -> pad to byte 9248
__global__ __launch_bounds__(256)
void edge_mma_k(const int* __restrict__ srcv, const int* __restrict__ dstv,
                const float* __restrict__ ee,
                const float* __restrict__ Ps, const float* __restrict__ Pd,
                const float* __restrict__ wex_g, const float* __restrict__ be1,
                const float* __restrict__ be2, const float* __restrict__ bx1,
                const float* __restrict__ Wx2, const float* __restrict__ bx2,
                const __nv_bfloat16* __restrict__ WBhi,
                const __nv_bfloat16* __restrict__ WBlo,
                int write_mij)
{
    extern __shared__ char smc[];
    float* smf = (float*)smc;
    float* diffs = smf + 0;
    float* dists = smf + 384;
    int*   dsts  = (int*)(smf + 512);
    float* ee0s  = smf + 640;
    float* ee1s  = smf + 768;
    float* wex   = smf + 896;
    float* be1s  = smf + 1280;
    float* be2s  = smf + 1408;
    float* bx1s  = smf + 1536;
    float* wx2s  = smf + 1664;
    float* bx2s  = smf + 2048;
    float* es    = smf + 2052;
    char* Ah = smc + 9248;
    char* Al = Ah + TILE_BYTES;
    char* Bh = Al + TILE_BYTES;
    char* Bl = Bh + TILE_BYTES;

    const int tid  = threadIdx.x;
    const int wid  = tid >> 5;
    const int lane = tid & 31;
    const int g    = lane >> 2;
    const int q    = lane & 3;
    const int ch   = wid >> 2;        // col half 0/1
    const int rg   = wid & 3;         // row group 0..3
    const int m0   = blockIdx.x * EDGE_CTA;

    // ---- phase 0: per-edge meta, biases, B1 tiles ----
    if (tid < 128) {
        int mm = m0 + tid;
        int s = srcv[mm], d = dstv[mm];
        float dx = g_coords[d * 3 + 0] - g_coords[s * 3 + 0];
        float dy = g_coords[d * 3 + 1] - g_coords[s * 3 + 1];
        float dz = g_coords[d * 3 + 2] - g_coords[s * 3 + 2];
        diffs[tid * 3 + 0] = dx;
        diffs[tid * 3 + 1] = dy;
        diffs[tid * 3 + 2] = dz;
        dists[tid] = sqrtf(dx * dx + dy * dy + dz * dz);
        dsts[tid] = d;
        ee0s[tid] = ee[mm * 2 + 0];
        ee1s[tid] = ee[mm * 2 + 1];
        be1s[tid] = be1[tid];
        be2s[tid] = be2[tid];
        bx1s[tid] = bx1[tid];
    }
    es[tid] = 0.f;
    for (int i = tid; i < 384; i += 256) { wex[i] = wex_g[i]; wx2s[i] = Wx2[i]; }
    if (tid < 3) bx2s[tid] = bx2[tid];

    // copy We2t hi/lo tiles: 128 rows x 16 uint4 = 2048 uint4 each
    {
        const uint4* shi = (const uint4*)WBhi;
        const uint4* slo = (const uint4*)WBlo;
#pragma unroll
        for (int i = 0; i < 8; i++) {
            int p = tid + i * 256;          // 0..2047
            int row = p >> 4, chunk = p & 15;
            *(uint4*)(Bh + row * TROW + chunk * 16) = shi[p];
            *(uint4*)(Bl + row * TROW + chunk * 16) = slo[p];
        }
    }
    __syncthreads();

    // ---- T1 build: 2 threads per edge row (64 cols each) ----
    {
        const int r  = tid >> 1;
        const int cb = (tid & 1) * 64;
        const int mm = m0 + r;
        const int s  = srcv[mm];
        const float* psp = Ps + (size_t)s * 128;
        const float* pdp = Pd + (size_t)dsts[r] * 128;
        const float di = dists[r];
        const float e0 = ee0s[r], e1 = ee1s[r];
        for (int c = cb; c < cb + 64; c += 8) {
            float o[8];
#pragma unroll
            for (int h = 0; h < 8; h += 4) {
                float4 a = *(const float4*)(psp + c + h);
                float4 b = *(const float4*)(pdp + c + h);
                o[h+0] = silu_f(a.x + b.x + di * wex[c+h+0] + e0 * wex[128+c+h+0] + e1 * wex[256+c+h+0] + be1s[c+h+0]);
                o[h+1] = silu_f(a.y + b.y + di * wex[c+h+1] + e0 * wex[128+c+h+1] + e1 * wex[256+c+h+1] + be1s[c+h+1]);
                o[h+2] = silu_f(a.z + b.z + di * wex[c+h+2] + e0 * wex[128+c+h+2] + e1 * wex[256+c+h+2] + be1s[c+h+2]);
                o[h+3] = silu_f(a.w + b.w + di * wex[c+h+3] + e0 * wex[128+c+h+3] + e1 * wex[256+c+h+3] + be1s[c+h+3]);
            }
            uint32_t H[4], L[4];
#pragma unroll
            for (int j = 0; j < 4; j++) {
                float hx = bf_hi(o[2*j]), hy = bf_hi(o[2*j+1]);
                H[j] = pk_bf2(o[2*j], o[2*j+1]);
                L[j] = pk_bf2(o[2*j] - hx, o[2*j+1] - hy);
            }
            *(uint4*)(Ah + r * TROW + c * 2) = *(uint4*)H;
            *(uint4*)(Al + r * TROW + c * 2) = *(uint4*)L;
        }
    }
    __syncthreads();

    const int abase = (rg * 32 + g) * TROW + q * 4;
    const int bbase = (ch * 64 + g) * TROW + q * 4;
    const int r0 = rg * 32 + g;   // warp rows: r0, +8, +16, +24

    float acc[2][8][4];

    // ---- GEMM1: D = T1 @ We2t^T ----
    warp_gemm3h(acc, Ah, Al, Bh, Bl, abase, bbase);

    // ---- epilogue 1: mij = silu(D + be2); mi scatter; mij/stats; A := mij --
    {
#pragma unroll
        for (int nt = 0; nt < 8; nt++) {
            const int c = ch * 64 + nt * 8 + q * 2;
            const float bc0 = be2s[c], bc1 = be2s[c + 1];
            float s0 = 0.f, s1 = 0.f, q0 = 0.f, q1 = 0.f;
#pragma unroll
            for (int mt = 0; mt < 2; mt++) {
                const int ra = r0 + mt * 16;
                const int rb = ra + 8;
                float v00 = silu_f(acc[mt][nt][0] + bc0);
                float v01 = silu_f(acc[mt][nt][1] + bc1);
                float v10 = silu_f(acc[mt][nt][2] + bc0);
                float v11 = silu_f(acc[mt][nt][3] + bc1);
                red_add_v2(&g_mi[(size_t)dsts[ra] * 128 + c], v00, v01);
                red_add_v2(&g_mi[(size_t)dsts[rb] * 128 + c], v10, v11);
                if (write_mij) {
                    *(float2*)(g_mij + (size_t)(m0 + ra) * 128 + c) = make_float2(v00, v01);
                    *(float2*)(g_mij + (size_t)(m0 + rb) * 128 + c) = make_float2(v10, v11);
                    float e00 = elu_f(v00), e01 = elu_f(v01);
                    float e10 = elu_f(v10), e11 = elu_f(v11);
                    s0 += e00 + e10;           s1 += e01 + e11;
                    q0 += e00 * e00 + e10 * e10;
                    q1 += e01 * e01 + e11 * e11;
                }
                float h00 = bf_hi(v00), h01 = bf_hi(v01);
                float h10 = bf_hi(v10), h11 = bf_hi(v11);
                *(uint32_t*)(Ah + ra * TROW + c * 2) = pk_bf2(v00, v01);
                *(uint32_t*)(Ah + rb * TROW + c * 2) = pk_bf2(v10, v11);
                *(uint32_t*)(Al + ra * TROW + c * 2) = pk_bf2(v00 - h00, v01 - h01);
                *(uint32_t*)(Al + rb * TROW + c * 2) = pk_bf2(v10 - h10, v11 - h11);
            }
            if (write_mij) {
#pragma unroll
                for (int o = 4; o < 32; o <<= 1) {
                    s0 += __shfl_xor_sync(0xFFFFFFFF, s0, o);
                    s1 += __shfl_xor_sync(0xFFFFFFFF, s1, o);
                    q0 += __shfl_xor_sync(0xFFFFFFFF, q0, o);
                    q1 += __shfl_xor_sync(0xFFFFFFFF, q1, o);
                }
                if (lane < 4) {
                    atomicAdd(&es[c], s0);
                    atomicAdd(&es[c + 1], s1);
                    atomicAdd(&es[128 + c], q0);
                    atomicAdd(&es[128 + c + 1], q1);
                }
            }
        }
    }
    // barrier: all GEMM1 B reads + A rewrites complete before B overwrite
    __syncthreads();
    if (write_mij && tid < 128) {
        g_partE[blockIdx.x * 128 + tid] = es[tid];
        g_partE[(EDGE_TILES + blockIdx.x) * 128 + tid] = es[128 + tid];
    }
    // overwrite B tiles with Wx1t hi/lo
    {
        const uint4* shi = (const uint4*)(WBhi + 16384);
        const uint4* slo = (const uint4*)(WBlo + 16384);
#pragma unroll
        for (int i = 0; i < 8; i++) {
            int p = tid + i * 256;
            int row = p >> 4, chunk = p & 15;
            *(uint4*)(Bh + row * TROW + chunk * 16) = shi[p];
            *(uint4*)(Bl + row * TROW + chunk * 16) = slo[p];
        }
    }
    __syncthreads();

    // ---- GEMM2: D = mij @ Wx1t^T ----
    warp_gemm3h(acc, Ah, Al, Bh, Bl, abase, bbase);

    // ---- epilogue 2: T2 = silu(D + bx1); px partial over this col half ----
    {
        float p0[4] = {0.f, 0.f, 0.f, 0.f};
        float p1[4] = {0.f, 0.f, 0.f, 0.f};
        float p2[4] = {0.f, 0.f, 0.f, 0.f};
#pragma unroll
        for (int nt = 0; nt < 8; nt++) {
            const int c = ch * 64 + nt * 8 + q * 2;
            const float bc0 = bx1s[c], bc1 = bx1s[c + 1];
            float w00 = wx2s[c * 3 + 0], w01 = wx2s[c * 3 + 1], w02 = wx2s[c * 3 + 2];
            float w10 = wx2s[c * 3 + 3], w11 = wx2s[c * 3 + 4], w12 = wx2s[c * 3 + 5];
#pragma unroll
            for (int mt = 0; mt < 2; mt++) {
                float ta0 = silu_f(acc[mt][nt][0] + bc0);
                float ta1 = silu_f(acc[mt][nt][1] + bc1);
                float tb0 = silu_f(acc[mt][nt][2] + bc0);
                float tb1 = silu_f(acc[mt][nt][3] + bc1);
                p0[mt * 2]     += ta0 * w00 + ta1 * w10;
                p1[mt * 2]     += ta0 * w01 + ta1 * w11;
                p2[mt * 2]     += ta0 * w02 + ta1 * w12;
                p0[mt * 2 + 1] += tb0 * w00 + tb1 * w10;
                p1[mt * 2 + 1] += tb0 * w01 + tb1 * w11;
                p2[mt * 2 + 1] += tb0 * w02 + tb1 * w12;
            }
        }
#pragma unroll
        for (int o = 1; o < 4; o <<= 1) {
#pragma unroll
            for (int j = 0; j < 4; j++) {
                p0[j] += __shfl_xor_sync(0xFFFFFFFF, p0[j], o);
                p1[j] += __shfl_xor_sync(0xFFFFFFFF, p1[j], o);
                p2[j] += __shfl_xor_sync(0xFFFFFFFF, p2[j], o);
            }
        }
        if (q == 0) {
            // p index j: mt0 -> {j0:r0, j1:r0+8}, mt1 -> {j2:r0+16, j3:r0+24}
            const int rows[4] = {r0, r0 + 8, r0 + 16, r0 + 24};
            // col-half 0 warps add the bx2 bias term exactly once per edge
            const float bxa = (ch == 0) ? bx2s[0] : 0.f;
            const float bxb = (ch == 0) ? bx2s[1] : 0.f;
            const float bxc = (ch == 0) ? bx2s[2] : 0.f;
#pragma unroll
            for (int j = 0; j < 4; j++) {
                const int r = rows[j];
                const int d = dsts[r];
                float x0 = p0[j] + bxa;
                float x1 = p1[j] + bxb;
                float x2 = p2[j] + bxc;
                atomicAdd(&g_accum[d * 3 + 0], diffs[r * 3 + 0] * x0);
                atomicAdd(&g_accum[d * 3 + 1], diffs[r * 3 + 1] * x1);
                atomicAdd(&g_accum[d * 3 + 2], diffs[r * 3 + 2] * x2);
            }
        }
    }
}

// ---------------- node side (unchanged from R8) ----------------
__device__ __forceinline__ int ts_off(int r, int c) {
    return r * 132 + ((r >> 3) & 1) * 4 + c;
}

__device__ __forceinline__ void gemm_tile4(ull (&acc)[4][4], const float* Ts,
                                           const float* Bs, int kbase,
                                           int row0, int col0)
{
    const float* arow = Ts + row0 * 132 + ((row0 >> 3) & 1) * 4 + kbase;
#pragma unroll
    for (int kk = 0; kk < 16; kk += 2) {
        const float* bp0 = Bs + kk * 132 + col0;
        const float* bp1 = bp0 + 132;
        ulonglong2 b01a = *(const ulonglong2*)bp0;
        ulonglong2 b23a = *(const ulonglong2*)(bp0 + 4);
        ulonglong2 b01b = *(const ulonglong2*)bp1;
        ulonglong2 b23b = *(const ulonglong2*)(bp1 + 4);
#pragma unroll
        for (int i = 0; i < 4; i++) {
            float2 a2 = *(const float2*)&arow[i * 132 + kk];
            ull av0 = dup2(a2.x), av1 = dup2(a2.y);
            acc[i][0] = fma2(av0, b01a.x, acc[i][0]);
            acc[i][1] = fma2(av0, b01a.y, acc[i][1]);
            acc[i][2] = fma2(av0, b23a.x, acc[i][2]);
            acc[i][3] = fma2(av0, b23a.y, acc[i][3]);
            acc[i][0] = fma2(av1, b01b.x, acc[i][0]);
            acc[i][1] = fma2(av1, b01b.y, acc[i][1]);
            acc[i][2] = fma2(av1, b23b.x, acc[i][2]);
            acc[i][3] = fma2(av1, b23b.y, acc[i][3]);
        }
    }
}

__global__ __launch_bounds__(256) void proj_k(
    const float* __restrict__ V, const float* __restrict__ We1l,
    float* __restrict__ Ps, float* __restrict__ Pd, int M)
{
    __shared__ float As[16][68];
    __shared__ float Bs[16][264];

    const int tid  = threadIdx.x;
    const int m0   = blockIdx.x * 64;
    const int arow = tid >> 2;
    const int akb  = (tid & 3) * 4;
    const int brow = tid >> 4;
    const int bcol = (tid & 15) * 16;
    const int gm   = m0 + arow;
    const bool mval = (gm < M);
    const int row0 = (tid >> 4) * 4;
    const int col0 = (tid & 15) * 16;

    {
        int r = tid >> 2, c = (tid & 3) * 32;
        if (m0 + r < M) {
            float4 z = make_float4(0.f, 0.f, 0.f, 0.f);
            float* p = g_mi + (size_t)(m0 + r) * 128 + c;
#pragma unroll
            for (int j = 0; j < 8; j++) *(float4*)(p + j * 4) = z;
        }
        if (tid < 192 && m0 + tid / 3 < M)
            g_accum[(size_t)m0 * 3 + tid] = 0.f;
    }

    float acc[4][16];
#pragma unroll
    for (int i = 0; i < 4; i++)
#pragma unroll
        for (int j = 0; j < 16; j++) acc[i][j] = 0.f;

    for (int kt = 0; kt < 8; kt++) {
        const int kbase = kt * 16;
        {
            const int gk = kbase + brow;
            const float* wp = (bcol < 128)
                ? We1l + (size_t)gk * 128 + bcol
                : We1l + (size_t)(128 + gk) * 128 + (bcol - 128);
#pragma unroll
            for (int j = 0; j < 16; j += 4)
                *(float4*)&Bs[brow][bcol + j] = *(const float4*)(wp + j);
        }
#pragma unroll
        for (int i = 0; i < 4; i++) {
            const int gk = kbase + akb + i;
            As[akb + i][arow] = mval ? V[(size_t)gm * 128 + gk] : 0.f;
        }
        __syncthreads();
#pragma unroll
        for (int kk = 0; kk < 16; kk++) {
            float4 a = *(const float4*)&As[kk][row0];
            float av[4] = {a.x, a.y, a.z, a.w};
            float bv[16];
#pragma unroll
            for (int j = 0; j < 16; j += 4)
                *(float4*)&bv[j] = *(const float4*)&Bs[kk][col0 + j];
#pragma unroll
            for (int i = 0; i < 4; i++)
#pragma unroll
                for (int j = 0; j < 16; j++) acc[i][j] += av[i] * bv[j];
        }
        __syncthreads();
    }

#pragma unroll
    for (int i = 0; i < 4; i++) {
        const int mm = m0 + row0 + i;
        if (mm < M) {
            float* cp = (col0 < 128)
                ? Ps + (size_t)mm * 128 + col0
                : Pd + (size_t)mm * 128 + (col0 - 128);
#pragma unroll
            for (int j = 0; j < 16; j += 4)
                *(float4*)(cp + j) = *(float4*)&acc[i][j];
        }
    }
}

__global__ __launch_bounds__(256) void node_fused_k(
    const float* __restrict__ V, const float* __restrict__ mi,
    const float* __restrict__ Wh1, const float* __restrict__ bh1,
    const float* __restrict__ Wh2, const float* __restrict__ bh2,
    float* __restrict__ Vraw, float* __restrict__ part, int M, int nblk)
{
    __shared__ float VH[64 * 132 + 4];
    __shared__ float As[16][68];
    __shared__ float Bs[16][132];
    __shared__ float sstat[256];

    const int tid  = threadIdx.x;
    const int m0   = blockIdx.x * 64;
    const int arow = tid >> 2;
    const int akb  = (tid & 3) * 4;
    const int brow = tid >> 4;
    const int bcol = (tid & 15) * 8;
    const int gm   = m0 + arow;
    const bool mval = (gm < M);
    const int row0 = (tid >> 4) * 4;
    const int col0 = (tid & 15) * 8;

    sstat[tid] = 0.f;

    float accA[4][8];
#pragma unroll
    for (int i = 0; i < 4; i++)
#pragma unroll
        for (int j = 0; j < 8; j++) accA[i][j] = 0.f;

    for (int kt = 0; kt < 16; kt++) {
        const int kbase = kt * 16;
        {
            const float* wp = Wh1 + (size_t)(kbase + brow) * 128 + bcol;
#pragma unroll
            for (int j = 0; j < 8; j += 4)
                *(float4*)&Bs[brow][bcol + j] = *(const float4*)(wp + j);
        }
#pragma unroll
        for (int i = 0; i < 4; i++) {
            const int gk = kbase + akb + i;
            float v = 0.f;
            if (mval)
                v = (gk < 128) ? V[(size_t)gm * 128 + gk]
                               : mi[(size_t)gm * 128 + (gk - 128)];
            As[akb + i][arow] = v;
        }
        __syncthreads();
#pragma unroll
        for (int kk = 0; kk < 16; kk++) {
            float4 a = *(const float4*)&As[kk][row0];
            float4 b0 = *(const float4*)&Bs[kk][col0];
            float4 b1 = *(const float4*)&Bs[kk][col0 + 4];
            float av[4] = {a.x, a.y, a.z, a.w};
            float bv[8] = {b0.x, b0.y, b0.z, b0.w, b1.x, b1.y, b1.z, b1.w};
#pragma unroll
            for (int i = 0; i < 4; i++)
#pragma unroll
                for (int j = 0; j < 8; j++) accA[i][j] += av[i] * bv[j];
        }
        __syncthreads();
    }
    {
        float b[8];
        *(float4*)b       = *(const float4*)(bh1 + col0);
        *(float4*)(b + 4) = *(const float4*)(bh1 + col0 + 4);
#pragma unroll
        for (int i = 0; i < 4; i++) {
            float* trow = VH + ts_off(row0 + i, col0);
            float o[8];
#pragma unroll
            for (int j = 0; j < 8; j++) o[j] = silu_f(accA[i][j] + b[j]);
            *(float4*)trow       = *(float4*)&o[0];
            *(float4*)(trow + 4) = *(float4*)&o[4];
        }
    }
    __syncthreads();

    ull acc[4][4];
#pragma unroll
    for (int i = 0; i < 4; i++)
#pragma unroll
        for (int j = 0; j < 4; j++) acc[i][j] = 0ULL;

    for (int kt = 0; kt < 8; kt++) {
        const int kbase = kt * 16;
        {
            const float* wp = Wh2 + (size_t)(kbase + brow) * 128 + bcol;
#pragma unroll
            for (int j = 0; j < 8; j += 4)
                *(float4*)&Bs[brow][bcol + j] = *(const float4*)(wp + j);
        }
        __syncthreads();
        gemm_tile4(acc, VH, &Bs[0][0], kbase, row0, col0);
        __syncthreads();
    }
    {
        float b[8];
        *(float4*)b       = *(const float4*)(bh2 + col0);
        *(float4*)(b + 4) = *(const float4*)(bh2 + col0 + 4);
        float cs[8], cq[8];
#pragma unroll
        for (int j = 0; j < 8; j++) { cs[j] = 0.f; cq[j] = 0.f; }
#pragma unroll
        for (int i = 0; i < 4; i++) {
            const int mm = m0 + row0 + i;
            if (mm < M) {
                float o[8];
#pragma unroll
                for (int jp = 0; jp < 4; jp++) {
                    float2 c = unpk(acc[i][jp]);
                    o[2 * jp]     = c.x + b[2 * jp];
                    o[2 * jp + 1] = c.y + b[2 * jp + 1];
                }
                float* cp = Vraw + (size_t)mm * 128 + col0;
                *(float4*)cp       = *(float4*)&o[0];
                *(float4*)(cp + 4) = *(float4*)&o[4];
#pragma unroll
                for (int j = 0; j < 8; j++) {
                    float e = elu_f(o[j]);
                    cs[j] += e;
                    cq[j] += e * e;
                }
            }
        }
        __syncthreads();
#pragma unroll
        for (int j = 0; j < 8; j++) {
            atomicAdd(&sstat[col0 + j], cs[j]);
            atomicAdd(&sstat[128 + col0 + j], cq[j]);
        }
        __syncthreads();
        if (tid < 128) {
            part[blockIdx.x * 128 + tid] = sstat[tid];
            part[(nblk + blockIdx.x) * 128 + tid] = sstat[128 + tid];
        }
    }
}

// ---------------- small kernels ----------------
__global__ void init_nodes_k(const float* __restrict__ emb,
                             const float* __restrict__ Wn,
                             const float* __restrict__ bn)
{
    int idx = blockIdx.x * blockDim.x + threadIdx.x;
    if (idx < N_NODES * 3) g_coords[idx] = emb[idx];
    if (idx < N_NODES * HDIM) {
        int n = idx >> 7, j = idx & 127;
        g_V[idx] = emb[n * 3 + 0] * Wn[0 * 128 + j]
                 + emb[n * 3 + 1] * Wn[1 * 128 + j]
                 + emb[n * 3 + 2] * Wn[2 * 128 + j]
                 + bn[j];
    }
}

__global__ void coords_update_k()
{
    int idx = blockIdx.x * blockDim.x + threadIdx.x;
    if (idx < N_NODES * 3)
        g_coords[idx] += g_accum[idx] * (1.0f / (float)(N_NODES - 1));
}

__global__ void bn_stats2_k(const float* __restrict__ part, int B, int M)
{
    int j = threadIdx.x;
    double s = 0.0, q = 0.0;
    for (int b = 0; b < B; b++) {
        s += (double)part[b * 128 + j];
        q += (double)part[(B + b) * 128 + j];
    }
    double mu  = s / (double)M;
    double var = q / (double)M - mu * mu;
    g_muinv[j]       = (float)mu;
    g_muinv[128 + j] = (float)rsqrt(var + (double)BN_EPS);
}

__global__ void bn_norm_k(const float* __restrict__ X,
                          const float* __restrict__ gam,
                          const float* __restrict__ bet,
                          float* __restrict__ out, int M)
{
    int idx = blockIdx.x * blockDim.x + threadIdx.x;
    if (idx >= M * 128) return;
    int j = idx & 127;
    float x = elu_f(X[idx]);
    out[idx] = gam[j] * (x - g_muinv[j]) * g_muinv[128 + j] + bet[j];
}

// ---------------- host launcher ----------------
static void* sym_addr(const void* sym)
{
    void* p = nullptr;
    cudaGetSymbolAddress(&p, sym);
    return p;
}

extern "C" void kernel_launch(void* const* d_in, const int* in_sizes, int n_in,
                              void* d_out, int out_size)
{
    (void)in_sizes; (void)n_in; (void)out_size;

    const float* emb_nodes = (const float*)d_in[0];
    const float* emb_edges = (const float*)d_in[1];
    const int*   edge_idx  = (const int*)d_in[2];
    const float* pre_Wn    = (const float*)d_in[3];
    const float* pre_bn    = (const float*)d_in[4];
    const float* We1 = (const float*)d_in[7];
    const float* be1 = (const float*)d_in[8];
    const float* We2 = (const float*)d_in[9];
    const float* be2 = (const float*)d_in[10];
    const float* Wx1 = (const float*)d_in[11];
    const float* bx1 = (const float*)d_in[12];
    const float* Wx2 = (const float*)d_in[13];
    const float* bx2 = (const float*)d_in[14];
    const float* Wh1 = (const float*)d_in[15];
    const float* bh1 = (const float*)d_in[16];
    const float* Wh2 = (const float*)d_in[17];
    const float* bh2 = (const float*)d_in[18];
    const float* gam_n = (const float*)d_in[19];
    const float* bet_n = (const float*)d_in[20];
    const float* gam_e = (const float*)d_in[21];
    const float* bet_e = (const float*)d_in[22];

    float* out  = (float*)d_out;
    float* outV = out;
    float* outE = out + (size_t)N_NODES * HDIM;

    const int* srcv = edge_idx;
    const int* dstv = edge_idx + N_EDGES;

    float* pV     = (float*)sym_addr(g_V);
    float* pVraw  = (float*)sym_addr(g_Vraw);
    float* pVH    = (float*)sym_addr(g_VH);
    float* pMi    = (float*)sym_addr(g_mi);
    float* pMij   = (float*)sym_addr(g_mij);
    float* pPartE = (float*)sym_addr(g_partE);
    float* pPartN = (float*)sym_addr(g_partN);
    __nv_bfloat16* pWbhi = (__nv_bfloat16*)sym_addr(g_wbhi);
    __nv_bfloat16* pWblo = (__nv_bfloat16*)sym_addr(g_wblo);

    const int EDGE_SMEM = 9248 + 4 * TILE_BYTES;   // 148512
    cudaFuncSetAttribute(edge_mma_k,
                         cudaFuncAttributeMaxDynamicSharedMemorySize, EDGE_SMEM);

    const int TB = 256;
    const int nodeHBlocks = (N_NODES * HDIM + TB - 1) / TB;
    const int edgeHBlocks = (N_EDGES * HDIM + TB - 1) / TB;

    init_nodes_k<<<nodeHBlocks, TB>>>(emb_nodes, pre_Wn, pre_bn);
    convw_k<<<(NLAYERS * 2 * 16384 + 255) / 256, 256>>>(We2, Wx1);

    for (int l = 0; l < NLAYERS; l++) {
        const float* We1l = We1 + (size_t)l * 259 * 128;
        const float* be1l = be1 + l * 128;
        const float* be2l = be2 + l * 128;
        const float* bx1l = bx1 + l * 128;
        const float* Wx2l = Wx2 + (size_t)l * 128 * 3;
        const float* bx2l = bx2 + l * 3;
        const float* Wh1l = Wh1 + (size_t)l * 256 * 128;
        const float* bh1l = bh1 + l * 128;
        const float* Wh2l = Wh2 + (size_t)l * 128 * 128;
        const float* bh2l = bh2 + l * 128;

        proj_k<<<NODE_TILES, 256>>>(pV, We1l, pVH, pVraw, N_NODES);

        edge_mma_k<<<EDGE_TILES, 256, EDGE_SMEM>>>(
            srcv, dstv, emb_edges, pVH, pVraw,
            We1l + 256 * 128, be1l, be2l, bx1l, Wx2l, bx2l,
            pWbhi + (size_t)l * 2 * 16384, pWblo + (size_t)l * 2 * 16384,
            (l == NLAYERS - 1) ? 1 : 0);

        coords_update_k<<<(N_NODES * 3 + TB - 1) / TB, TB>>>();

        node_fused_k<<<NODE_TILES, 256>>>(
            pV, pMi, Wh1l, bh1l, Wh2l, bh2l,
            pVraw, pPartN, N_NODES, NODE_TILES);

        bn_stats2_k<<<1, 128>>>(pPartN, NODE_TILES, N_NODES);
        float* vdst = (l == NLAYERS - 1) ? outV : pV;
        bn_norm_k<<<nodeHBlocks, TB>>>(pVraw, gam_n + l * 128, bet_n + l * 128,
                                       vdst, N_NODES);

        if (l == NLAYERS - 1) {
            bn_stats2_k<<<1, 128>>>(pPartE, EDGE_TILES, N_EDGES);
            bn_norm_k<<<edgeHBlocks, TB>>>(pMij, gam_e + l * 128, bet_e + l * 128,
                                           outE, N_EDGES);
        }
    }
}

// round 12
// speedup vs baseline: 1.5105x; 1.5105x over previous
#include <cuda_runtime.h>
#include <cuda_bf16.h>
#include <math.h>
#include <stdint.h>

typedef unsigned long long ull;

#define N_NODES 10000
#define N_EDGES 160000
#define HDIM    128
#define NLAYERS 3
#define BN_EPS  1e-5f

#define EDGE_TILES (N_EDGES / 128)        // 1250
#define NODE_TILES ((N_NODES + 63) / 64)  // 157

// bf16 tile geometry: 128 rows x 128 cols, row stride 136 bf16 (272 B)
#define TROW 272
#define TILE_BYTES (128 * TROW)           // 34816

// ---------------- device scratch ----------------
__device__ float g_coords[N_NODES * 3];
__device__ float g_V[N_NODES * HDIM];
__device__ float g_Vraw[N_NODES * HDIM];   // Pd during edge phase
__device__ float g_VH[N_NODES * HDIM];     // Ps during edge phase
__device__ float g_mi[N_NODES * HDIM];
__device__ float g_accum[N_NODES * 3];
__device__ float g_mij[N_EDGES * HDIM];
__device__ float g_partE[2 * EDGE_TILES * HDIM];
__device__ float g_partN[2 * 160 * HDIM];
__device__ float g_muinv[2 * HDIM];
// bf16 weight images, [layer][mat(We2t,Wx1t)][n*128+k] (row-major [n][k])
__device__ __nv_bfloat16 g_wbhi[NLAYERS * 2 * 16384];
__device__ __nv_bfloat16 g_wblo[NLAYERS * 2 * 16384];

__device__ __forceinline__ float silu_f(float x) { return x / (1.0f + expf(-x)); }
__device__ __forceinline__ float elu_f(float x)  { return x > 0.0f ? x : (expf(x) - 1.0f); }

__device__ __forceinline__ ull fma2(ull a, ull b, ull c) {
    ull d;
    asm("fma.rn.f32x2 %0, %1, %2, %3;" : "=l"(d) : "l"(a), "l"(b), "l"(c));
    return d;
}
__device__ __forceinline__ float2 unpk(ull v) {
    unsigned lo, hi;
    asm("mov.b64 {%0,%1}, %2;" : "=r"(lo), "=r"(hi) : "l"(v));
    return make_float2(__uint_as_float(lo), __uint_as_float(hi));
}
__device__ __forceinline__ ull dup2(float a) {
    ull d;
    asm("mov.b64 %0, {%1,%1};" : "=l"(d) : "f"(a));
    return d;
}
__device__ __forceinline__ void red_add_v2(float* addr, float x, float y) {
    asm volatile("red.global.add.v2.f32 [%0], {%1,%2};"
                 :: "l"(addr), "f"(x), "f"(y) : "memory");
}

__device__ __forceinline__ uint32_t pk_bf2(float x, float y) {
    __nv_bfloat162 t = __floats2bfloat162_rn(x, y);
    return *(uint32_t*)&t;
}
__device__ __forceinline__ float bf_hi(float x) {
    return __bfloat162float(__float2bfloat16(x));
}

// mma.sync m16n8k16 bf16 (plain PTX; compiles for compute_103)
__device__ __forceinline__ void mma16816(float* d, uint32_t a0, uint32_t a1,
                                         uint32_t a2, uint32_t a3,
                                         uint32_t b0, uint32_t b1) {
    asm("mma.sync.aligned.m16n8k16.row.col.f32.bf16.bf16.f32 "
        "{%0,%1,%2,%3}, {%4,%5,%6,%7}, {%8,%9}, {%0,%1,%2,%3};"
        : "+f"(d[0]), "+f"(d[1]), "+f"(d[2]), "+f"(d[3])
        : "r"(a0), "r"(a1), "r"(a2), "r"(a3), "r"(b0), "r"(b1));
}

// ldmatrix x4 (non-transposed), shared-space 32-bit address
__device__ __forceinline__ void ldsm4(uint32_t* r, uint32_t addr) {
    asm volatile("ldmatrix.sync.aligned.m8n8.x4.shared.b16 {%0,%1,%2,%3}, [%4];"
        : "=r"(r[0]), "=r"(r[1]), "=r"(r[2]), "=r"(r[3]) : "r"(addr));
}

// warp GEMM: acc[nt][4] = A[warp rows 16][128] @ Bt[n][k]^T, bf16 split-3.
// Fragment loads via ldmatrix: per ks-step 1 LDSM(A) + 8 LDSM(B) feed 16 MMAs.
// aoff/boff: per-lane byte offsets into the tiles (canonical x4 address maps).
__device__ __forceinline__ void warp_gemm3(float (&acc)[16][4],
                                           uint32_t AhS, uint32_t AlS,
                                           uint32_t BhS, uint32_t BlS,
                                           int aoff, int boff)
{
#pragma unroll
    for (int i = 0; i < 16; i++)
#pragma unroll
        for (int j = 0; j < 4; j++) acc[i][j] = 0.f;

#pragma unroll 1
    for (int sp = 0; sp < 3; sp++) {
        const uint32_t A = (sp == 1) ? AlS : AhS;
        const uint32_t B = (sp == 2) ? BlS : BhS;
#pragma unroll 2
        for (int ks = 0; ks < 8; ks++) {
            uint32_t a[4];
            ldsm4(a, A + aoff + ks * 32);
            const uint32_t bb = B + boff + ks * 32;
#pragma unroll
            for (int ntp = 0; ntp < 8; ntp++) {
                uint32_t b[4];
                ldsm4(b, bb + ntp * 16 * TROW);
                mma16816(acc[2 * ntp],     a[0], a[1], a[2], a[3], b[0], b[1]);
                mma16816(acc[2 * ntp + 1], a[0], a[1], a[2], a[3], b[2], b[3]);
            }
        }
    }
}

// ---------------- weight pre-convert: W[k][n] f32 -> bf16 hi/lo [n][k] ------
__global__ void convw_k(const float* __restrict__ We2, const float* __restrict__ Wx1)
{
    int idx = blockIdx.x * 256 + threadIdx.x;
    if (idx >= NLAYERS * 2 * 16384) return;
    int l = idx / 32768;
    int rest = idx % 32768;
    int m = rest >> 14;
    int e = rest & 16383;
    int n = e >> 7, k = e & 127;
    const float* W = m ? (Wx1 + (size_t)l * 16384) : (We2 + (size_t)l * 16384);
    float x = W[k * 128 + n];
    __nv_bfloat16 h = __float2bfloat16(x);
    __nv_bfloat16 lo = __float2bfloat16(x - __bfloat162float(h));
    g_wbhi[(l * 2 + m) * 16384 + n * 128 + k] = h;
    g_wblo[(l * 2 + m) * 16384 + n * 128 + k] = lo;
}

// ---------------- fused edge pipeline (mma.sync + ldmatrix) -----------------
__global__ __launch_bounds__(256)
void edge_mma_k(const int* __restrict__ srcv, const int* __restrict__ dstv,
                const float* __restrict__ ee,
                const float* __restrict__ Ps, const float* __restrict__ Pd,
                const float* __restrict__ wex_g, const float* __restrict__ be1,
                const float* __restrict__ be2, const float* __restrict__ bx1,
                const float* __restrict__ Wx2, const float* __restrict__ bx2,
                const __nv_bfloat16* __restrict__ WBhi,
                const __nv_bfloat16* __restrict__ WBlo,
                int write_mij)
{
    extern __shared__ char smc[];
    float* smf = (float*)smc;
    float* diffs = smf + 0;      // 384
    float* dists = smf + 384;    // 128
    int*   dsts  = (int*)(smf + 512);
    float* ee0s  = smf + 640;
    float* ee1s  = smf + 768;
    float* wex   = smf + 896;    // 384
    float* be1s  = smf + 1280;
    float* be2s  = smf + 1408;
    float* bx1s  = smf + 1536;
    float* wx2s  = smf + 1664;   // 384
    float* bx2s  = smf + 2048;   // 4
    float* es    = smf + 2052;   // 256
    char* Ah  = smc + 9248;
    char* Al  = Ah  + TILE_BYTES;
    char* Bh1 = Al  + TILE_BYTES;
    char* Bl1 = Bh1 + TILE_BYTES;
    char* Bh2 = Bl1 + TILE_BYTES;
    char* Bl2 = Bh2 + TILE_BYTES;

    const int tid  = threadIdx.x;
    const int wid  = tid >> 5;
    const int lane = tid & 31;
    const int g    = lane >> 2;
    const int q    = lane & 3;
    const int m0   = blockIdx.x * 128;

    // shared-space addresses for ldmatrix
    const uint32_t AhS  = (uint32_t)__cvta_generic_to_shared(Ah);
    const uint32_t AlS  = (uint32_t)__cvta_generic_to_shared(Al);
    const uint32_t Bh1S = (uint32_t)__cvta_generic_to_shared(Bh1);
    const uint32_t Bl1S = (uint32_t)__cvta_generic_to_shared(Bl1);
    const uint32_t Bh2S = (uint32_t)__cvta_generic_to_shared(Bh2);
    const uint32_t Bl2S = (uint32_t)__cvta_generic_to_shared(Bl2);

    // ---- phase 0: geometry, biases, weight tiles ----
    if (tid < 128) {
        int mm = m0 + tid;
        int s = srcv[mm], d = dstv[mm];
        float dx = g_coords[d * 3 + 0] - g_coords[s * 3 + 0];
        float dy = g_coords[d * 3 + 1] - g_coords[s * 3 + 1];
        float dz = g_coords[d * 3 + 2] - g_coords[s * 3 + 2];
        diffs[tid * 3 + 0] = dx;
        diffs[tid * 3 + 1] = dy;
        diffs[tid * 3 + 2] = dz;
        dists[tid] = sqrtf(dx * dx + dy * dy + dz * dz);
        dsts[tid] = d;
        ee0s[tid] = ee[mm * 2 + 0];
        ee1s[tid] = ee[mm * 2 + 1];
        be1s[tid] = be1[tid];
        be2s[tid] = be2[tid];
        bx1s[tid] = bx1[tid];
    }
    es[tid] = 0.f;
    for (int i = tid; i < 384; i += 256) { wex[i] = wex_g[i]; wx2s[i] = Wx2[i]; }
    if (tid < 3) bx2s[tid] = bx2[tid];

    // copy 4 weight tiles (We2t hi/lo, Wx1t hi/lo): 2048 uint4 each
    {
        const char* srcs[4] = {(const char*)WBhi, (const char*)WBlo,
                               (const char*)(WBhi + 16384), (const char*)(WBlo + 16384)};
        char* dstp[4] = {Bh1, Bl1, Bh2, Bl2};
#pragma unroll
        for (int t = 0; t < 4; t++) {
            const uint4* s4 = (const uint4*)srcs[t];
            char* d4 = dstp[t];
#pragma unroll
            for (int i = 0; i < 8; i++) {
                int p = tid + i * 256;       // 0..2047
                int row = p >> 4, chunk = p & 15;
                *(uint4*)(d4 + row * TROW + chunk * 16) = s4[p];
            }
        }
    }
    // REQUIRED: T1 build below reads wex/be1s written cooperatively above.
    __syncthreads();

    // ---- T1 build: silu(Ps[src]+Pd[dst]+dist*w+ee@W+be1) -> Ah/Al ----
    {
        const int r  = tid >> 1;
        const int cb = (tid & 1) * 64;
        const int mm = m0 + r;
        const int s  = srcv[mm];
        const float* psp = Ps + (size_t)s * 128;
        const float* pdp = Pd + (size_t)dsts[r] * 128;
        const float di = dists[r];
        const float e0 = ee0s[r], e1 = ee1s[r];
        for (int c = cb; c < cb + 64; c += 8) {
            float o[8];
#pragma unroll
            for (int h = 0; h < 8; h += 4) {
                float4 a = *(const float4*)(psp + c + h);
                float4 b = *(const float4*)(pdp + c + h);
                o[h+0] = silu_f(a.x + b.x + di * wex[c+h+0] + e0 * wex[128+c+h+0] + e1 * wex[256+c+h+0] + be1s[c+h+0]);
                o[h+1] = silu_f(a.y + b.y + di * wex[c+h+1] + e0 * wex[128+c+h+1] + e1 * wex[256+c+h+1] + be1s[c+h+1]);
                o[h+2] = silu_f(a.z + b.z + di * wex[c+h+2] + e0 * wex[128+c+h+2] + e1 * wex[256+c+h+2] + be1s[c+h+2]);
                o[h+3] = silu_f(a.w + b.w + di * wex[c+h+3] + e0 * wex[128+c+h+3] + e1 * wex[256+c+h+3] + be1s[c+h+3]);
            }
            uint32_t H[4], L[4];
#pragma unroll
            for (int j = 0; j < 4; j++) {
                float hx = bf_hi(o[2*j]), hy = bf_hi(o[2*j+1]);
                H[j] = pk_bf2(o[2*j], o[2*j+1]);
                L[j] = pk_bf2(o[2*j] - hx, o[2*j+1] - hy);
            }
            *(uint4*)(Ah + r * TROW + c * 2) = *(uint4*)H;
            *(uint4*)(Al + r * TROW + c * 2) = *(uint4*)L;
        }
    }
    __syncthreads();

    // ldmatrix per-lane address offsets (canonical x4 maps)
    // A 16x16: mat0 rows0-7 k0-7, mat1 rows8-15 k0-7, mat2 rows0-7 k8-15, mat3 rows8-15 k8-15
    const int arow = wid * 16 + (lane & 7) + ((lane & 8) ? 8 : 0);
    const int aoff = arow * TROW + ((lane >> 4) & 1) * 16;
    // B pair (16 n-rows x 16 k): mat0 n0-7 k0-7, mat1 n0-7 k8-15, mat2 n8-15 k0-7, mat3 n8-15 k8-15
    const int brow = (lane & 7) + (((lane >> 4) & 1) << 3);
    const int boff = brow * TROW + ((lane & 8) ? 16 : 0);

    const int r0 = wid * 16 + g, r1 = r0 + 8;

    float acc[16][4];

    // ---- GEMM1: D = T1 @ We2t^T ----
    warp_gemm3(acc, AhS, AlS, Bh1S, Bl1S, aoff, boff);

    // ---- epilogue 1: mij = silu(D + be2); mi scatter; mij/stats; A := mij --
    {
        const int d0 = dsts[r0], d1 = dsts[r1];
#pragma unroll
        for (int nt = 0; nt < 16; nt++) {
            const int c = nt * 8 + q * 2;
            float v00 = silu_f(acc[nt][0] + be2s[c]);
            float v01 = silu_f(acc[nt][1] + be2s[c + 1]);
            float v10 = silu_f(acc[nt][2] + be2s[c]);
            float v11 = silu_f(acc[nt][3] + be2s[c + 1]);
            red_add_v2(&g_mi[(size_t)d0 * 128 + c], v00, v01);
            red_add_v2(&g_mi[(size_t)d1 * 128 + c], v10, v11);
            if (write_mij) {
                *(float2*)(g_mij + (size_t)(m0 + r0) * 128 + c) = make_float2(v00, v01);
                *(float2*)(g_mij + (size_t)(m0 + r1) * 128 + c) = make_float2(v10, v11);
                float e00 = elu_f(v00), e01 = elu_f(v01);
                float e10 = elu_f(v10), e11 = elu_f(v11);
                float s0 = e00 + e10, s1 = e01 + e11;
                float q0 = e00 * e00 + e10 * e10, q1 = e01 * e01 + e11 * e11;
#pragma unroll
                for (int o = 4; o < 32; o <<= 1) {
                    s0 += __shfl_xor_sync(0xFFFFFFFF, s0, o);
                    s1 += __shfl_xor_sync(0xFFFFFFFF, s1, o);
                    q0 += __shfl_xor_sync(0xFFFFFFFF, q0, o);
                    q1 += __shfl_xor_sync(0xFFFFFFFF, q1, o);
                }
                if (lane < 4) {
                    atomicAdd(&es[c], s0);
                    atomicAdd(&es[c + 1], s1);
                    atomicAdd(&es[128 + c], q0);
                    atomicAdd(&es[128 + c + 1], q1);
                }
            }
            // rewrite warp-own A rows with mij hi/lo
            float h00 = bf_hi(v00), h01 = bf_hi(v01);
            float h10 = bf_hi(v10), h11 = bf_hi(v11);
            *(uint32_t*)(Ah + r0 * TROW + c * 2) = pk_bf2(v00, v01);
            *(uint32_t*)(Ah + r1 * TROW + c * 2) = pk_bf2(v10, v11);
            *(uint32_t*)(Al + r0 * TROW + c * 2) = pk_bf2(v00 - h00, v01 - h01);
            *(uint32_t*)(Al + r1 * TROW + c * 2) = pk_bf2(v10 - h10, v11 - h11);
        }
    }
    __syncwarp();   // make cross-lane A rewrites visible before GEMM2
    if (write_mij) {
        __syncthreads();
        if (tid < 128) {
            g_partE[blockIdx.x * 128 + tid] = es[tid];
            g_partE[(EDGE_TILES + blockIdx.x) * 128 + tid] = es[128 + tid];
        }
    }

    // ---- GEMM2: D = mij @ Wx1t^T  (A rows are warp-own) ----
    warp_gemm3(acc, AhS, AlS, Bh2S, Bl2S, aoff, boff);

    // ---- epilogue 2: T2 = silu(D + bx1); px = T2 @ Wx2 + bx2; scatter ----
    {
        float pa0 = 0.f, pa1 = 0.f, pa2 = 0.f;
        float pb0 = 0.f, pb1 = 0.f, pb2 = 0.f;
#pragma unroll
        for (int nt = 0; nt < 16; nt++) {
            const int c = nt * 8 + q * 2;
            float t00 = silu_f(acc[nt][0] + bx1s[c]);
            float t01 = silu_f(acc[nt][1] + bx1s[c + 1]);
            float t10 = silu_f(acc[nt][2] + bx1s[c]);
            float t11 = silu_f(acc[nt][3] + bx1s[c + 1]);
            float w00 = wx2s[c * 3 + 0], w01 = wx2s[c * 3 + 1], w02 = wx2s[c * 3 + 2];
            float w10 = wx2s[c * 3 + 3], w11 = wx2s[c * 3 + 4], w12 = wx2s[c * 3 + 5];
            pa0 += t00 * w00 + t01 * w10;
            pa1 += t00 * w01 + t01 * w11;
            pa2 += t00 * w02 + t01 * w12;
            pb0 += t10 * w00 + t11 * w10;
            pb1 += t10 * w01 + t11 * w11;
            pb2 += t10 * w02 + t11 * w12;
        }
#pragma unroll
        for (int o = 1; o < 4; o <<= 1) {
            pa0 += __shfl_xor_sync(0xFFFFFFFF, pa0, o);
            pa1 += __shfl_xor_sync(0xFFFFFFFF, pa1, o);
            pa2 += __shfl_xor_sync(0xFFFFFFFF, pa2, o);
            pb0 += __shfl_xor_sync(0xFFFFFFFF, pb0, o);
            pb1 += __shfl_xor_sync(0xFFFFFFFF, pb1, o);
            pb2 += __shfl_xor_sync(0xFFFFFFFF, pb2, o);
        }
        if (q == 0) {
            const int d0 = dsts[r0], d1 = dsts[r1];
            float x0 = pa0 + bx2s[0], x1 = pa1 + bx2s[1], x2 = pa2 + bx2s[2];
            atomicAdd(&g_accum[d0 * 3 + 0], diffs[r0 * 3 + 0] * x0);
            atomicAdd(&g_accum[d0 * 3 + 1], diffs[r0 * 3 + 1] * x1);
            atomicAdd(&g_accum[d0 * 3 + 2], diffs[r0 * 3 + 2] * x2);
            float y0 = pb0 + bx2s[0], y1 = pb1 + bx2s[1], y2 = pb2 + bx2s[2];
            atomicAdd(&g_accum[d1 * 3 + 0], diffs[r1 * 3 + 0] * y0);
            atomicAdd(&g_accum[d1 * 3 + 1], diffs[r1 * 3 + 1] * y1);
            atomicAdd(&g_accum[d1 * 3 + 2], diffs[r1 * 3 + 2] * y2);
        }
    }
}

// ---------------- node side (unchanged from R8) ----------------
__device__ __forceinline__ int ts_off(int r, int c) {
    return r * 132 + ((r >> 3) & 1) * 4 + c;
}

__device__ __forceinline__ void gemm_tile4(ull (&acc)[4][4], const float* Ts,
                                           const float* Bs, int kbase,
                                           int row0, int col0)
{
    const float* arow = Ts + row0 * 132 + ((row0 >> 3) & 1) * 4 + kbase;
#pragma unroll
    for (int kk = 0; kk < 16; kk += 2) {
        const float* bp0 = Bs + kk * 132 + col0;
        const float* bp1 = bp0 + 132;
        ulonglong2 b01a = *(const ulonglong2*)bp0;
        ulonglong2 b23a = *(const ulonglong2*)(bp0 + 4);
        ulonglong2 b01b = *(const ulonglong2*)bp1;
        ulonglong2 b23b = *(const ulonglong2*)(bp1 + 4);
#pragma unroll
        for (int i = 0; i < 4; i++) {
            float2 a2 = *(const float2*)&arow[i * 132 + kk];
            ull av0 = dup2(a2.x), av1 = dup2(a2.y);
            acc[i][0] = fma2(av0, b01a.x, acc[i][0]);
            acc[i][1] = fma2(av0, b01a.y, acc[i][1]);
            acc[i][2] = fma2(av0, b23a.x, acc[i][2]);
            acc[i][3] = fma2(av0, b23a.y, acc[i][3]);
            acc[i][0] = fma2(av1, b01b.x, acc[i][0]);
            acc[i][1] = fma2(av1, b01b.y, acc[i][1]);
            acc[i][2] = fma2(av1, b23b.x, acc[i][2]);
            acc[i][3] = fma2(av1, b23b.y, acc[i][3]);
        }
    }
}

__global__ __launch_bounds__(256) void proj_k(
    const float* __restrict__ V, const float* __restrict__ We1l,
    float* __restrict__ Ps, float* __restrict__ Pd, int M)
{
    __shared__ float As[16][68];
    __shared__ float Bs[16][264];

    const int tid  = threadIdx.x;
    const int m0   = blockIdx.x * 64;
    const int arow = tid >> 2;
    const int akb  = (tid & 3) * 4;
    const int brow = tid >> 4;
    const int bcol = (tid & 15) * 16;
    const int gm   = m0 + arow;
    const bool mval = (gm < M);
    const int row0 = (tid >> 4) * 4;
    const int col0 = (tid & 15) * 16;

    {
        int r = tid >> 2, c = (tid & 3) * 32;
        if (m0 + r < M) {
            float4 z = make_float4(0.f, 0.f, 0.f, 0.f);
            float* p = g_mi + (size_t)(m0 + r) * 128 + c;
#pragma unroll
            for (int j = 0; j < 8; j++) *(float4*)(p + j * 4) = z;
        }
        if (tid < 192 && m0 + tid / 3 < M)
            g_accum[(size_t)m0 * 3 + tid] = 0.f;
    }

    float acc[4][16];
#pragma unroll
    for (int i = 0; i < 4; i++)
#pragma unroll
        for (int j = 0; j < 16; j++) acc[i][j] = 0.f;

    for (int kt = 0; kt < 8; kt++) {
        const int kbase = kt * 16;
        {
            const int gk = kbase + brow;
            const float* wp = (bcol < 128)
                ? We1l + (size_t)gk * 128 + bcol
                : We1l + (size_t)(128 + gk) * 128 + (bcol - 128);
#pragma unroll
            for (int j = 0; j < 16; j += 4)
                *(float4*)&Bs[brow][bcol + j] = *(const float4*)(wp + j);
        }
#pragma unroll
        for (int i = 0; i < 4; i++) {
            const int gk = kbase + akb + i;
            As[akb + i][arow] = mval ? V[(size_t)gm * 128 + gk] : 0.f;
        }
        __syncthreads();
#pragma unroll
        for (int kk = 0; kk < 16; kk++) {
            float4 a = *(const float4*)&As[kk][row0];
            float av[4] = {a.x, a.y, a.z, a.w};
            float bv[16];
#pragma unroll
            for (int j = 0; j < 16; j += 4)
                *(float4*)&bv[j] = *(const float4*)&Bs[kk][col0 + j];
#pragma unroll
            for (int i = 0; i < 4; i++)
#pragma unroll
                for (int j = 0; j < 16; j++) acc[i][j] += av[i] * bv[j];
        }
        __syncthreads();
    }

#pragma unroll
    for (int i = 0; i < 4; i++) {
        const int mm = m0 + row0 + i;
        if (mm < M) {
            float* cp = (col0 < 128)
                ? Ps + (size_t)mm * 128 + col0
                : Pd + (size_t)mm * 128 + (col0 - 128);
#pragma unroll
            for (int j = 0; j < 16; j += 4)
                *(float4*)(cp + j) = *(float4*)&acc[i][j];
        }
    }
}

__global__ __launch_bounds__(256) void node_fused_k(
    const float* __restrict__ V, const float* __restrict__ mi,
    const float* __restrict__ Wh1, const float* __restrict__ bh1,
    const float* __restrict__ Wh2, const float* __restrict__ bh2,
    float* __restrict__ Vraw, float* __restrict__ part, int M, int nblk)
{
    __shared__ float VH[64 * 132 + 4];
    __shared__ float As[16][68];
    __shared__ float Bs[16][132];
    __shared__ float sstat[256];

    const int tid  = threadIdx.x;
    const int m0   = blockIdx.x * 64;
    const int arow = tid >> 2;
    const int akb  = (tid & 3) * 4;
    const int brow = tid >> 4;
    const int bcol = (tid & 15) * 8;
    const int gm   = m0 + arow;
    const bool mval = (gm < M);
    const int row0 = (tid >> 4) * 4;
    const int col0 = (tid & 15) * 8;

    sstat[tid] = 0.f;

    float accA[4][8];
#pragma unroll
    for (int i = 0; i < 4; i++)
#pragma unroll
        for (int j = 0; j < 8; j++) accA[i][j] = 0.f;

    for (int kt = 0; kt < 16; kt++) {
        const int kbase = kt * 16;
        {
            const float* wp = Wh1 + (size_t)(kbase + brow) * 128 + bcol;
#pragma unroll
            for (int j = 0; j < 8; j += 4)
                *(float4*)&Bs[brow][bcol + j] = *(const float4*)(wp + j);
        }
#pragma unroll
        for (int i = 0; i < 4; i++) {
            const int gk = kbase + akb + i;
            float v = 0.f;
            if (mval)
                v = (gk < 128) ? V[(size_t)gm * 128 + gk]
                               : mi[(size_t)gm * 128 + (gk - 128)];
            As[akb + i][arow] = v;
        }
        __syncthreads();
#pragma unroll
        for (int kk = 0; kk < 16; kk++) {
            float4 a = *(const float4*)&As[kk][row0];
            float4 b0 = *(const float4*)&Bs[kk][col0];
            float4 b1 = *(const float4*)&Bs[kk][col0 + 4];
            float av[4] = {a.x, a.y, a.z, a.w};
            float bv[8] = {b0.x, b0.y, b0.z, b0.w, b1.x, b1.y, b1.z, b1.w};
#pragma unroll
            for (int i = 0; i < 4; i++)
#pragma unroll
                for (int j = 0; j < 8; j++) accA[i][j] += av[i] * bv[j];
        }
        __syncthreads();
    }
    {
        float b[8];
        *(float4*)b       = *(const float4*)(bh1 + col0);
        *(float4*)(b + 4) = *(const float4*)(bh1 + col0 + 4);
#pragma unroll
        for (int i = 0; i < 4; i++) {
            float* trow = VH + ts_off(row0 + i, col0);
            float o[8];
#pragma unroll
            for (int j = 0; j < 8; j++) o[j] = silu_f(accA[i][j] + b[j]);
            *(float4*)trow       = *(float4*)&o[0];
            *(float4*)(trow + 4) = *(float4*)&o[4];
        }
    }
    __syncthreads();

    ull acc[4][4];
#pragma unroll
    for (int i = 0; i < 4; i++)
#pragma unroll
        for (int j = 0; j < 4; j++) acc[i][j] = 0ULL;

    for (int kt = 0; kt < 8; kt++) {
        const int kbase = kt * 16;
        {
            const float* wp = Wh2 + (size_t)(kbase + brow) * 128 + bcol;
#pragma unroll
            for (int j = 0; j < 8; j += 4)
                *(float4*)&Bs[brow][bcol + j] = *(const float4*)(wp + j);
        }
        __syncthreads();
        gemm_tile4(acc, VH, &Bs[0][0], kbase, row0, col0);
        __syncthreads();
    }
    {
        float b[8];
        *(float4*)b       = *(const float4*)(bh2 + col0);
        *(float4*)(b + 4) = *(const float4*)(bh2 + col0 + 4);
        float cs[8], cq[8];
#pragma unroll
        for (int j = 0; j < 8; j++) { cs[j] = 0.f; cq[j] = 0.f; }
#pragma unroll
        for (int i = 0; i < 4; i++) {
            const int mm = m0 + row0 + i;
            if (mm < M) {
                float o[8];
#pragma unroll
                for (int jp = 0; jp < 4; jp++) {
                    float2 c = unpk(acc[i][jp]);
                    o[2 * jp]     = c.x + b[2 * jp];
                    o[2 * jp + 1] = c.y + b[2 * jp + 1];
                }
                float* cp = Vraw + (size_t)mm * 128 + col0;
                *(float4*)cp       = *(float4*)&o[0];
                *(float4*)(cp + 4) = *(float4*)&o[4];
#pragma unroll
                for (int j = 0; j < 8; j++) {
                    float e = elu_f(o[j]);
                    cs[j] += e;
                    cq[j] += e * e;
                }
            }
        }
        __syncthreads();
#pragma unroll
        for (int j = 0; j < 8; j++) {
            atomicAdd(&sstat[col0 + j], cs[j]);
            atomicAdd(&sstat[128 + col0 + j], cq[j]);
        }
        __syncthreads();
        if (tid < 128) {
            part[blockIdx.x * 128 + tid] = sstat[tid];
            part[(nblk + blockIdx.x) * 128 + tid] = sstat[128 + tid];
        }
    }
}

// ---------------- small kernels ----------------
__global__ void init_nodes_k(const float* __restrict__ emb,
                             const float* __restrict__ Wn,
                             const float* __restrict__ bn)
{
    int idx = blockIdx.x * blockDim.x + threadIdx.x;
    if (idx < N_NODES * 3) g_coords[idx] = emb[idx];
    if (idx < N_NODES * HDIM) {
        int n = idx >> 7, j = idx & 127;
        g_V[idx] = emb[n * 3 + 0] * Wn[0 * 128 + j]
                 + emb[n * 3 + 1] * Wn[1 * 128 + j]
                 + emb[n * 3 + 2] * Wn[2 * 128 + j]
                 + bn[j];
    }
}

__global__ void coords_update_k()
{
    int idx = blockIdx.x * blockDim.x + threadIdx.x;
    if (idx < N_NODES * 3)
        g_coords[idx] += g_accum[idx] * (1.0f / (float)(N_NODES - 1));
}

__global__ void bn_stats2_k(const float* __restrict__ part, int B, int M)
{
    int j = threadIdx.x;
    double s = 0.0, q = 0.0;
    for (int b = 0; b < B; b++) {
        s += (double)part[b * 128 + j];
        q += (double)part[(B + b) * 128 + j];
    }
    double mu  = s / (double)M;
    double var = q / (double)M - mu * mu;
    g_muinv[j]       = (float)mu;
    g_muinv[128 + j] = (float)rsqrt(var + (double)BN_EPS);
}

__global__ void bn_norm_k(const float* __restrict__ X,
                          const float* __restrict__ gam,
                          const float* __restrict__ bet,
                          float* __restrict__ out, int M)
{
    int idx = blockIdx.x * blockDim.x + threadIdx.x;
    if (idx >= M * 128) return;
    int j = idx & 127;
    float x = elu_f(X[idx]);
    out[idx] = gam[j] * (x - g_muinv[j]) * g_muinv[128 + j] + bet[j];
}

// ---------------- host launcher ----------------
static void* sym_addr(const void* sym)
{
    void* p = nullptr;
    cudaGetSymbolAddress(&p, sym);
    return p;
}

extern "C" void kernel_launch(void* const* d_in, const int* in_sizes, int n_in,
                              void* d_out, int out_size)
{
    (void)in_sizes; (void)n_in; (void)out_size;

    const float* emb_nodes = (const float*)d_in[0];
    const float* emb_edges = (const float*)d_in[1];
    const int*   edge_idx  = (const int*)d_in[2];
    const float* pre_Wn    = (const float*)d_in[3];
    const float* pre_bn    = (const float*)d_in[4];
    const float* We1 = (const float*)d_in[7];
    const float* be1 = (const float*)d_in[8];
    const float* We2 = (const float*)d_in[9];
    const float* be2 = (const float*)d_in[10];
    const float* Wx1 = (const float*)d_in[11];
    const float* bx1 = (const float*)d_in[12];
    const float* Wx2 = (const float*)d_in[13];
    const float* bx2 = (const float*)d_in[14];
    const float* Wh1 = (const float*)d_in[15];
    const float* bh1 = (const float*)d_in[16];
    const float* Wh2 = (const float*)d_in[17];
    const float* bh2 = (const float*)d_in[18];
    const float* gam_n = (const float*)d_in[19];
    const float* bet_n = (const float*)d_in[20];
    const float* gam_e = (const float*)d_in[21];
    const float* bet_e = (const float*)d_in[22];

    float* out  = (float*)d_out;
    float* outV = out;
    float* outE = out + (size_t)N_NODES * HDIM;

    const int* srcv = edge_idx;
    const int* dstv = edge_idx + N_EDGES;

    float* pV     = (float*)sym_addr(g_V);
    float* pVraw  = (float*)sym_addr(g_Vraw);
    float* pVH    = (float*)sym_addr(g_VH);
    float* pMi    = (float*)sym_addr(g_mi);
    float* pMij   = (float*)sym_addr(g_mij);
    float* pPartE = (float*)sym_addr(g_partE);
    float* pPartN = (float*)sym_addr(g_partN);
    __nv_bfloat16* pWbhi = (__nv_bfloat16*)sym_addr(g_wbhi);
    __nv_bfloat16* pWblo = (__nv_bfloat16*)sym_addr(g_wblo);

    const int EDGE_SMEM = 9248 + 6 * TILE_BYTES;   // 218144 B
    cudaFuncSetAttribute(edge_mma_k,
                         cudaFuncAttributeMaxDynamicSharedMemorySize, EDGE_SMEM);

    const int TB = 256;
    const int nodeHBlocks = (N_NODES * HDIM + TB - 1) / TB;
    const int edgeHBlocks = (N_EDGES * HDIM + TB - 1) / TB;

    init_nodes_k<<<nodeHBlocks, TB>>>(emb_nodes, pre_Wn, pre_bn);
    convw_k<<<(NLAYERS * 2 * 16384 + 255) / 256, 256>>>(We2, Wx1);

    for (int l = 0; l < NLAYERS; l++) {
        const float* We1l = We1 + (size_t)l * 259 * 128;
        const float* be1l = be1 + l * 128;
        const float* be2l = be2 + l * 128;
        const float* bx1l = bx1 + l * 128;
        const float* Wx2l = Wx2 + (size_t)l * 128 * 3;
        const float* bx2l = bx2 + l * 3;
        const float* Wh1l = Wh1 + (size_t)l * 256 * 128;
        const float* bh1l = bh1 + l * 128;
        const float* Wh2l = Wh2 + (size_t)l * 128 * 128;
        const float* bh2l = bh2 + l * 128;

        proj_k<<<NODE_TILES, 256>>>(pV, We1l, pVH, pVraw, N_NODES);

        edge_mma_k<<<EDGE_TILES, 256, EDGE_SMEM>>>(
            srcv, dstv, emb_edges, pVH, pVraw,
            We1l + 256 * 128, be1l, be2l, bx1l, Wx2l, bx2l,
            pWbhi + (size_t)l * 2 * 16384, pWblo + (size_t)l * 2 * 16384,
            (l == NLAYERS - 1) ? 1 : 0);

        coords_update_k<<<(N_NODES * 3 + TB - 1) / TB, TB>>>();

        node_fused_k<<<NODE_TILES, 256>>>(
            pV, pMi, Wh1l, bh1l, Wh2l, bh2l,
            pVraw, pPartN, N_NODES, NODE_TILES);

        bn_stats2_k<<<1, 128>>>(pPartN, NODE_TILES, N_NODES);
        float* vdst = (l == NLAYERS - 1) ? outV : pV;
        bn_norm_k<<<nodeHBlocks, TB>>>(pVraw, gam_n + l * 128, bet_n + l * 128,
                                       vdst, N_NODES);

        if (l == NLAYERS - 1) {
            bn_stats2_k<<<1, 128>>>(pPartE, EDGE_TILES, N_EDGES);
            bn_norm_k<<<edgeHBlocks, TB>>>(pMij, gam_e + l * 128, bet_e + l * 128,
                                           outE, N_EDGES);
        }
    }
}

// round 13
// speedup vs baseline: 1.7581x; 1.1640x over previous
#include <cuda_runtime.h>
#include <cuda_bf16.h>
#include <math.h>
#include <stdint.h>

typedef unsigned long long ull;

#define N_NODES 10000
#define N_EDGES 160000
#define HDIM    128
#define NLAYERS 3
#define BN_EPS  1e-5f

#define EDGE_CTA   256
#define EDGE_TILES (N_EDGES / EDGE_CTA)   // 625
#define NODE_TILES ((N_NODES + 63) / 64)  // 157

// bf16 tile row stride: 136 bf16 = 272 B
#define TROW 272
#define A_TILE_BYTES (256 * TROW)         // 69632 (256 edge rows)
#define B_TILE_BYTES (128 * TROW)         // 34816

// ---------------- device scratch ----------------
__device__ float g_coords[N_NODES * 3];
__device__ float g_V[N_NODES * HDIM];
__device__ float g_Vraw[N_NODES * HDIM];   // Pd during edge phase
__device__ float g_VH[N_NODES * HDIM];     // Ps during edge phase
__device__ float g_mi[N_NODES * HDIM];
__device__ float g_accum[N_NODES * 3];
__device__ float g_mij[N_EDGES * HDIM];
__device__ float g_partE[2 * EDGE_TILES * HDIM];
__device__ float g_partN[2 * 160 * HDIM];
__device__ float g_muinv[2 * HDIM];
// bf16 weight images, [layer][mat(We2t,Wx1t)][n*128+k] (row-major [n][k])
__device__ __nv_bfloat16 g_wbhi[NLAYERS * 2 * 16384];
__device__ __nv_bfloat16 g_wblo[NLAYERS * 2 * 16384];

__device__ __forceinline__ float silu_f(float x) { return x / (1.0f + expf(-x)); }
__device__ __forceinline__ float elu_f(float x)  { return x > 0.0f ? x : (expf(x) - 1.0f); }

__device__ __forceinline__ ull fma2(ull a, ull b, ull c) {
    ull d;
    asm("fma.rn.f32x2 %0, %1, %2, %3;" : "=l"(d) : "l"(a), "l"(b), "l"(c));
    return d;
}
__device__ __forceinline__ float2 unpk(ull v) {
    unsigned lo, hi;
    asm("mov.b64 {%0,%1}, %2;" : "=r"(lo), "=r"(hi) : "l"(v));
    return make_float2(__uint_as_float(lo), __uint_as_float(hi));
}
__device__ __forceinline__ ull dup2(float a) {
    ull d;
    asm("mov.b64 %0, {%1,%1};" : "=l"(d) : "f"(a));
    return d;
}
__device__ __forceinline__ void red_add_v2(float* addr, float x, float y) {
    asm volatile("red.global.add.v2.f32 [%0], {%1,%2};"
                 :: "l"(addr), "f"(x), "f"(y) : "memory");
}

__device__ __forceinline__ uint32_t pk_bf2(float x, float y) {
    __nv_bfloat162 t = __floats2bfloat162_rn(x, y);
    return *(uint32_t*)&t;
}
__device__ __forceinline__ float bf_hi(float x) {
    return __bfloat162float(__float2bfloat16(x));
}

// mma.sync m16n8k16 bf16 (plain PTX; compiles for compute_103)
__device__ __forceinline__ void mma16816(float* d, uint32_t a0, uint32_t a1,
                                         uint32_t a2, uint32_t a3,
                                         uint32_t b0, uint32_t b1) {
    asm("mma.sync.aligned.m16n8k16.row.col.f32.bf16.bf16.f32 "
        "{%0,%1,%2,%3}, {%4,%5,%6,%7}, {%8,%9}, {%0,%1,%2,%3};"
        : "+f"(d[0]), "+f"(d[1]), "+f"(d[2]), "+f"(d[3])
        : "r"(a0), "r"(a1), "r"(a2), "r"(a3), "r"(b0), "r"(b1));
}

// ldmatrix x4 (non-transposed), shared-space 32-bit address
__device__ __forceinline__ void ldsm4(uint32_t* r, uint32_t addr) {
    asm volatile("ldmatrix.sync.aligned.m8n8.x4.shared.b16 {%0,%1,%2,%3}, [%4];"
        : "=r"(r[0]), "=r"(r[1]), "=r"(r[2]), "=r"(r[3]) : "r"(addr));
}

// warp GEMM: acc[nt][4] = A[warp rows 16][128] @ Bt[n][k]^T, bf16 split-3.
// ldmatrix fragment loads: per ks-step 1 LDSM(A) + 8 LDSM(B) feed 16 MMAs.
__device__ __forceinline__ void warp_gemm3(float (&acc)[16][4],
                                           uint32_t AhS, uint32_t AlS,
                                           uint32_t BhS, uint32_t BlS,
                                           int aoff, int boff)
{
#pragma unroll
    for (int i = 0; i < 16; i++)
#pragma unroll
        for (int j = 0; j < 4; j++) acc[i][j] = 0.f;

#pragma unroll 1
    for (int sp = 0; sp < 3; sp++) {
        const uint32_t A = (sp == 1) ? AlS : AhS;
        const uint32_t B = (sp == 2) ? BlS : BhS;
#pragma unroll 2
        for (int ks = 0; ks < 8; ks++) {
            uint32_t a[4];
            ldsm4(a, A + aoff + ks * 32);
            const uint32_t bb = B + boff + ks * 32;
#pragma unroll
            for (int ntp = 0; ntp < 8; ntp++) {
                uint32_t b[4];
                ldsm4(b, bb + ntp * 16 * TROW);
                mma16816(acc[2 * ntp],     a[0], a[1], a[2], a[3], b[0], b[1]);
                mma16816(acc[2 * ntp + 1], a[0], a[1], a[2], a[3], b[2], b[3]);
            }
        }
    }
}

// ---------------- weight pre-convert: W[k][n] f32 -> bf16 hi/lo [n][k] ------
__global__ void convw_k(const float* __restrict__ We2, const float* __restrict__ Wx1)
{
    int idx = blockIdx.x * 256 + threadIdx.x;
    if (idx >= NLAYERS * 2 * 16384) return;
    int l = idx / 32768;
    int rest = idx % 32768;
    int m = rest >> 14;
    int e = rest & 16383;
    int n = e >> 7, k = e & 127;
    const float* W = m ? (Wx1 + (size_t)l * 16384) : (We2 + (size_t)l * 16384);
    float x = W[k * 128 + n];
    __nv_bfloat16 h = __float2bfloat16(x);
    __nv_bfloat16 lo = __float2bfloat16(x - __bfloat162float(h));
    g_wbhi[(l * 2 + m) * 16384 + n * 128 + k] = h;
    g_wblo[(l * 2 + m) * 16384 + n * 128 + k] = lo;
}

// ---------------- fused edge pipeline: 512 thr, 256 edges/CTA ---------------
// smem float offsets:
//  diffs 0 (768) | dists 768 (256) | dsts 1024 (256) | ee0s 1280 | ee1s 1536
//  wex 1792 (384) | be1s 2176 | be2s 2304 | bx1s 2432 | wx2s 2560 (384)
//  bx2s 2944 (4) | es 2948 (256) | end 3204 -> tiles at byte 12816
__global__ __launch_bounds__(512)
void edge_mma_k(const int* __restrict__ srcv, const int* __restrict__ dstv,
                const float* __restrict__ ee,
                const float* __restrict__ Ps, const float* __restrict__ Pd,
                const float* __restrict__ wex_g, const float* __restrict__ be1,
                const float* __restrict__ be2, const float* __restrict__ bx1,
                const float* __restrict__ Wx2, const float* __restrict__ bx2,
                const __nv_bfloat16* __restrict__ WBhi,
                const __nv_bfloat16* __restrict__ WBlo,
                int write_mij)
{
    extern __shared__ char smc[];
    float* smf = (float*)smc;
    float* diffs = smf + 0;
    float* dists = smf + 768;
    int*   dsts  = (int*)(smf + 1024);
    float* ee0s  = smf + 1280;
    float* ee1s  = smf + 1536;
    float* wex   = smf + 1792;
    float* be1s  = smf + 2176;
    float* be2s  = smf + 2304;
    float* bx1s  = smf + 2432;
    float* wx2s  = smf + 2560;
    float* bx2s  = smf + 2944;
    float* es    = smf + 2948;
    char* Ah = smc + 12816;
    char* Al = Ah + A_TILE_BYTES;
    char* Bh = Al + A_TILE_BYTES;
    char* Bl = Bh + B_TILE_BYTES;

    const int tid  = threadIdx.x;
    const int wid  = tid >> 5;        // 0..15
    const int lane = tid & 31;
    const int g    = lane >> 2;
    const int q    = lane & 3;
    const int m0   = blockIdx.x * EDGE_CTA;

    const uint32_t AhS = (uint32_t)__cvta_generic_to_shared(Ah);
    const uint32_t AlS = (uint32_t)__cvta_generic_to_shared(Al);
    const uint32_t BhS = (uint32_t)__cvta_generic_to_shared(Bh);
    const uint32_t BlS = (uint32_t)__cvta_generic_to_shared(Bl);

    // ---- phase 0: per-edge meta (256 rows), biases, B1 tiles ----
    if (tid < 256) {
        int mm = m0 + tid;
        int s = srcv[mm], d = dstv[mm];
        float dx = g_coords[d * 3 + 0] - g_coords[s * 3 + 0];
        float dy = g_coords[d * 3 + 1] - g_coords[s * 3 + 1];
        float dz = g_coords[d * 3 + 2] - g_coords[s * 3 + 2];
        diffs[tid * 3 + 0] = dx;
        diffs[tid * 3 + 1] = dy;
        diffs[tid * 3 + 2] = dz;
        dists[tid] = sqrtf(dx * dx + dy * dy + dz * dz);
        dsts[tid] = d;
        ee0s[tid] = ee[mm * 2 + 0];
        ee1s[tid] = ee[mm * 2 + 1];
        es[tid] = 0.f;
    }
    if (tid < 128) { be1s[tid] = be1[tid]; be2s[tid] = be2[tid]; bx1s[tid] = bx1[tid]; }
    for (int i = tid; i < 384; i += 512) { wex[i] = wex_g[i]; wx2s[i] = Wx2[i]; }
    if (tid < 3) bx2s[tid] = bx2[tid];

    // copy We2t hi/lo tiles: 2048 uint4 each
    {
        const uint4* shi = (const uint4*)WBhi;
        const uint4* slo = (const uint4*)WBlo;
#pragma unroll
        for (int i = 0; i < 4; i++) {
            int p = tid + i * 512;          // 0..2047
            int row = p >> 4, chunk = p & 15;
            *(uint4*)(Bh + row * TROW + chunk * 16) = shi[p];
            *(uint4*)(Bl + row * TROW + chunk * 16) = slo[p];
        }
    }
    __syncthreads();

    // ---- T1 build: 2 threads per edge row (64 cols each) ----
    {
        const int r  = tid >> 1;          // 0..255
        const int cb = (tid & 1) * 64;
        const int mm = m0 + r;
        const int s  = srcv[mm];
        const float* psp = Ps + (size_t)s * 128;
        const float* pdp = Pd + (size_t)dsts[r] * 128;
        const float di = dists[r];
        const float e0 = ee0s[r], e1 = ee1s[r];
        for (int c = cb; c < cb + 64; c += 8) {
            float o[8];
#pragma unroll
            for (int h = 0; h < 8; h += 4) {
                float4 a = *(const float4*)(psp + c + h);
                float4 b = *(const float4*)(pdp + c + h);
                o[h+0] = silu_f(a.x + b.x + di * wex[c+h+0] + e0 * wex[128+c+h+0] + e1 * wex[256+c+h+0] + be1s[c+h+0]);
                o[h+1] = silu_f(a.y + b.y + di * wex[c+h+1] + e0 * wex[128+c+h+1] + e1 * wex[256+c+h+1] + be1s[c+h+1]);
                o[h+2] = silu_f(a.z + b.z + di * wex[c+h+2] + e0 * wex[128+c+h+2] + e1 * wex[256+c+h+2] + be1s[c+h+2]);
                o[h+3] = silu_f(a.w + b.w + di * wex[c+h+3] + e0 * wex[128+c+h+3] + e1 * wex[256+c+h+3] + be1s[c+h+3]);
            }
            uint32_t H[4], L[4];
#pragma unroll
            for (int j = 0; j < 4; j++) {
                float hx = bf_hi(o[2*j]), hy = bf_hi(o[2*j+1]);
                H[j] = pk_bf2(o[2*j], o[2*j+1]);
                L[j] = pk_bf2(o[2*j] - hx, o[2*j+1] - hy);
            }
            *(uint4*)(Ah + r * TROW + c * 2) = *(uint4*)H;
            *(uint4*)(Al + r * TROW + c * 2) = *(uint4*)L;
        }
    }
    __syncthreads();

    // ldmatrix per-lane address offsets (canonical x4 maps)
    const int arow = wid * 16 + (lane & 7) + ((lane & 8) ? 8 : 0);
    const int aoff = arow * TROW + ((lane >> 4) & 1) * 16;
    const int brow = (lane & 7) + (((lane >> 4) & 1) << 3);
    const int boff = brow * TROW + ((lane & 8) ? 16 : 0);

    const int r0 = wid * 16 + g, r1 = r0 + 8;   // 0..255

    float acc[16][4];

    // ---- GEMM1: D = T1 @ We2t^T ----
    warp_gemm3(acc, AhS, AlS, BhS, BlS, aoff, boff);

    // ---- epilogue 1: mij = silu(D + be2); mi scatter; mij/stats; A := mij --
    {
        const int d0 = dsts[r0], d1 = dsts[r1];
#pragma unroll
        for (int nt = 0; nt < 16; nt++) {
            const int c = nt * 8 + q * 2;
            float v00 = silu_f(acc[nt][0] + be2s[c]);
            float v01 = silu_f(acc[nt][1] + be2s[c + 1]);
            float v10 = silu_f(acc[nt][2] + be2s[c]);
            float v11 = silu_f(acc[nt][3] + be2s[c + 1]);
            red_add_v2(&g_mi[(size_t)d0 * 128 + c], v00, v01);
            red_add_v2(&g_mi[(size_t)d1 * 128 + c], v10, v11);
            if (write_mij) {
                *(float2*)(g_mij + (size_t)(m0 + r0) * 128 + c) = make_float2(v00, v01);
                *(float2*)(g_mij + (size_t)(m0 + r1) * 128 + c) = make_float2(v10, v11);
                float e00 = elu_f(v00), e01 = elu_f(v01);
                float e10 = elu_f(v10), e11 = elu_f(v11);
                float s0 = e00 + e10, s1 = e01 + e11;
                float q0 = e00 * e00 + e10 * e10, q1 = e01 * e01 + e11 * e11;
#pragma unroll
                for (int o = 4; o < 32; o <<= 1) {
                    s0 += __shfl_xor_sync(0xFFFFFFFF, s0, o);
                    s1 += __shfl_xor_sync(0xFFFFFFFF, s1, o);
                    q0 += __shfl_xor_sync(0xFFFFFFFF, q0, o);
                    q1 += __shfl_xor_sync(0xFFFFFFFF, q1, o);
                }
                if (lane < 4) {
                    atomicAdd(&es[c], s0);
                    atomicAdd(&es[c + 1], s1);
                    atomicAdd(&es[128 + c], q0);
                    atomicAdd(&es[128 + c + 1], q1);
                }
            }
            float h00 = bf_hi(v00), h01 = bf_hi(v01);
            float h10 = bf_hi(v10), h11 = bf_hi(v11);
            *(uint32_t*)(Ah + r0 * TROW + c * 2) = pk_bf2(v00, v01);
            *(uint32_t*)(Ah + r1 * TROW + c * 2) = pk_bf2(v10, v11);
            *(uint32_t*)(Al + r0 * TROW + c * 2) = pk_bf2(v00 - h00, v01 - h01);
            *(uint32_t*)(Al + r1 * TROW + c * 2) = pk_bf2(v10 - h10, v11 - h11);
        }
    }
    // barrier: all GEMM1 B reads + A rewrites complete before B overwrite
    __syncthreads();
    if (write_mij && tid < 128) {
        g_partE[blockIdx.x * 128 + tid] = es[tid];
        g_partE[(EDGE_TILES + blockIdx.x) * 128 + tid] = es[128 + tid];
    }
    // overwrite B tiles with Wx1t hi/lo (2048 uint4 each)
    {
        const uint4* shi = (const uint4*)(WBhi + 16384);
        const uint4* slo = (const uint4*)(WBlo + 16384);
#pragma unroll
        for (int i = 0; i < 4; i++) {
            int p = tid + i * 512;
            int row = p >> 4, chunk = p & 15;
            *(uint4*)(Bh + row * TROW + chunk * 16) = shi[p];
            *(uint4*)(Bl + row * TROW + chunk * 16) = slo[p];
        }
    }
    __syncthreads();

    // ---- GEMM2: D = mij @ Wx1t^T ----
    warp_gemm3(acc, AhS, AlS, BhS, BlS, aoff, boff);

    // ---- epilogue 2: T2 = silu(D + bx1); px = T2 @ Wx2 + bx2; scatter ----
    {
        float pa0 = 0.f, pa1 = 0.f, pa2 = 0.f;
        float pb0 = 0.f, pb1 = 0.f, pb2 = 0.f;
#pragma unroll
        for (int nt = 0; nt < 16; nt++) {
            const int c = nt * 8 + q * 2;
            float t00 = silu_f(acc[nt][0] + bx1s[c]);
            float t01 = silu_f(acc[nt][1] + bx1s[c + 1]);
            float t10 = silu_f(acc[nt][2] + bx1s[c]);
            float t11 = silu_f(acc[nt][3] + bx1s[c + 1]);
            float w00 = wx2s[c * 3 + 0], w01 = wx2s[c * 3 + 1], w02 = wx2s[c * 3 + 2];
            float w10 = wx2s[c * 3 + 3], w11 = wx2s[c * 3 + 4], w12 = wx2s[c * 3 + 5];
            pa0 += t00 * w00 + t01 * w10;
            pa1 += t00 * w01 + t01 * w11;
            pa2 += t00 * w02 + t01 * w12;
            pb0 += t10 * w00 + t11 * w10;
            pb1 += t10 * w01 + t11 * w11;
            pb2 += t10 * w02 + t11 * w12;
        }
#pragma unroll
        for (int o = 1; o < 4; o <<= 1) {
            pa0 += __shfl_xor_sync(0xFFFFFFFF, pa0, o);
            pa1 += __shfl_xor_sync(0xFFFFFFFF, pa1, o);
            pa2 += __shfl_xor_sync(0xFFFFFFFF, pa2, o);
            pb0 += __shfl_xor_sync(0xFFFFFFFF, pb0, o);
            pb1 += __shfl_xor_sync(0xFFFFFFFF, pb1, o);
            pb2 += __shfl_xor_sync(0xFFFFFFFF, pb2, o);
        }
        if (q == 0) {
            const int d0 = dsts[r0], d1 = dsts[r1];
            float x0 = pa0 + bx2s[0], x1 = pa1 + bx2s[1], x2 = pa2 + bx2s[2];
            atomicAdd(&g_accum[d0 * 3 + 0], diffs[r0 * 3 + 0] * x0);
            atomicAdd(&g_accum[d0 * 3 + 1], diffs[r0 * 3 + 1] * x1);
            atomicAdd(&g_accum[d0 * 3 + 2], diffs[r0 * 3 + 2] * x2);
            float y0 = pb0 + bx2s[0], y1 = pb1 + bx2s[1], y2 = pb2 + bx2s[2];
            atomicAdd(&g_accum[d1 * 3 + 0], diffs[r1 * 3 + 0] * y0);
            atomicAdd(&g_accum[d1 * 3 + 1], diffs[r1 * 3 + 1] * y1);
            atomicAdd(&g_accum[d1 * 3 + 2], diffs[r1 * 3 + 2] * y2);
        }
    }
}

// ---------------- node side (unchanged from R12) ----------------
__device__ __forceinline__ int ts_off(int r, int c) {
    return r * 132 + ((r >> 3) & 1) * 4 + c;
}

__device__ __forceinline__ void gemm_tile4(ull (&acc)[4][4], const float* Ts,
                                           const float* Bs, int kbase,
                                           int row0, int col0)
{
    const float* arow = Ts + row0 * 132 + ((row0 >> 3) & 1) * 4 + kbase;
#pragma unroll
    for (int kk = 0; kk < 16; kk += 2) {
        const float* bp0 = Bs + kk * 132 + col0;
        const float* bp1 = bp0 + 132;
        ulonglong2 b01a = *(const ulonglong2*)bp0;
        ulonglong2 b23a = *(const ulonglong2*)(bp0 + 4);
        ulonglong2 b01b = *(const ulonglong2*)bp1;
        ulonglong2 b23b = *(const ulonglong2*)(bp1 + 4);
#pragma unroll
        for (int i = 0; i < 4; i++) {
            float2 a2 = *(const float2*)&arow[i * 132 + kk];
            ull av0 = dup2(a2.x), av1 = dup2(a2.y);
            acc[i][0] = fma2(av0, b01a.x, acc[i][0]);
            acc[i][1] = fma2(av0, b01a.y, acc[i][1]);
            acc[i][2] = fma2(av0, b23a.x, acc[i][2]);
            acc[i][3] = fma2(av0, b23a.y, acc[i][3]);
            acc[i][0] = fma2(av1, b01b.x, acc[i][0]);
            acc[i][1] = fma2(av1, b01b.y, acc[i][1]);
            acc[i][2] = fma2(av1, b23b.x, acc[i][2]);
            acc[i][3] = fma2(av1, b23b.y, acc[i][3]);
        }
    }
}

__global__ __launch_bounds__(256) void proj_k(
    const float* __restrict__ V, const float* __restrict__ We1l,
    float* __restrict__ Ps, float* __restrict__ Pd, int M)
{
    __shared__ float As[16][68];
    __shared__ float Bs[16][264];

    const int tid  = threadIdx.x;
    const int m0   = blockIdx.x * 64;
    const int arow = tid >> 2;
    const int akb  = (tid & 3) * 4;
    const int brow = tid >> 4;
    const int bcol = (tid & 15) * 16;
    const int gm   = m0 + arow;
    const bool mval = (gm < M);
    const int row0 = (tid >> 4) * 4;
    const int col0 = (tid & 15) * 16;

    {
        int r = tid >> 2, c = (tid & 3) * 32;
        if (m0 + r < M) {
            float4 z = make_float4(0.f, 0.f, 0.f, 0.f);
            float* p = g_mi + (size_t)(m0 + r) * 128 + c;
#pragma unroll
            for (int j = 0; j < 8; j++) *(float4*)(p + j * 4) = z;
        }
        if (tid < 192 && m0 + tid / 3 < M)
            g_accum[(size_t)m0 * 3 + tid] = 0.f;
    }

    float acc[4][16];
#pragma unroll
    for (int i = 0; i < 4; i++)
#pragma unroll
        for (int j = 0; j < 16; j++) acc[i][j] = 0.f;

    for (int kt = 0; kt < 8; kt++) {
        const int kbase = kt * 16;
        {
            const int gk = kbase + brow;
            const float* wp = (bcol < 128)
                ? We1l + (size_t)gk * 128 + bcol
                : We1l + (size_t)(128 + gk) * 128 + (bcol - 128);
#pragma unroll
            for (int j = 0; j < 16; j += 4)
                *(float4*)&Bs[brow][bcol + j] = *(const float4*)(wp + j);
        }
#pragma unroll
        for (int i = 0; i < 4; i++) {
            const int gk = kbase + akb + i;
            As[akb + i][arow] = mval ? V[(size_t)gm * 128 + gk] : 0.f;
        }
        __syncthreads();
#pragma unroll
        for (int kk = 0; kk < 16; kk++) {
            float4 a = *(const float4*)&As[kk][row0];
            float av[4] = {a.x, a.y, a.z, a.w};
            float bv[16];
#pragma unroll
            for (int j = 0; j < 16; j += 4)
                *(float4*)&bv[j] = *(const float4*)&Bs[kk][col0 + j];
#pragma unroll
            for (int i = 0; i < 4; i++)
#pragma unroll
                for (int j = 0; j < 16; j++) acc[i][j] += av[i] * bv[j];
        }
        __syncthreads();
    }

#pragma unroll
    for (int i = 0; i < 4; i++) {
        const int mm = m0 + row0 + i;
        if (mm < M) {
            float* cp = (col0 < 128)
                ? Ps + (size_t)mm * 128 + col0
                : Pd + (size_t)mm * 128 + (col0 - 128);
#pragma unroll
            for (int j = 0; j < 16; j += 4)
                *(float4*)(cp + j) = *(float4*)&acc[i][j];
        }
    }
}

__global__ __launch_bounds__(256) void node_fused_k(
    const float* __restrict__ V, const float* __restrict__ mi,
    const float* __restrict__ Wh1, const float* __restrict__ bh1,
    const float* __restrict__ Wh2, const float* __restrict__ bh2,
    float* __restrict__ Vraw, float* __restrict__ part, int M, int nblk)
{
    __shared__ float VH[64 * 132 + 4];
    __shared__ float As[16][68];
    __shared__ float Bs[16][132];
    __shared__ float sstat[256];

    const int tid  = threadIdx.x;
    const int m0   = blockIdx.x * 64;
    const int arow = tid >> 2;
    const int akb  = (tid & 3) * 4;
    const int brow = tid >> 4;
    const int bcol = (tid & 15) * 8;
    const int gm   = m0 + arow;
    const bool mval = (gm < M);
    const int row0 = (tid >> 4) * 4;
    const int col0 = (tid & 15) * 8;

    sstat[tid] = 0.f;

    float accA[4][8];
#pragma unroll
    for (int i = 0; i < 4; i++)
#pragma unroll
        for (int j = 0; j < 8; j++) accA[i][j] = 0.f;

    for (int kt = 0; kt < 16; kt++) {
        const int kbase = kt * 16;
        {
            const float* wp = Wh1 + (size_t)(kbase + brow) * 128 + bcol;
#pragma unroll
            for (int j = 0; j < 8; j += 4)
                *(float4*)&Bs[brow][bcol + j] = *(const float4*)(wp + j);
        }
#pragma unroll
        for (int i = 0; i < 4; i++) {
            const int gk = kbase + akb + i;
            float v = 0.f;
            if (mval)
                v = (gk < 128) ? V[(size_t)gm * 128 + gk]
                               : mi[(size_t)gm * 128 + (gk - 128)];
            As[akb + i][arow] = v;
        }
        __syncthreads();
#pragma unroll
        for (int kk = 0; kk < 16; kk++) {
            float4 a = *(const float4*)&As[kk][row0];
            float4 b0 = *(const float4*)&Bs[kk][col0];
            float4 b1 = *(const float4*)&Bs[kk][col0 + 4];
            float av[4] = {a.x, a.y, a.z, a.w};
            float bv[8] = {b0.x, b0.y, b0.z, b0.w, b1.x, b1.y, b1.z, b1.w};
#pragma unroll
            for (int i = 0; i < 4; i++)
#pragma unroll
                for (int j = 0; j < 8; j++) accA[i][j] += av[i] * bv[j];
        }
        __syncthreads();
    }
    {
        float b[8];
        *(float4*)b       = *(const float4*)(bh1 + col0);
        *(float4*)(b + 4) = *(const float4*)(bh1 + col0 + 4);
#pragma unroll
        for (int i = 0; i < 4; i++) {
            float* trow = VH + ts_off(row0 + i, col0);
            float o[8];
#pragma unroll
            for (int j = 0; j < 8; j++) o[j] = silu_f(accA[i][j] + b[j]);
            *(float4*)trow       = *(float4*)&o[0];
            *(float4*)(trow + 4) = *(float4*)&o[4];
        }
    }
    __syncthreads();

    ull acc[4][4];
#pragma unroll
    for (int i = 0; i < 4; i++)
#pragma unroll
        for (int j = 0; j < 4; j++) acc[i][j] = 0ULL;

    for (int kt = 0; kt < 8; kt++) {
        const int kbase = kt * 16;
        {
            const float* wp = Wh2 + (size_t)(kbase + brow) * 128 + bcol;
#pragma unroll
            for (int j = 0; j < 8; j += 4)
                *(float4*)&Bs[brow][bcol + j] = *(const float4*)(wp + j);
        }
        __syncthreads();
        gemm_tile4(acc, VH, &Bs[0][0], kbase, row0, col0);
        __syncthreads();
    }
    {
        float b[8];
        *(float4*)b       = *(const float4*)(bh2 + col0);
        *(float4*)(b + 4) = *(const float4*)(bh2 + col0 + 4);
        float cs[8], cq[8];
#pragma unroll
        for (int j = 0; j < 8; j++) { cs[j] = 0.f; cq[j] = 0.f; }
#pragma unroll
        for (int i = 0; i < 4; i++) {
            const int mm = m0 + row0 + i;
            if (mm < M) {
                float o[8];
#pragma unroll
                for (int jp = 0; jp < 4; jp++) {
                    float2 c = unpk(acc[i][jp]);
                    o[2 * jp]     = c.x + b[2 * jp];
                    o[2 * jp + 1] = c.y + b[2 * jp + 1];
                }
                float* cp = Vraw + (size_t)mm * 128 + col0;
                *(float4*)cp       = *(float4*)&o[0];
                *(float4*)(cp + 4) = *(float4*)&o[4];
#pragma unroll
                for (int j = 0; j < 8; j++) {
                    float e = elu_f(o[j]);
                    cs[j] += e;
                    cq[j] += e * e;
                }
            }
        }
        __syncthreads();
#pragma unroll
        for (int j = 0; j < 8; j++) {
            atomicAdd(&sstat[col0 + j], cs[j]);
            atomicAdd(&sstat[128 + col0 + j], cq[j]);
        }
        __syncthreads();
        if (tid < 128) {
            part[blockIdx.x * 128 + tid] = sstat[tid];
            part[(nblk + blockIdx.x) * 128 + tid] = sstat[128 + tid];
        }
    }
}

// ---------------- small kernels ----------------
__global__ void init_nodes_k(const float* __restrict__ emb,
                             const float* __restrict__ Wn,
                             const float* __restrict__ bn)
{
    int idx = blockIdx.x * blockDim.x + threadIdx.x;
    if (idx < N_NODES * 3) g_coords[idx] = emb[idx];
    if (idx < N_NODES * HDIM) {
        int n = idx >> 7, j = idx & 127;
        g_V[idx] = emb[n * 3 + 0] * Wn[0 * 128 + j]
                 + emb[n * 3 + 1] * Wn[1 * 128 + j]
                 + emb[n * 3 + 2] * Wn[2 * 128 + j]
                 + bn[j];
    }
}

__global__ void coords_update_k()
{
    int idx = blockIdx.x * blockDim.x + threadIdx.x;
    if (idx < N_NODES * 3)
        g_coords[idx] += g_accum[idx] * (1.0f / (float)(N_NODES - 1));
}

__global__ void bn_stats2_k(const float* __restrict__ part, int B, int M)
{
    int j = threadIdx.x;
    double s = 0.0, q = 0.0;
    for (int b = 0; b < B; b++) {
        s += (double)part[b * 128 + j];
        q += (double)part[(B + b) * 128 + j];
    }
    double mu  = s / (double)M;
    double var = q / (double)M - mu * mu;
    g_muinv[j]       = (float)mu;
    g_muinv[128 + j] = (float)rsqrt(var + (double)BN_EPS);
}

__global__ void bn_norm_k(const float* __restrict__ X,
                          const float* __restrict__ gam,
                          const float* __restrict__ bet,
                          float* __restrict__ out, int M)
{
    int idx = blockIdx.x * blockDim.x + threadIdx.x;
    if (idx >= M * 128) return;
    int j = idx & 127;
    float x = elu_f(X[idx]);
    out[idx] = gam[j] * (x - g_muinv[j]) * g_muinv[128 + j] + bet[j];
}

// ---------------- host launcher ----------------
static void* sym_addr(const void* sym)
{
    void* p = nullptr;
    cudaGetSymbolAddress(&p, sym);
    return p;
}

extern "C" void kernel_launch(void* const* d_in, const int* in_sizes, int n_in,
                              void* d_out, int out_size)
{
    (void)in_sizes; (void)n_in; (void)out_size;

    const float* emb_nodes = (const float*)d_in[0];
    const float* emb_edges = (const float*)d_in[1];
    const int*   edge_idx  = (const int*)d_in[2];
    const float* pre_Wn    = (const float*)d_in[3];
    const float* pre_bn    = (const float*)d_in[4];
    const float* We1 = (const float*)d_in[7];
    const float* be1 = (const float*)d_in[8];
    const float* We2 = (const float*)d_in[9];
    const float* be2 = (const float*)d_in[10];
    const float* Wx1 = (const float*)d_in[11];
    const float* bx1 = (const float*)d_in[12];
    const float* Wx2 = (const float*)d_in[13];
    const float* bx2 = (const float*)d_in[14];
    const float* Wh1 = (const float*)d_in[15];
    const float* bh1 = (const float*)d_in[16];
    const float* Wh2 = (const float*)d_in[17];
    const float* bh2 = (const float*)d_in[18];
    const float* gam_n = (const float*)d_in[19];
    const float* bet_n = (const float*)d_in[20];
    const float* gam_e = (const float*)d_in[21];
    const float* bet_e = (const float*)d_in[22];

    float* out  = (float*)d_out;
    float* outV = out;
    float* outE = out + (size_t)N_NODES * HDIM;

    const int* srcv = edge_idx;
    const int* dstv = edge_idx + N_EDGES;

    float* pV     = (float*)sym_addr(g_V);
    float* pVraw  = (float*)sym_addr(g_Vraw);
    float* pVH    = (float*)sym_addr(g_VH);
    float* pMi    = (float*)sym_addr(g_mi);
    float* pMij   = (float*)sym_addr(g_mij);
    float* pPartE = (float*)sym_addr(g_partE);
    float* pPartN = (float*)sym_addr(g_partN);
    __nv_bfloat16* pWbhi = (__nv_bfloat16*)sym_addr(g_wbhi);
    __nv_bfloat16* pWblo = (__nv_bfloat16*)sym_addr(g_wblo);

    const int EDGE_SMEM = 12816 + 2 * A_TILE_BYTES + 2 * B_TILE_BYTES; // 221712
    cudaFuncSetAttribute(edge_mma_k,
                         cudaFuncAttributeMaxDynamicSharedMemorySize, EDGE_SMEM);

    const int TB = 256;
    const int nodeHBlocks = (N_NODES * HDIM + TB - 1) / TB;
    const int edgeHBlocks = (N_EDGES * HDIM + TB - 1) / TB;

    init_nodes_k<<<nodeHBlocks, TB>>>(emb_nodes, pre_Wn, pre_bn);
    convw_k<<<(NLAYERS * 2 * 16384 + 255) / 256, 256>>>(We2, Wx1);

    for (int l = 0; l < NLAYERS; l++) {
        const float* We1l = We1 + (size_t)l * 259 * 128;
        const float* be1l = be1 + l * 128;
        const float* be2l = be2 + l * 128;
        const float* bx1l = bx1 + l * 128;
        const float* Wx2l = Wx2 + (size_t)l * 128 * 3;
        const float* bx2l = bx2 + l * 3;
        const float* Wh1l = Wh1 + (size_t)l * 256 * 128;
        const float* bh1l = bh1 + l * 128;
        const float* Wh2l = Wh2 + (size_t)l * 128 * 128;
        const float* bh2l = bh2 + l * 128;

        proj_k<<<NODE_TILES, 256>>>(pV, We1l, pVH, pVraw, N_NODES);

        edge_mma_k<<<EDGE_TILES, 512, EDGE_SMEM>>>(
            srcv, dstv, emb_edges, pVH, pVraw,
            We1l + 256 * 128, be1l, be2l, bx1l, Wx2l, bx2l,
            pWbhi + (size_t)l * 2 * 16384, pWblo + (size_t)l * 2 * 16384,
            (l == NLAYERS - 1) ? 1 : 0);

        coords_update_k<<<(N_NODES * 3 + TB - 1) / TB, TB>>>();

        node_fused_k<<<NODE_TILES, 256>>>(
            pV, pMi, Wh1l, bh1l, Wh2l, bh2l,
            pVraw, pPartN, N_NODES, NODE_TILES);

        bn_stats2_k<<<1, 128>>>(pPartN, NODE_TILES, N_NODES);
        float* vdst = (l == NLAYERS - 1) ? outV : pV;
        bn_norm_k<<<nodeHBlocks, TB>>>(pVraw, gam_n + l * 128, bet_n + l * 128,
                                       vdst, N_NODES);

        if (l == NLAYERS - 1) {
            bn_stats2_k<<<1, 128>>>(pPartE, EDGE_TILES, N_EDGES);
            bn_norm_k<<<edgeHBlocks, TB>>>(pMij, gam_e + l * 128, bet_e + l * 128,
                                           outE, N_EDGES);
        }
    }
}

// round 14
// speedup vs baseline: 1.7943x; 1.0206x over previous
#include <cuda_runtime.h>
#include <cuda_bf16.h>
#include <math.h>
#include <stdint.h>

typedef unsigned long long ull;

#define N_NODES 10000
#define N_EDGES 160000
#define HDIM    128
#define NLAYERS 3
#define BN_EPS  1e-5f

#define EDGE_CTA   256
#define EDGE_TILES (N_EDGES / EDGE_CTA)   // 625
#define NODE_TILES ((N_NODES + 63) / 64)  // 157

// bf16 tile row stride: 136 bf16 = 272 B
#define TROW 272
#define A_TILE_BYTES (256 * TROW)         // 69632 (256 edge rows)
#define B_TILE_BYTES (128 * TROW)         // 34816

// ---------------- device scratch ----------------
__device__ float g_coords[N_NODES * 3];
__device__ float g_V[N_NODES * HDIM];
__device__ float g_Vraw[N_NODES * HDIM];   // Pd during edge phase
__device__ float g_VH[N_NODES * HDIM];     // Ps during edge phase
__device__ float g_mi[N_NODES * HDIM];
__device__ float g_accum[N_NODES * 3];
__device__ float g_mij[N_EDGES * HDIM];
__device__ float g_partE[2 * EDGE_TILES * HDIM];
__device__ float g_partN[2 * 160 * HDIM];
__device__ float g_muinv[2 * HDIM];
// bf16 weight images, [layer][mat(We2t,Wx1t)][n*128+k] (row-major [n][k])
__device__ __nv_bfloat16 g_wbhi[NLAYERS * 2 * 16384];
__device__ __nv_bfloat16 g_wblo[NLAYERS * 2 * 16384];

__device__ __forceinline__ float silu_f(float x) { return x / (1.0f + expf(-x)); }
__device__ __forceinline__ float elu_f(float x)  { return x > 0.0f ? x : (expf(x) - 1.0f); }

__device__ __forceinline__ ull fma2(ull a, ull b, ull c) {
    ull d;
    asm("fma.rn.f32x2 %0, %1, %2, %3;" : "=l"(d) : "l"(a), "l"(b), "l"(c));
    return d;
}
__device__ __forceinline__ float2 unpk(ull v) {
    unsigned lo, hi;
    asm("mov.b64 {%0,%1}, %2;" : "=r"(lo), "=r"(hi) : "l"(v));
    return make_float2(__uint_as_float(lo), __uint_as_float(hi));
}
__device__ __forceinline__ ull dup2(float a) {
    ull d;
    asm("mov.b64 %0, {%1,%1};" : "=l"(d) : "f"(a));
    return d;
}
__device__ __forceinline__ void red_add_v2(float* addr, float x, float y) {
    asm volatile("red.global.add.v2.f32 [%0], {%1,%2};"
                 :: "l"(addr), "f"(x), "f"(y) : "memory");
}

__device__ __forceinline__ uint32_t pk_bf2(float x, float y) {
    __nv_bfloat162 t = __floats2bfloat162_rn(x, y);
    return *(uint32_t*)&t;
}
__device__ __forceinline__ float bf_hi(float x) {
    return __bfloat162float(__float2bfloat16(x));
}

// mma.sync m16n8k16 bf16 (plain PTX; compiles for compute_103)
__device__ __forceinline__ void mma16816(float* d, uint32_t a0, uint32_t a1,
                                         uint32_t a2, uint32_t a3,
                                         uint32_t b0, uint32_t b1) {
    asm("mma.sync.aligned.m16n8k16.row.col.f32.bf16.bf16.f32 "
        "{%0,%1,%2,%3}, {%4,%5,%6,%7}, {%8,%9}, {%0,%1,%2,%3};"
        : "+f"(d[0]), "+f"(d[1]), "+f"(d[2]), "+f"(d[3])
        : "r"(a0), "r"(a1), "r"(a2), "r"(a3), "r"(b0), "r"(b1));
}

// ldmatrix x4 (non-transposed), shared-space 32-bit address
__device__ __forceinline__ void ldsm4(uint32_t* r, uint32_t addr) {
    asm volatile("ldmatrix.sync.aligned.m8n8.x4.shared.b16 {%0,%1,%2,%3}, [%4];"
        : "=r"(r[0]), "=r"(r[1]), "=r"(r[2]), "=r"(r[3]) : "r"(addr));
}

// warp GEMM: acc[nt][4] = A[warp rows 16][128] @ Bt[n][k]^T, bf16 split-3.
// Split loop hoisted inside: per ks load Ah+Al once, per ntp load Bh+Bl once,
// issue Ah*Bh + Al*Bh + Ah*Bl from registers. 18 LDSM per ks feed 48 MMAs.
__device__ __forceinline__ void warp_gemm3(float (&acc)[16][4],
                                           uint32_t AhS, uint32_t AlS,
                                           uint32_t BhS, uint32_t BlS,
                                           int aoff, int boff)
{
#pragma unroll
    for (int i = 0; i < 16; i++)
#pragma unroll
        for (int j = 0; j < 4; j++) acc[i][j] = 0.f;

#pragma unroll 2
    for (int ks = 0; ks < 8; ks++) {
        uint32_t ah[4], al[4];
        ldsm4(ah, AhS + aoff + ks * 32);
        ldsm4(al, AlS + aoff + ks * 32);
        const uint32_t bhb = BhS + boff + ks * 32;
        const uint32_t blb = BlS + boff + ks * 32;
#pragma unroll
        for (int ntp = 0; ntp < 8; ntp++) {
            uint32_t bh[4], bl[4];
            ldsm4(bh, bhb + ntp * 16 * TROW);
            ldsm4(bl, blb + ntp * 16 * TROW);
            mma16816(acc[2 * ntp],     ah[0], ah[1], ah[2], ah[3], bh[0], bh[1]);
            mma16816(acc[2 * ntp + 1], ah[0], ah[1], ah[2], ah[3], bh[2], bh[3]);
            mma16816(acc[2 * ntp],     al[0], al[1], al[2], al[3], bh[0], bh[1]);
            mma16816(acc[2 * ntp + 1], al[0], al[1], al[2], al[3], bh[2], bh[3]);
            mma16816(acc[2 * ntp],     ah[0], ah[1], ah[2], ah[3], bl[0], bl[1]);
            mma16816(acc[2 * ntp + 1], ah[0], ah[1], ah[2], ah[3], bl[2], bl[3]);
        }
    }
}

// ---------------- weight pre-convert: W[k][n] f32 -> bf16 hi/lo [n][k] ------
__global__ void convw_k(const float* __restrict__ We2, const float* __restrict__ Wx1)
{
    int idx = blockIdx.x * 256 + threadIdx.x;
    if (idx >= NLAYERS * 2 * 16384) return;
    int l = idx / 32768;
    int rest = idx % 32768;
    int m = rest >> 14;
    int e = rest & 16383;
    int n = e >> 7, k = e & 127;
    const float* W = m ? (Wx1 + (size_t)l * 16384) : (We2 + (size_t)l * 16384);
    float x = W[k * 128 + n];
    __nv_bfloat16 h = __float2bfloat16(x);
    __nv_bfloat16 lo = __float2bfloat16(x - __bfloat162float(h));
    g_wbhi[(l * 2 + m) * 16384 + n * 128 + k] = h;
    g_wblo[(l * 2 + m) * 16384 + n * 128 + k] = lo;
}

// ---------------- fused edge pipeline: 512 thr, 256 edges/CTA ---------------
__global__ __launch_bounds__(512)
void edge_mma_k(const int* __restrict__ srcv, const int* __restrict__ dstv,
                const float* __restrict__ ee,
                const float* __restrict__ Ps, const float* __restrict__ Pd,
                const float* __restrict__ wex_g, const float* __restrict__ be1,
                const float* __restrict__ be2, const float* __restrict__ bx1,
                const float* __restrict__ Wx2, const float* __restrict__ bx2,
                const __nv_bfloat16* __restrict__ WBhi,
                const __nv_bfloat16* __restrict__ WBlo,
                int write_mij)
{
    extern __shared__ char smc[];
    float* smf = (float*)smc;
    float* diffs = smf + 0;
    float* dists = smf + 768;
    int*   dsts  = (int*)(smf + 1024);
    float* ee0s  = smf + 1280;
    float* ee1s  = smf + 1536;
    float* wex   = smf + 1792;
    float* be1s  = smf + 2176;
    float* be2s  = smf + 2304;
    float* bx1s  = smf + 2432;
    float* wx2s  = smf + 2560;
    float* bx2s  = smf + 2944;
    float* es    = smf + 2948;
    char* Ah = smc + 12816;
    char* Al = Ah + A_TILE_BYTES;
    char* Bh = Al + A_TILE_BYTES;
    char* Bl = Bh + B_TILE_BYTES;

    const int tid  = threadIdx.x;
    const int wid  = tid >> 5;        // 0..15
    const int lane = tid & 31;
    const int g    = lane >> 2;
    const int q    = lane & 3;
    const int m0   = blockIdx.x * EDGE_CTA;

    const uint32_t AhS = (uint32_t)__cvta_generic_to_shared(Ah);
    const uint32_t AlS = (uint32_t)__cvta_generic_to_shared(Al);
    const uint32_t BhS = (uint32_t)__cvta_generic_to_shared(Bh);
    const uint32_t BlS = (uint32_t)__cvta_generic_to_shared(Bl);

    // ---- phase 0: per-edge meta (256 rows), biases, B1 tiles ----
    if (tid < 256) {
        int mm = m0 + tid;
        int s = srcv[mm], d = dstv[mm];
        float dx = g_coords[d * 3 + 0] - g_coords[s * 3 + 0];
        float dy = g_coords[d * 3 + 1] - g_coords[s * 3 + 1];
        float dz = g_coords[d * 3 + 2] - g_coords[s * 3 + 2];
        diffs[tid * 3 + 0] = dx;
        diffs[tid * 3 + 1] = dy;
        diffs[tid * 3 + 2] = dz;
        dists[tid] = sqrtf(dx * dx + dy * dy + dz * dz);
        dsts[tid] = d;
        ee0s[tid] = ee[mm * 2 + 0];
        ee1s[tid] = ee[mm * 2 + 1];
        es[tid] = 0.f;
    }
    if (tid < 128) { be1s[tid] = be1[tid]; be2s[tid] = be2[tid]; bx1s[tid] = bx1[tid]; }
    for (int i = tid; i < 384; i += 512) { wex[i] = wex_g[i]; wx2s[i] = Wx2[i]; }
    if (tid < 3) bx2s[tid] = bx2[tid];

    // copy We2t hi/lo tiles: 2048 uint4 each
    {
        const uint4* shi = (const uint4*)WBhi;
        const uint4* slo = (const uint4*)WBlo;
#pragma unroll
        for (int i = 0; i < 4; i++) {
            int p = tid + i * 512;          // 0..2047
            int row = p >> 4, chunk = p & 15;
            *(uint4*)(Bh + row * TROW + chunk * 16) = shi[p];
            *(uint4*)(Bl + row * TROW + chunk * 16) = slo[p];
        }
    }
    __syncthreads();

    // ---- T1 build: 2 threads per edge row (64 cols each) ----
    {
        const int r  = tid >> 1;          // 0..255
        const int cb = (tid & 1) * 64;
        const int mm = m0 + r;
        const int s  = srcv[mm];
        const float* psp = Ps + (size_t)s * 128;
        const float* pdp = Pd + (size_t)dsts[r] * 128;
        const float di = dists[r];
        const float e0 = ee0s[r], e1 = ee1s[r];
        for (int c = cb; c < cb + 64; c += 8) {
            float o[8];
#pragma unroll
            for (int h = 0; h < 8; h += 4) {
                float4 a = *(const float4*)(psp + c + h);
                float4 b = *(const float4*)(pdp + c + h);
                o[h+0] = silu_f(a.x + b.x + di * wex[c+h+0] + e0 * wex[128+c+h+0] + e1 * wex[256+c+h+0] + be1s[c+h+0]);
                o[h+1] = silu_f(a.y + b.y + di * wex[c+h+1] + e0 * wex[128+c+h+1] + e1 * wex[256+c+h+1] + be1s[c+h+1]);
                o[h+2] = silu_f(a.z + b.z + di * wex[c+h+2] + e0 * wex[128+c+h+2] + e1 * wex[256+c+h+2] + be1s[c+h+2]);
                o[h+3] = silu_f(a.w + b.w + di * wex[c+h+3] + e0 * wex[128+c+h+3] + e1 * wex[256+c+h+3] + be1s[c+h+3]);
            }
            uint32_t H[4], L[4];
#pragma unroll
            for (int j = 0; j < 4; j++) {
                float hx = bf_hi(o[2*j]), hy = bf_hi(o[2*j+1]);
                H[j] = pk_bf2(o[2*j], o[2*j+1]);
                L[j] = pk_bf2(o[2*j] - hx, o[2*j+1] - hy);
            }
            *(uint4*)(Ah + r * TROW + c * 2) = *(uint4*)H;
            *(uint4*)(Al + r * TROW + c * 2) = *(uint4*)L;
        }
    }
    __syncthreads();

    // ldmatrix per-lane address offsets (canonical x4 maps)
    const int arow = wid * 16 + (lane & 7) + ((lane & 8) ? 8 : 0);
    const int aoff = arow * TROW + ((lane >> 4) & 1) * 16;
    const int brow = (lane & 7) + (((lane >> 4) & 1) << 3);
    const int boff = brow * TROW + ((lane & 8) ? 16 : 0);

    const int r0 = wid * 16 + g, r1 = r0 + 8;   // 0..255

    float acc[16][4];

    // ---- GEMM1: D = T1 @ We2t^T ----
    warp_gemm3(acc, AhS, AlS, BhS, BlS, aoff, boff);

    // ---- epilogue 1: mij = silu(D + be2); mi scatter; mij/stats; A := mij --
    {
        const int d0 = dsts[r0], d1 = dsts[r1];
#pragma unroll
        for (int nt = 0; nt < 16; nt++) {
            const int c = nt * 8 + q * 2;
            float v00 = silu_f(acc[nt][0] + be2s[c]);
            float v01 = silu_f(acc[nt][1] + be2s[c + 1]);
            float v10 = silu_f(acc[nt][2] + be2s[c]);
            float v11 = silu_f(acc[nt][3] + be2s[c + 1]);
            red_add_v2(&g_mi[(size_t)d0 * 128 + c], v00, v01);
            red_add_v2(&g_mi[(size_t)d1 * 128 + c], v10, v11);
            if (write_mij) {
                *(float2*)(g_mij + (size_t)(m0 + r0) * 128 + c) = make_float2(v00, v01);
                *(float2*)(g_mij + (size_t)(m0 + r1) * 128 + c) = make_float2(v10, v11);
                float e00 = elu_f(v00), e01 = elu_f(v01);
                float e10 = elu_f(v10), e11 = elu_f(v11);
                float s0 = e00 + e10, s1 = e01 + e11;
                float q0 = e00 * e00 + e10 * e10, q1 = e01 * e01 + e11 * e11;
#pragma unroll
                for (int o = 4; o < 32; o <<= 1) {
                    s0 += __shfl_xor_sync(0xFFFFFFFF, s0, o);
                    s1 += __shfl_xor_sync(0xFFFFFFFF, s1, o);
                    q0 += __shfl_xor_sync(0xFFFFFFFF, q0, o);
                    q1 += __shfl_xor_sync(0xFFFFFFFF, q1, o);
                }
                if (lane < 4) {
                    atomicAdd(&es[c], s0);
                    atomicAdd(&es[c + 1], s1);
                    atomicAdd(&es[128 + c], q0);
                    atomicAdd(&es[128 + c + 1], q1);
                }
            }
            float h00 = bf_hi(v00), h01 = bf_hi(v01);
            float h10 = bf_hi(v10), h11 = bf_hi(v11);
            *(uint32_t*)(Ah + r0 * TROW + c * 2) = pk_bf2(v00, v01);
            *(uint32_t*)(Ah + r1 * TROW + c * 2) = pk_bf2(v10, v11);
            *(uint32_t*)(Al + r0 * TROW + c * 2) = pk_bf2(v00 - h00, v01 - h01);
            *(uint32_t*)(Al + r1 * TROW + c * 2) = pk_bf2(v10 - h10, v11 - h11);
        }
    }
    // barrier: all GEMM1 B reads + A rewrites complete before B overwrite
    __syncthreads();
    if (write_mij && tid < 128) {
        g_partE[blockIdx.x * 128 + tid] = es[tid];
        g_partE[(EDGE_TILES + blockIdx.x) * 128 + tid] = es[128 + tid];
    }
    // overwrite B tiles with Wx1t hi/lo (2048 uint4 each)
    {
        const uint4* shi = (const uint4*)(WBhi + 16384);
        const uint4* slo = (const uint4*)(WBlo + 16384);
#pragma unroll
        for (int i = 0; i < 4; i++) {
            int p = tid + i * 512;
            int row = p >> 4, chunk = p & 15;
            *(uint4*)(Bh + row * TROW + chunk * 16) = shi[p];
            *(uint4*)(Bl + row * TROW + chunk * 16) = slo[p];
        }
    }
    __syncthreads();

    // ---- GEMM2: D = mij @ Wx1t^T ----
    warp_gemm3(acc, AhS, AlS, BhS, BlS, aoff, boff);

    // ---- epilogue 2: T2 = silu(D + bx1); px = T2 @ Wx2 + bx2; scatter ----
    {
        float pa0 = 0.f, pa1 = 0.f, pa2 = 0.f;
        float pb0 = 0.f, pb1 = 0.f, pb2 = 0.f;
#pragma unroll
        for (int nt = 0; nt < 16; nt++) {
            const int c = nt * 8 + q * 2;
            float t00 = silu_f(acc[nt][0] + bx1s[c]);
            float t01 = silu_f(acc[nt][1] + bx1s[c + 1]);
            float t10 = silu_f(acc[nt][2] + bx1s[c]);
            float t11 = silu_f(acc[nt][3] + bx1s[c + 1]);
            float w00 = wx2s[c * 3 + 0], w01 = wx2s[c * 3 + 1], w02 = wx2s[c * 3 + 2];
            float w10 = wx2s[c * 3 + 3], w11 = wx2s[c * 3 + 4], w12 = wx2s[c * 3 + 5];
            pa0 += t00 * w00 + t01 * w10;
            pa1 += t00 * w01 + t01 * w11;
            pa2 += t00 * w02 + t01 * w12;
            pb0 += t10 * w00 + t11 * w10;
            pb1 += t10 * w01 + t11 * w11;
            pb2 += t10 * w02 + t11 * w12;
        }
#pragma unroll
        for (int o = 1; o < 4; o <<= 1) {
            pa0 += __shfl_xor_sync(0xFFFFFFFF, pa0, o);
            pa1 += __shfl_xor_sync(0xFFFFFFFF, pa1, o);
            pa2 += __shfl_xor_sync(0xFFFFFFFF, pa2, o);
            pb0 += __shfl_xor_sync(0xFFFFFFFF, pb0, o);
            pb1 += __shfl_xor_sync(0xFFFFFFFF, pb1, o);
            pb2 += __shfl_xor_sync(0xFFFFFFFF, pb2, o);
        }
        if (q == 0) {
            const int d0 = dsts[r0], d1 = dsts[r1];
            float x0 = pa0 + bx2s[0], x1 = pa1 + bx2s[1], x2 = pa2 + bx2s[2];
            atomicAdd(&g_accum[d0 * 3 + 0], diffs[r0 * 3 + 0] * x0);
            atomicAdd(&g_accum[d0 * 3 + 1], diffs[r0 * 3 + 1] * x1);
            atomicAdd(&g_accum[d0 * 3 + 2], diffs[r0 * 3 + 2] * x2);
            float y0 = pb0 + bx2s[0], y1 = pb1 + bx2s[1], y2 = pb2 + bx2s[2];
            atomicAdd(&g_accum[d1 * 3 + 0], diffs[r1 * 3 + 0] * y0);
            atomicAdd(&g_accum[d1 * 3 + 1], diffs[r1 * 3 + 1] * y1);
            atomicAdd(&g_accum[d1 * 3 + 2], diffs[r1 * 3 + 2] * y2);
        }
    }
}

// ---------------- node side (unchanged from R13) ----------------
__device__ __forceinline__ int ts_off(int r, int c) {
    return r * 132 + ((r >> 3) & 1) * 4 + c;
}

__device__ __forceinline__ void gemm_tile4(ull (&acc)[4][4], const float* Ts,
                                           const float* Bs, int kbase,
                                           int row0, int col0)
{
    const float* arow = Ts + row0 * 132 + ((row0 >> 3) & 1) * 4 + kbase;
#pragma unroll
    for (int kk = 0; kk < 16; kk += 2) {
        const float* bp0 = Bs + kk * 132 + col0;
        const float* bp1 = bp0 + 132;
        ulonglong2 b01a = *(const ulonglong2*)bp0;
        ulonglong2 b23a = *(const ulonglong2*)(bp0 + 4);
        ulonglong2 b01b = *(const ulonglong2*)bp1;
        ulonglong2 b23b = *(const ulonglong2*)(bp1 + 4);
#pragma unroll
        for (int i = 0; i < 4; i++) {
            float2 a2 = *(const float2*)&arow[i * 132 + kk];
            ull av0 = dup2(a2.x), av1 = dup2(a2.y);
            acc[i][0] = fma2(av0, b01a.x, acc[i][0]);
            acc[i][1] = fma2(av0, b01a.y, acc[i][1]);
            acc[i][2] = fma2(av0, b23a.x, acc[i][2]);
            acc[i][3] = fma2(av0, b23a.y, acc[i][3]);
            acc[i][0] = fma2(av1, b01b.x, acc[i][0]);
            acc[i][1] = fma2(av1, b01b.y, acc[i][1]);
            acc[i][2] = fma2(av1, b23b.x, acc[i][2]);
            acc[i][3] = fma2(av1, b23b.y, acc[i][3]);
        }
    }
}

__global__ __launch_bounds__(256) void proj_k(
    const float* __restrict__ V, const float* __restrict__ We1l,
    float* __restrict__ Ps, float* __restrict__ Pd, int M)
{
    __shared__ float As[16][68];
    __shared__ float Bs[16][264];

    const int tid  = threadIdx.x;
    const int m0   = blockIdx.x * 64;
    const int arow = tid >> 2;
    const int akb  = (tid & 3) * 4;
    const int brow = tid >> 4;
    const int bcol = (tid & 15) * 16;
    const int gm   = m0 + arow;
    const bool mval = (gm < M);
    const int row0 = (tid >> 4) * 4;
    const int col0 = (tid & 15) * 16;

    {
        int r = tid >> 2, c = (tid & 3) * 32;
        if (m0 + r < M) {
            float4 z = make_float4(0.f, 0.f, 0.f, 0.f);
            float* p = g_mi + (size_t)(m0 + r) * 128 + c;
#pragma unroll
            for (int j = 0; j < 8; j++) *(float4*)(p + j * 4) = z;
        }
        if (tid < 192 && m0 + tid / 3 < M)
            g_accum[(size_t)m0 * 3 + tid] = 0.f;
    }

    float acc[4][16];
#pragma unroll
    for (int i = 0; i < 4; i++)
#pragma unroll
        for (int j = 0; j < 16; j++) acc[i][j] = 0.f;

    for (int kt = 0; kt < 8; kt++) {
        const int kbase = kt * 16;
        {
            const int gk = kbase + brow;
            const float* wp = (bcol < 128)
                ? We1l + (size_t)gk * 128 + bcol
                : We1l + (size_t)(128 + gk) * 128 + (bcol - 128);
#pragma unroll
            for (int j = 0; j < 16; j += 4)
                *(float4*)&Bs[brow][bcol + j] = *(const float4*)(wp + j);
        }
#pragma unroll
        for (int i = 0; i < 4; i++) {
            const int gk = kbase + akb + i;
            As[akb + i][arow] = mval ? V[(size_t)gm * 128 + gk] : 0.f;
        }
        __syncthreads();
#pragma unroll
        for (int kk = 0; kk < 16; kk++) {
            float4 a = *(const float4*)&As[kk][row0];
            float av[4] = {a.x, a.y, a.z, a.w};
            float bv[16];
#pragma unroll
            for (int j = 0; j < 16; j += 4)
                *(float4*)&bv[j] = *(const float4*)&Bs[kk][col0 + j];
#pragma unroll
            for (int i = 0; i < 4; i++)
#pragma unroll
                for (int j = 0; j < 16; j++) acc[i][j] += av[i] * bv[j];
        }
        __syncthreads();
    }

#pragma unroll
    for (int i = 0; i < 4; i++) {
        const int mm = m0 + row0 + i;
        if (mm < M) {
            float* cp = (col0 < 128)
                ? Ps + (size_t)mm * 128 + col0
                : Pd + (size_t)mm * 128 + (col0 - 128);
#pragma unroll
            for (int j = 0; j < 16; j += 4)
                *(float4*)(cp + j) = *(float4*)&acc[i][j];
        }
    }
}

__global__ __launch_bounds__(256) void node_fused_k(
    const float* __restrict__ V, const float* __restrict__ mi,
    const float* __restrict__ Wh1, const float* __restrict__ bh1,
    const float* __restrict__ Wh2, const float* __restrict__ bh2,
    float* __restrict__ Vraw, float* __restrict__ part, int M, int nblk)
{
    __shared__ float VH[64 * 132 + 4];
    __shared__ float As[16][68];
    __shared__ float Bs[16][132];
    __shared__ float sstat[256];

    const int tid  = threadIdx.x;
    const int m0   = blockIdx.x * 64;
    const int arow = tid >> 2;
    const int akb  = (tid & 3) * 4;
    const int brow = tid >> 4;
    const int bcol = (tid & 15) * 8;
    const int gm   = m0 + arow;
    const bool mval = (gm < M);
    const int row0 = (tid >> 4) * 4;
    const int col0 = (tid & 15) * 8;

    sstat[tid] = 0.f;

    float accA[4][8];
#pragma unroll
    for (int i = 0; i < 4; i++)
#pragma unroll
        for (int j = 0; j < 8; j++) accA[i][j] = 0.f;

    for (int kt = 0; kt < 16; kt++) {
        const int kbase = kt * 16;
        {
            const float* wp = Wh1 + (size_t)(kbase + brow) * 128 + bcol;
#pragma unroll
            for (int j = 0; j < 8; j += 4)
                *(float4*)&Bs[brow][bcol + j] = *(const float4*)(wp + j);
        }
#pragma unroll
        for (int i = 0; i < 4; i++) {
            const int gk = kbase + akb + i;
            float v = 0.f;
            if (mval)
                v = (gk < 128) ? V[(size_t)gm * 128 + gk]
                               : mi[(size_t)gm * 128 + (gk - 128)];
            As[akb + i][arow] = v;
        }
        __syncthreads();
#pragma unroll
        for (int kk = 0; kk < 16; kk++) {
            float4 a = *(const float4*)&As[kk][row0];
            float4 b0 = *(const float4*)&Bs[kk][col0];
            float4 b1 = *(const float4*)&Bs[kk][col0 + 4];
            float av[4] = {a.x, a.y, a.z, a.w};
            float bv[8] = {b0.x, b0.y, b0.z, b0.w, b1.x, b1.y, b1.z, b1.w};
#pragma unroll
            for (int i = 0; i < 4; i++)
#pragma unroll
                for (int j = 0; j < 8; j++) accA[i][j] += av[i] * bv[j];
        }
        __syncthreads();
    }
    {
        float b[8];
        *(float4*)b       = *(const float4*)(bh1 + col0);
        *(float4*)(b + 4) = *(const float4*)(bh1 + col0 + 4);
#pragma unroll
        for (int i = 0; i < 4; i++) {
            float* trow = VH + ts_off(row0 + i, col0);
            float o[8];
#pragma unroll
            for (int j = 0; j < 8; j++) o[j] = silu_f(accA[i][j] + b[j]);
            *(float4*)trow       = *(float4*)&o[0];
            *(float4*)(trow + 4) = *(float4*)&o[4];
        }
    }
    __syncthreads();

    ull acc[4][4];
#pragma unroll
    for (int i = 0; i < 4; i++)
#pragma unroll
        for (int j = 0; j < 4; j++) acc[i][j] = 0ULL;

    for (int kt = 0; kt < 8; kt++) {
        const int kbase = kt * 16;
        {
            const float* wp = Wh2 + (size_t)(kbase + brow) * 128 + bcol;
#pragma unroll
            for (int j = 0; j < 8; j += 4)
                *(float4*)&Bs[brow][bcol + j] = *(const float4*)(wp + j);
        }
        __syncthreads();
        gemm_tile4(acc, VH, &Bs[0][0], kbase, row0, col0);
        __syncthreads();
    }
    {
        float b[8];
        *(float4*)b       = *(const float4*)(bh2 + col0);
        *(float4*)(b + 4) = *(const float4*)(bh2 + col0 + 4);
        float cs[8], cq[8];
#pragma unroll
        for (int j = 0; j < 8; j++) { cs[j] = 0.f; cq[j] = 0.f; }
#pragma unroll
        for (int i = 0; i < 4; i++) {
            const int mm = m0 + row0 + i;
            if (mm < M) {
                float o[8];
#pragma unroll
                for (int jp = 0; jp < 4; jp++) {
                    float2 c = unpk(acc[i][jp]);
                    o[2 * jp]     = c.x + b[2 * jp];
                    o[2 * jp + 1] = c.y + b[2 * jp + 1];
                }
                float* cp = Vraw + (size_t)mm * 128 + col0;
                *(float4*)cp       = *(float4*)&o[0];
                *(float4*)(cp + 4) = *(float4*)&o[4];
#pragma unroll
                for (int j = 0; j < 8; j++) {
                    float e = elu_f(o[j]);
                    cs[j] += e;
                    cq[j] += e * e;
                }
            }
        }
        __syncthreads();
#pragma unroll
        for (int j = 0; j < 8; j++) {
            atomicAdd(&sstat[col0 + j], cs[j]);
            atomicAdd(&sstat[128 + col0 + j], cq[j]);
        }
        __syncthreads();
        if (tid < 128) {
            part[blockIdx.x * 128 + tid] = sstat[tid];
            part[(nblk + blockIdx.x) * 128 + tid] = sstat[128 + tid];
        }
    }
}

// ---------------- small kernels ----------------
__global__ void init_nodes_k(const float* __restrict__ emb,
                             const float* __restrict__ Wn,
                             const float* __restrict__ bn)
{
    int idx = blockIdx.x * blockDim.x + threadIdx.x;
    if (idx < N_NODES * 3) g_coords[idx] = emb[idx];
    if (idx < N_NODES * HDIM) {
        int n = idx >> 7, j = idx & 127;
        g_V[idx] = emb[n * 3 + 0] * Wn[0 * 128 + j]
                 + emb[n * 3 + 1] * Wn[1 * 128 + j]
                 + emb[n * 3 + 2] * Wn[2 * 128 + j]
                 + bn[j];
    }
}

__global__ void coords_update_k()
{
    int idx = blockIdx.x * blockDim.x + threadIdx.x;
    if (idx < N_NODES * 3)
        g_coords[idx] += g_accum[idx] * (1.0f / (float)(N_NODES - 1));
}

__global__ void bn_stats2_k(const float* __restrict__ part, int B, int M)
{
    int j = threadIdx.x;
    double s = 0.0, q = 0.0;
    for (int b = 0; b < B; b++) {
        s += (double)part[b * 128 + j];
        q += (double)part[(B + b) * 128 + j];
    }
    double mu  = s / (double)M;
    double var = q / (double)M - mu * mu;
    g_muinv[j]       = (float)mu;
    g_muinv[128 + j] = (float)rsqrt(var + (double)BN_EPS);
}

__global__ void bn_norm_k(const float* __restrict__ X,
                          const float* __restrict__ gam,
                          const float* __restrict__ bet,
                          float* __restrict__ out, int M)
{
    int idx = blockIdx.x * blockDim.x + threadIdx.x;
    if (idx >= M * 128) return;
    int j = idx & 127;
    float x = elu_f(X[idx]);
    out[idx] = gam[j] * (x - g_muinv[j]) * g_muinv[128 + j] + bet[j];
}

// ---------------- host launcher ----------------
static void* sym_addr(const void* sym)
{
    void* p = nullptr;
    cudaGetSymbolAddress(&p, sym);
    return p;
}

extern "C" void kernel_launch(void* const* d_in, const int* in_sizes, int n_in,
                              void* d_out, int out_size)
{
    (void)in_sizes; (void)n_in; (void)out_size;

    const float* emb_nodes = (const float*)d_in[0];
    const float* emb_edges = (const float*)d_in[1];
    const int*   edge_idx  = (const int*)d_in[2];
    const float* pre_Wn    = (const float*)d_in[3];
    const float* pre_bn    = (const float*)d_in[4];
    const float* We1 = (const float*)d_in[7];
    const float* be1 = (const float*)d_in[8];
    const float* We2 = (const float*)d_in[9];
    const float* be2 = (const float*)d_in[10];
    const float* Wx1 = (const float*)d_in[11];
    const float* bx1 = (const float*)d_in[12];
    const float* Wx2 = (const float*)d_in[13];
    const float* bx2 = (const float*)d_in[14];
    const float* Wh1 = (const float*)d_in[15];
    const float* bh1 = (const float*)d_in[16];
    const float* Wh2 = (const float*)d_in[17];
    const float* bh2 = (const float*)d_in[18];
    const float* gam_n = (const float*)d_in[19];
    const float* bet_n = (const float*)d_in[20];
    const float* gam_e = (const float*)d_in[21];
    const float* bet_e = (const float*)d_in[22];

    float* out  = (float*)d_out;
    float* outV = out;
    float* outE = out + (size_t)N_NODES * HDIM;

    const int* srcv = edge_idx;
    const int* dstv = edge_idx + N_EDGES;

    float* pV     = (float*)sym_addr(g_V);
    float* pVraw  = (float*)sym_addr(g_Vraw);
    float* pVH    = (float*)sym_addr(g_VH);
    float* pMi    = (float*)sym_addr(g_mi);
    float* pMij   = (float*)sym_addr(g_mij);
    float* pPartE = (float*)sym_addr(g_partE);
    float* pPartN = (float*)sym_addr(g_partN);
    __nv_bfloat16* pWbhi = (__nv_bfloat16*)sym_addr(g_wbhi);
    __nv_bfloat16* pWblo = (__nv_bfloat16*)sym_addr(g_wblo);

    const int EDGE_SMEM = 12816 + 2 * A_TILE_BYTES + 2 * B_TILE_BYTES; // 221712
    cudaFuncSetAttribute(edge_mma_k,
                         cudaFuncAttributeMaxDynamicSharedMemorySize, EDGE_SMEM);

    const int TB = 256;
    const int nodeHBlocks = (N_NODES * HDIM + TB - 1) / TB;
    const int edgeHBlocks = (N_EDGES * HDIM + TB - 1) / TB;

    init_nodes_k<<<nodeHBlocks, TB>>>(emb_nodes, pre_Wn, pre_bn);
    convw_k<<<(NLAYERS * 2 * 16384 + 255) / 256, 256>>>(We2, Wx1);

    for (int l = 0; l < NLAYERS; l++) {
        const float* We1l = We1 + (size_t)l * 259 * 128;
        const float* be1l = be1 + l * 128;
        const float* be2l = be2 + l * 128;
        const float* bx1l = bx1 + l * 128;
        const float* Wx2l = Wx2 + (size_t)l * 128 * 3;
        const float* bx2l = bx2 + l * 3;
        const float* Wh1l = Wh1 + (size_t)l * 256 * 128;
        const float* bh1l = bh1 + l * 128;
        const float* Wh2l = Wh2 + (size_t)l * 128 * 128;
        const float* bh2l = bh2 + l * 128;

        proj_k<<<NODE_TILES, 256>>>(pV, We1l, pVH, pVraw, N_NODES);

        edge_mma_k<<<EDGE_TILES, 512, EDGE_SMEM>>>(
            srcv, dstv, emb_edges, pVH, pVraw,
            We1l + 256 * 128, be1l, be2l, bx1l, Wx2l, bx2l,
            pWbhi + (size_t)l * 2 * 16384, pWblo + (size_t)l * 2 * 16384,
            (l == NLAYERS - 1) ? 1 : 0);

        coords_update_k<<<(N_NODES * 3 + TB - 1) / TB, TB>>>();

        node_fused_k<<<NODE_TILES, 256>>>(
            pV, pMi, Wh1l, bh1l, Wh2l, bh2l,
            pVraw, pPartN, N_NODES, NODE_TILES);

        bn_stats2_k<<<1, 128>>>(pPartN, NODE_TILES, N_NODES);
        float* vdst = (l == NLAYERS - 1) ? outV : pV;
        bn_norm_k<<<nodeHBlocks, TB>>>(pVraw, gam_n + l * 128, bet_n + l * 128,
                                       vdst, N_NODES);

        if (l == NLAYERS - 1) {
            bn_stats2_k<<<1, 128>>>(pPartE, EDGE_TILES, N_EDGES);
            bn_norm_k<<<edgeHBlocks, TB>>>(pMij, gam_e + l * 128, bet_e + l * 128,
                                           outE, N_EDGES);
        }
    }
}

// round 15
// speedup vs baseline: 2.2439x; 1.2506x over previous
#include <cuda_runtime.h>
#include <cuda_bf16.h>
#include <math.h>
#include <stdint.h>

#define N_NODES 10000
#define N_EDGES 160000
#define HDIM    128
#define NLAYERS 3
#define BN_EPS  1e-5f

#define EDGE_CTA   256
#define EDGE_TILES (N_EDGES / EDGE_CTA)   // 625
#define NODE_TILES ((N_NODES + 63) / 64)  // 157
#define NMAT 7                            // bf16 weight matrices per layer

// bf16 tile row stride: 136 bf16 = 272 B
#define TROW 272
#define A_TILE_BYTES (256 * TROW)         // 69632
#define B_TILE_BYTES (128 * TROW)         // 34816
#define A64_TILE     (64 * TROW)          // 17408

// ---------------- device scratch ----------------
__device__ float g_coords[N_NODES * 3];
__device__ float g_V[N_NODES * HDIM];
__device__ float g_Vraw[N_NODES * HDIM];   // Pd during edge phase
__device__ float g_VH[N_NODES * HDIM];     // Ps during edge phase
__device__ float g_mi[N_NODES * HDIM];
__device__ float g_accum[N_NODES * 3];
__device__ float g_mij[N_EDGES * HDIM];
__device__ float g_partE[2 * EDGE_TILES * HDIM];
__device__ float g_partN[2 * 160 * HDIM];
__device__ float g_muinv[2 * HDIM];
// bf16 weight images, [layer][m][n*128+k]; m: 0=We2t 1=Wx1t 2=We1at 3=We1bt
// 4=Wh1t_c0 5=Wh1t_c1 6=Wh2t
__device__ __nv_bfloat16 g_wbhi[NLAYERS * NMAT * 16384];
__device__ __nv_bfloat16 g_wblo[NLAYERS * NMAT * 16384];

__device__ __forceinline__ float silu_f(float x) { return x / (1.0f + expf(-x)); }
__device__ __forceinline__ float elu_f(float x)  { return x > 0.0f ? x : (expf(x) - 1.0f); }

__device__ __forceinline__ void red_add_v2(float* addr, float x, float y) {
    asm volatile("red.global.add.v2.f32 [%0], {%1,%2};"
                 :: "l"(addr), "f"(x), "f"(y) : "memory");
}
__device__ __forceinline__ uint32_t pk_bf2(float x, float y) {
    __nv_bfloat162 t = __floats2bfloat162_rn(x, y);
    return *(uint32_t*)&t;
}
__device__ __forceinline__ float bf_hi(float x) {
    return __bfloat162float(__float2bfloat16(x));
}

__device__ __forceinline__ void mma16816(float* d, uint32_t a0, uint32_t a1,
                                         uint32_t a2, uint32_t a3,
                                         uint32_t b0, uint32_t b1) {
    asm("mma.sync.aligned.m16n8k16.row.col.f32.bf16.bf16.f32 "
        "{%0,%1,%2,%3}, {%4,%5,%6,%7}, {%8,%9}, {%0,%1,%2,%3};"
        : "+f"(d[0]), "+f"(d[1]), "+f"(d[2]), "+f"(d[3])
        : "r"(a0), "r"(a1), "r"(a2), "r"(a3), "r"(b0), "r"(b1));
}
__device__ __forceinline__ void ldsm4(uint32_t* r, uint32_t addr) {
    asm volatile("ldmatrix.sync.aligned.m8n8.x4.shared.b16 {%0,%1,%2,%3}, [%4];"
        : "=r"(r[0]), "=r"(r[1]), "=r"(r[2]), "=r"(r[3]) : "r"(addr));
}

// warp GEMM 16 rows x 128 cols, K=128, bf16 split-3 (R14-validated)
__device__ __forceinline__ void warp_gemm3(float (&acc)[16][4],
                                           uint32_t AhS, uint32_t AlS,
                                           uint32_t BhS, uint32_t BlS,
                                           int aoff, int boff)
{
#pragma unroll
    for (int i = 0; i < 16; i++)
#pragma unroll
        for (int j = 0; j < 4; j++) acc[i][j] = 0.f;

#pragma unroll 2
    for (int ks = 0; ks < 8; ks++) {
        uint32_t ah[4], al[4];
        ldsm4(ah, AhS + aoff + ks * 32);
        ldsm4(al, AlS + aoff + ks * 32);
        const uint32_t bhb = BhS + boff + ks * 32;
        const uint32_t blb = BlS + boff + ks * 32;
#pragma unroll
        for (int ntp = 0; ntp < 8; ntp++) {
            uint32_t bh[4], bl[4];
            ldsm4(bh, bhb + ntp * 16 * TROW);
            ldsm4(bl, blb + ntp * 16 * TROW);
            mma16816(acc[2 * ntp],     ah[0], ah[1], ah[2], ah[3], bh[0], bh[1]);
            mma16816(acc[2 * ntp + 1], ah[0], ah[1], ah[2], ah[3], bh[2], bh[3]);
            mma16816(acc[2 * ntp],     al[0], al[1], al[2], al[3], bh[0], bh[1]);
            mma16816(acc[2 * ntp + 1], al[0], al[1], al[2], al[3], bh[2], bh[3]);
            mma16816(acc[2 * ntp],     ah[0], ah[1], ah[2], ah[3], bl[0], bl[1]);
            mma16816(acc[2 * ntp + 1], ah[0], ah[1], ah[2], ah[3], bl[2], bl[3]);
        }
    }
}

// warp GEMM 16 rows x 64 cols, K=128, bf16 split-3, optional accumulate
__device__ __forceinline__ void wg3h(float (&acc)[8][4],
                                     uint32_t AhS, uint32_t AlS,
                                     uint32_t BhS, uint32_t BlS,
                                     int aoff, int boff, bool first)
{
    if (first) {
#pragma unroll
        for (int i = 0; i < 8; i++)
#pragma unroll
            for (int j = 0; j < 4; j++) acc[i][j] = 0.f;
    }
#pragma unroll 2
    for (int ks = 0; ks < 8; ks++) {
        uint32_t ah[4], al[4];
        ldsm4(ah, AhS + aoff + ks * 32);
        ldsm4(al, AlS + aoff + ks * 32);
        const uint32_t bhb = BhS + boff + ks * 32;
        const uint32_t blb = BlS + boff + ks * 32;
#pragma unroll
        for (int ntp = 0; ntp < 4; ntp++) {
            uint32_t bh[4], bl[4];
            ldsm4(bh, bhb + ntp * 16 * TROW);
            ldsm4(bl, blb + ntp * 16 * TROW);
            mma16816(acc[2 * ntp],     ah[0], ah[1], ah[2], ah[3], bh[0], bh[1]);
            mma16816(acc[2 * ntp + 1], ah[0], ah[1], ah[2], ah[3], bh[2], bh[3]);
            mma16816(acc[2 * ntp],     al[0], al[1], al[2], al[3], bh[0], bh[1]);
            mma16816(acc[2 * ntp + 1], al[0], al[1], al[2], al[3], bh[2], bh[3]);
            mma16816(acc[2 * ntp],     ah[0], ah[1], ah[2], ah[3], bl[0], bl[1]);
            mma16816(acc[2 * ntp + 1], ah[0], ah[1], ah[2], ah[3], bl[2], bl[3]);
        }
    }
}

// ---------------- weight pre-convert (7 mats/layer) ----------------
__global__ void convw_k(const float* __restrict__ We2, const float* __restrict__ Wx1,
                        const float* __restrict__ We1, const float* __restrict__ Wh1,
                        const float* __restrict__ Wh2)
{
    int idx = blockIdx.x * 256 + threadIdx.x;
    if (idx >= NLAYERS * NMAT * 16384) return;
    int l = idx / (NMAT * 16384);
    int rest = idx % (NMAT * 16384);
    int m = rest / 16384;
    int e = rest & 16383;
    int n = e >> 7, k = e & 127;
    float x;
    switch (m) {
        case 0: x = We2[(size_t)l * 16384 + k * 128 + n]; break;
        case 1: x = Wx1[(size_t)l * 16384 + k * 128 + n]; break;
        case 2: x = We1[(size_t)l * 259 * 128 + k * 128 + n]; break;
        case 3: x = We1[(size_t)l * 259 * 128 + (128 + k) * 128 + n]; break;
        case 4: x = Wh1[(size_t)l * 256 * 128 + k * 128 + n]; break;
        case 5: x = Wh1[(size_t)l * 256 * 128 + (128 + k) * 128 + n]; break;
        default: x = Wh2[(size_t)l * 16384 + k * 128 + n]; break;
    }
    __nv_bfloat16 h = __float2bfloat16(x);
    __nv_bfloat16 lo = __float2bfloat16(x - __bfloat162float(h));
    g_wbhi[(size_t)(l * NMAT + m) * 16384 + n * 128 + k] = h;
    g_wblo[(size_t)(l * NMAT + m) * 16384 + n * 128 + k] = lo;
}

// ---------------- fused edge pipeline (unchanged from R14) ------------------
__global__ __launch_bounds__(512)
void edge_mma_k(const int* __restrict__ srcv, const int* __restrict__ dstv,
                const float* __restrict__ ee,
                const float* __restrict__ Ps, const float* __restrict__ Pd,
                const float* __restrict__ wex_g, const float* __restrict__ be1,
                const float* __restrict__ be2, const float* __restrict__ bx1,
                const float* __restrict__ Wx2, const float* __restrict__ bx2,
                const __nv_bfloat16* __restrict__ WBhi,
                const __nv_bfloat16* __restrict__ WBlo,
                int write_mij)
{
    extern __shared__ char smc[];
    float* smf = (float*)smc;
    float* diffs = smf + 0;
    float* dists = smf + 768;
    int*   dsts  = (int*)(smf + 1024);
    float* ee0s  = smf + 1280;
    float* ee1s  = smf + 1536;
    float* wex   = smf + 1792;
    float* be1s  = smf + 2176;
    float* be2s  = smf + 2304;
    float* bx1s  = smf + 2432;
    float* wx2s  = smf + 2560;
    float* bx2s  = smf + 2944;
    float* es    = smf + 2948;
    char* Ah = smc + 12816;
    char* Al = Ah + A_TILE_BYTES;
    char* Bh = Al + A_TILE_BYTES;
    char* Bl = Bh + B_TILE_BYTES;

    const int tid  = threadIdx.x;
    const int wid  = tid >> 5;
    const int lane = tid & 31;
    const int g    = lane >> 2;
    const int q    = lane & 3;
    const int m0   = blockIdx.x * EDGE_CTA;

    const uint32_t AhS = (uint32_t)__cvta_generic_to_shared(Ah);
    const uint32_t AlS = (uint32_t)__cvta_generic_to_shared(Al);
    const uint32_t BhS = (uint32_t)__cvta_generic_to_shared(Bh);
    const uint32_t BlS = (uint32_t)__cvta_generic_to_shared(Bl);

    if (tid < 256) {
        int mm = m0 + tid;
        int s = srcv[mm], d = dstv[mm];
        float dx = g_coords[d * 3 + 0] - g_coords[s * 3 + 0];
        float dy = g_coords[d * 3 + 1] - g_coords[s * 3 + 1];
        float dz = g_coords[d * 3 + 2] - g_coords[s * 3 + 2];
        diffs[tid * 3 + 0] = dx;
        diffs[tid * 3 + 1] = dy;
        diffs[tid * 3 + 2] = dz;
        dists[tid] = sqrtf(dx * dx + dy * dy + dz * dz);
        dsts[tid] = d;
        ee0s[tid] = ee[mm * 2 + 0];
        ee1s[tid] = ee[mm * 2 + 1];
        es[tid] = 0.f;
    }
    if (tid < 128) { be1s[tid] = be1[tid]; be2s[tid] = be2[tid]; bx1s[tid] = bx1[tid]; }
    for (int i = tid; i < 384; i += 512) { wex[i] = wex_g[i]; wx2s[i] = Wx2[i]; }
    if (tid < 3) bx2s[tid] = bx2[tid];

    {
        const uint4* shi = (const uint4*)WBhi;
        const uint4* slo = (const uint4*)WBlo;
#pragma unroll
        for (int i = 0; i < 4; i++) {
            int p = tid + i * 512;
            int row = p >> 4, chunk = p & 15;
            *(uint4*)(Bh + row * TROW + chunk * 16) = shi[p];
            *(uint4*)(Bl + row * TROW + chunk * 16) = slo[p];
        }
    }
    __syncthreads();

    {
        const int r  = tid >> 1;
        const int cb = (tid & 1) * 64;
        const int mm = m0 + r;
        const int s  = srcv[mm];
        const float* psp = Ps + (size_t)s * 128;
        const float* pdp = Pd + (size_t)dsts[r] * 128;
        const float di = dists[r];
        const float e0 = ee0s[r], e1 = ee1s[r];
        for (int c = cb; c < cb + 64; c += 8) {
            float o[8];
#pragma unroll
            for (int h = 0; h < 8; h += 4) {
                float4 a = *(const float4*)(psp + c + h);
                float4 b = *(const float4*)(pdp + c + h);
                o[h+0] = silu_f(a.x + b.x + di * wex[c+h+0] + e0 * wex[128+c+h+0] + e1 * wex[256+c+h+0] + be1s[c+h+0]);
                o[h+1] = silu_f(a.y + b.y + di * wex[c+h+1] + e0 * wex[128+c+h+1] + e1 * wex[256+c+h+1] + be1s[c+h+1]);
                o[h+2] = silu_f(a.z + b.z + di * wex[c+h+2] + e0 * wex[128+c+h+2] + e1 * wex[256+c+h+2] + be1s[c+h+2]);
                o[h+3] = silu_f(a.w + b.w + di * wex[c+h+3] + e0 * wex[128+c+h+3] + e1 * wex[256+c+h+3] + be1s[c+h+3]);
            }
            uint32_t H[4], L[4];
#pragma unroll
            for (int j = 0; j < 4; j++) {
                float hx = bf_hi(o[2*j]), hy = bf_hi(o[2*j+1]);
                H[j] = pk_bf2(o[2*j], o[2*j+1]);
                L[j] = pk_bf2(o[2*j] - hx, o[2*j+1] - hy);
            }
            *(uint4*)(Ah + r * TROW + c * 2) = *(uint4*)H;
            *(uint4*)(Al + r * TROW + c * 2) = *(uint4*)L;
        }
    }
    __syncthreads();

    const int arow = wid * 16 + (lane & 7) + ((lane & 8) ? 8 : 0);
    const int aoff = arow * TROW + ((lane >> 4) & 1) * 16;
    const int brow = (lane & 7) + (((lane >> 4) & 1) << 3);
    const int boff = brow * TROW + ((lane & 8) ? 16 : 0);

    const int r0 = wid * 16 + g, r1 = r0 + 8;

    float acc[16][4];

    warp_gemm3(acc, AhS, AlS, BhS, BlS, aoff, boff);

    {
        const int d0 = dsts[r0], d1 = dsts[r1];
#pragma unroll
        for (int nt = 0; nt < 16; nt++) {
            const int c = nt * 8 + q * 2;
            float v00 = silu_f(acc[nt][0] + be2s[c]);
            float v01 = silu_f(acc[nt][1] + be2s[c + 1]);
            float v10 = silu_f(acc[nt][2] + be2s[c]);
            float v11 = silu_f(acc[nt][3] + be2s[c + 1]);
            red_add_v2(&g_mi[(size_t)d0 * 128 + c], v00, v01);
            red_add_v2(&g_mi[(size_t)d1 * 128 + c], v10, v11);
            if (write_mij) {
                *(float2*)(g_mij + (size_t)(m0 + r0) * 128 + c) = make_float2(v00, v01);
                *(float2*)(g_mij + (size_t)(m0 + r1) * 128 + c) = make_float2(v10, v11);
                float e00 = elu_f(v00), e01 = elu_f(v01);
                float e10 = elu_f(v10), e11 = elu_f(v11);
                float s0 = e00 + e10, s1 = e01 + e11;
                float q0 = e00 * e00 + e10 * e10, q1 = e01 * e01 + e11 * e11;
#pragma unroll
                for (int o = 4; o < 32; o <<= 1) {
                    s0 += __shfl_xor_sync(0xFFFFFFFF, s0, o);
                    s1 += __shfl_xor_sync(0xFFFFFFFF, s1, o);
                    q0 += __shfl_xor_sync(0xFFFFFFFF, q0, o);
                    q1 += __shfl_xor_sync(0xFFFFFFFF, q1, o);
                }
                if (lane < 4) {
                    atomicAdd(&es[c], s0);
                    atomicAdd(&es[c + 1], s1);
                    atomicAdd(&es[128 + c], q0);
                    atomicAdd(&es[128 + c + 1], q1);
                }
            }
            float h00 = bf_hi(v00), h01 = bf_hi(v01);
            float h10 = bf_hi(v10), h11 = bf_hi(v11);
            *(uint32_t*)(Ah + r0 * TROW + c * 2) = pk_bf2(v00, v01);
            *(uint32_t*)(Ah + r1 * TROW + c * 2) = pk_bf2(v10, v11);
            *(uint32_t*)(Al + r0 * TROW + c * 2) = pk_bf2(v00 - h00, v01 - h01);
            *(uint32_t*)(Al + r1 * TROW + c * 2) = pk_bf2(v10 - h10, v11 - h11);
        }
    }
    __syncthreads();
    if (write_mij && tid < 128) {
        g_partE[blockIdx.x * 128 + tid] = es[tid];
        g_partE[(EDGE_TILES + blockIdx.x) * 128 + tid] = es[128 + tid];
    }
    {
        const uint4* shi = (const uint4*)(WBhi + 16384);
        const uint4* slo = (const uint4*)(WBlo + 16384);
#pragma unroll
        for (int i = 0; i < 4; i++) {
            int p = tid + i * 512;
            int row = p >> 4, chunk = p & 15;
            *(uint4*)(Bh + row * TROW + chunk * 16) = shi[p];
            *(uint4*)(Bl + row * TROW + chunk * 16) = slo[p];
        }
    }
    __syncthreads();

    warp_gemm3(acc, AhS, AlS, BhS, BlS, aoff, boff);

    {
        float pa0 = 0.f, pa1 = 0.f, pa2 = 0.f;
        float pb0 = 0.f, pb1 = 0.f, pb2 = 0.f;
#pragma unroll
        for (int nt = 0; nt < 16; nt++) {
            const int c = nt * 8 + q * 2;
            float t00 = silu_f(acc[nt][0] + bx1s[c]);
            float t01 = silu_f(acc[nt][1] + bx1s[c + 1]);
            float t10 = silu_f(acc[nt][2] + bx1s[c]);
            float t11 = silu_f(acc[nt][3] + bx1s[c + 1]);
            float w00 = wx2s[c * 3 + 0], w01 = wx2s[c * 3 + 1], w02 = wx2s[c * 3 + 2];
            float w10 = wx2s[c * 3 + 3], w11 = wx2s[c * 3 + 4], w12 = wx2s[c * 3 + 5];
            pa0 += t00 * w00 + t01 * w10;
            pa1 += t00 * w01 + t01 * w11;
            pa2 += t00 * w02 + t01 * w12;
            pb0 += t10 * w00 + t11 * w10;
            pb1 += t10 * w01 + t11 * w11;
            pb2 += t10 * w02 + t11 * w12;
        }
#pragma unroll
        for (int o = 1; o < 4; o <<= 1) {
            pa0 += __shfl_xor_sync(0xFFFFFFFF, pa0, o);
            pa1 += __shfl_xor_sync(0xFFFFFFFF, pa1, o);
            pa2 += __shfl_xor_sync(0xFFFFFFFF, pa2, o);
            pb0 += __shfl_xor_sync(0xFFFFFFFF, pb0, o);
            pb1 += __shfl_xor_sync(0xFFFFFFFF, pb1, o);
            pb2 += __shfl_xor_sync(0xFFFFFFFF, pb2, o);
        }
        if (q == 0) {
            const int d0 = dsts[r0], d1 = dsts[r1];
            float x0 = pa0 + bx2s[0], x1 = pa1 + bx2s[1], x2 = pa2 + bx2s[2];
            atomicAdd(&g_accum[d0 * 3 + 0], diffs[r0 * 3 + 0] * x0);
            atomicAdd(&g_accum[d0 * 3 + 1], diffs[r0 * 3 + 1] * x1);
            atomicAdd(&g_accum[d0 * 3 + 2], diffs[r0 * 3 + 2] * x2);
            float y0 = pb0 + bx2s[0], y1 = pb1 + bx2s[1], y2 = pb2 + bx2s[2];
            atomicAdd(&g_accum[d1 * 3 + 0], diffs[r1 * 3 + 0] * y0);
            atomicAdd(&g_accum[d1 * 3 + 1], diffs[r1 * 3 + 1] * y1);
            atomicAdd(&g_accum[d1 * 3 + 2], diffs[r1 * 3 + 2] * y2);
        }
    }
}

// ---------------- proj_tc_k: [Ps|Pd] = V @ We1[0:256], tensor path ----------
// CTA = 64 node rows, 256 thr; warp = 16 rows x 128 cols; wid&1 -> Ps/Pd.
// smem: Ah 0 | Al 17408 | Bh 34816 (256 rows) | Bl 104448 ; total 174080
__global__ __launch_bounds__(256)
void proj_tc_k(const float* __restrict__ V,
               const __nv_bfloat16* __restrict__ WBhi,   // base at m2 (We1at)
               const __nv_bfloat16* __restrict__ WBlo,
               float* __restrict__ Ps, float* __restrict__ Pd, int M)
{
    extern __shared__ char smc[];
    char* Ah = smc;
    char* Al = smc + A64_TILE;
    char* Bh = smc + 2 * A64_TILE;
    char* Bl = Bh + 2 * B_TILE_BYTES;

    const int tid  = threadIdx.x;
    const int wid  = tid >> 5;
    const int lane = tid & 31;
    const int g    = lane >> 2;
    const int q    = lane & 3;
    const int rg   = wid >> 1;
    const int out  = wid & 1;
    const int mb   = blockIdx.x * 64;

    const uint32_t AhS = (uint32_t)__cvta_generic_to_shared(Ah);
    const uint32_t AlS = (uint32_t)__cvta_generic_to_shared(Al);
    const uint32_t BhS = (uint32_t)__cvta_generic_to_shared(Bh);
    const uint32_t BlS = (uint32_t)__cvta_generic_to_shared(Bl);

    // zero g_mi / g_accum for this CTA's rows
    {
        int r = tid >> 2, c = (tid & 3) * 32;
        if (mb + r < M) {
            float4 z = make_float4(0.f, 0.f, 0.f, 0.f);
            float* p = g_mi + (size_t)(mb + r) * 128 + c;
#pragma unroll
            for (int j = 0; j < 8; j++) *(float4*)(p + j * 4) = z;
        }
        if (tid < 192 && mb + tid / 3 < M)
            g_accum[(size_t)mb * 3 + tid] = 0.f;
    }

    // B copy: 256 rows x 16 uint4 = 4096 uint4 (hi and lo)
    {
        const uint4* shi = (const uint4*)WBhi;
        const uint4* slo = (const uint4*)WBlo;
#pragma unroll
        for (int i = 0; i < 16; i++) {
            int p = tid + i * 256;
            int row = p >> 4, chunk = p & 15;
            *(uint4*)(Bh + row * TROW + chunk * 16) = shi[p];
            *(uint4*)(Bl + row * TROW + chunk * 16) = slo[p];
        }
    }

    // A conversion: V rows -> bf16 hi/lo
    {
        const int r  = tid >> 2;
        const int cb = (tid & 3) * 32;
        const int gm = mb + r;
        for (int c = cb; c < cb + 32; c += 8) {
            float o[8];
            if (gm < M) {
                *(float4*)o       = *(const float4*)(V + (size_t)gm * 128 + c);
                *(float4*)(o + 4) = *(const float4*)(V + (size_t)gm * 128 + c + 4);
            } else {
#pragma unroll
                for (int j = 0; j < 8; j++) o[j] = 0.f;
            }
            uint32_t H[4], L[4];
#pragma unroll
            for (int j = 0; j < 4; j++) {
                float hx = bf_hi(o[2*j]), hy = bf_hi(o[2*j+1]);
                H[j] = pk_bf2(o[2*j], o[2*j+1]);
                L[j] = pk_bf2(o[2*j] - hx, o[2*j+1] - hy);
            }
            *(uint4*)(Ah + r * TROW + c * 2) = *(uint4*)H;
            *(uint4*)(Al + r * TROW + c * 2) = *(uint4*)L;
        }
    }
    __syncthreads();

    const int arow = rg * 16 + (lane & 7) + ((lane & 8) ? 8 : 0);
    const int aoff = arow * TROW + ((lane >> 4) & 1) * 16;
    const int brow = (lane & 7) + (((lane >> 4) & 1) << 3);
    const int boff = (out * 128 + brow) * TROW + ((lane & 8) ? 16 : 0);

    float acc[16][4];
    warp_gemm3(acc, AhS, AlS, BhS, BlS, aoff, boff);

    float* O = out ? Pd : Ps;
    const int gr0 = mb + rg * 16 + g, gr1 = gr0 + 8;
#pragma unroll
    for (int nt = 0; nt < 16; nt++) {
        const int c = nt * 8 + q * 2;
        if (gr0 < M) *(float2*)(O + (size_t)gr0 * 128 + c) = make_float2(acc[nt][0], acc[nt][1]);
        if (gr1 < M) *(float2*)(O + (size_t)gr1 * 128 + c) = make_float2(acc[nt][2], acc[nt][3]);
    }
}

// ---------------- node_fused_tc_k: VH=silu([V,mi]@Wh1+bh1); Vraw=VH@Wh2+bh2 -
// CTA = 64 rows, 256 thr; warp = 16 rows x 64 cols (rg = wid>>1, nh = wid&1).
// smem: A0h 0 | A0l | A1h | A1l (4x17408) | Bh 69632 | Bl 104448 |
//       bh1s @139264 | bh2s @139776 | es @140288 ; total 141312
__global__ __launch_bounds__(256)
void node_fused_tc_k(const float* __restrict__ V, const float* __restrict__ mi,
                     const __nv_bfloat16* __restrict__ WBhi,  // layer base (m0)
                     const __nv_bfloat16* __restrict__ WBlo,
                     const float* __restrict__ bh1, const float* __restrict__ bh2,
                     float* __restrict__ Vraw, float* __restrict__ part,
                     int M, int nblk)
{
    extern __shared__ char smc[];
    char* A0h = smc;
    char* A0l = smc + A64_TILE;
    char* A1h = smc + 2 * A64_TILE;
    char* A1l = smc + 3 * A64_TILE;
    char* Bh  = smc + 4 * A64_TILE;
    char* Bl  = Bh + B_TILE_BYTES;
    float* bh1s = (float*)(smc + 139264);
    float* bh2s = (float*)(smc + 139776);
    float* es   = (float*)(smc + 140288);

    const int tid  = threadIdx.x;
    const int wid  = tid >> 5;
    const int lane = tid & 31;
    const int g    = lane >> 2;
    const int q    = lane & 3;
    const int rg   = wid >> 1;
    const int nh   = wid & 1;
    const int mb   = blockIdx.x * 64;

    const uint32_t A0hS = (uint32_t)__cvta_generic_to_shared(A0h);
    const uint32_t A0lS = (uint32_t)__cvta_generic_to_shared(A0l);
    const uint32_t A1hS = (uint32_t)__cvta_generic_to_shared(A1h);
    const uint32_t A1lS = (uint32_t)__cvta_generic_to_shared(A1l);
    const uint32_t BhS  = (uint32_t)__cvta_generic_to_shared(Bh);
    const uint32_t BlS  = (uint32_t)__cvta_generic_to_shared(Bl);

    if (tid < 128) { bh1s[tid] = bh1[tid]; bh2s[tid] = bh2[tid]; }
    es[tid] = 0.f;

    // B copy Wh1t chunk0 (m4)
    {
        const uint4* shi = (const uint4*)(WBhi + 4 * 16384);
        const uint4* slo = (const uint4*)(WBlo + 4 * 16384);
#pragma unroll
        for (int i = 0; i < 8; i++) {
            int p = tid + i * 256;
            int row = p >> 4, chunk = p & 15;
            *(uint4*)(Bh + row * TROW + chunk * 16) = shi[p];
            *(uint4*)(Bl + row * TROW + chunk * 16) = slo[p];
        }
    }

    // A0 <- V, A1 <- mi (bf16 hi/lo), guarded
    {
        const int r  = tid >> 2;
        const int cb = (tid & 3) * 32;
        const int gm = mb + r;
        for (int c = cb; c < cb + 32; c += 8) {
            float o0[8], o1[8];
            if (gm < M) {
                *(float4*)o0       = *(const float4*)(V + (size_t)gm * 128 + c);
                *(float4*)(o0 + 4) = *(const float4*)(V + (size_t)gm * 128 + c + 4);
                *(float4*)o1       = *(const float4*)(mi + (size_t)gm * 128 + c);
                *(float4*)(o1 + 4) = *(const float4*)(mi + (size_t)gm * 128 + c + 4);
            } else {
#pragma unroll
                for (int j = 0; j < 8; j++) { o0[j] = 0.f; o1[j] = 0.f; }
            }
            uint32_t H[4], L[4];
#pragma unroll
            for (int j = 0; j < 4; j++) {
                float hx = bf_hi(o0[2*j]), hy = bf_hi(o0[2*j+1]);
                H[j] = pk_bf2(o0[2*j], o0[2*j+1]);
                L[j] = pk_bf2(o0[2*j] - hx, o0[2*j+1] - hy);
            }
            *(uint4*)(A0h + r * TROW + c * 2) = *(uint4*)H;
            *(uint4*)(A0l + r * TROW + c * 2) = *(uint4*)L;
#pragma unroll
            for (int j = 0; j < 4; j++) {
                float hx = bf_hi(o1[2*j]), hy = bf_hi(o1[2*j+1]);
                H[j] = pk_bf2(o1[2*j], o1[2*j+1]);
                L[j] = pk_bf2(o1[2*j] - hx, o1[2*j+1] - hy);
            }
            *(uint4*)(A1h + r * TROW + c * 2) = *(uint4*)H;
            *(uint4*)(A1l + r * TROW + c * 2) = *(uint4*)L;
        }
    }
    __syncthreads();

    const int arow = rg * 16 + (lane & 7) + ((lane & 8) ? 8 : 0);
    const int aoff = arow * TROW + ((lane >> 4) & 1) * 16;
    const int brow = (lane & 7) + (((lane >> 4) & 1) << 3);
    const int boff = (nh * 64 + brow) * TROW + ((lane & 8) ? 16 : 0);

    const int r0 = rg * 16 + g, r1 = r0 + 8;

    float acc[8][4];

    // GEMM1 chunk0: [V] @ Wh1[0:128]
    wg3h(acc, A0hS, A0lS, BhS, BlS, aoff, boff, true);
    __syncthreads();
    // B <- Wh1t chunk1 (m5)
    {
        const uint4* shi = (const uint4*)(WBhi + 5 * 16384);
        const uint4* slo = (const uint4*)(WBlo + 5 * 16384);
#pragma unroll
        for (int i = 0; i < 8; i++) {
            int p = tid + i * 256;
            int row = p >> 4, chunk = p & 15;
            *(uint4*)(Bh + row * TROW + chunk * 16) = shi[p];
            *(uint4*)(Bl + row * TROW + chunk * 16) = slo[p];
        }
    }
    __syncthreads();
    // GEMM1 chunk1: [mi] @ Wh1[128:256], accumulate
    wg3h(acc, A1hS, A1lS, BhS, BlS, aoff, boff, false);

    // epilogue 1: VH = silu(acc + bh1) -> rewrite into A0 (warp-own rows/cols)
#pragma unroll
    for (int nt = 0; nt < 8; nt++) {
        const int c = nh * 64 + nt * 8 + q * 2;
        float v00 = silu_f(acc[nt][0] + bh1s[c]);
        float v01 = silu_f(acc[nt][1] + bh1s[c + 1]);
        float v10 = silu_f(acc[nt][2] + bh1s[c]);
        float v11 = silu_f(acc[nt][3] + bh1s[c + 1]);
        float h00 = bf_hi(v00), h01 = bf_hi(v01);
        float h10 = bf_hi(v10), h11 = bf_hi(v11);
        *(uint32_t*)(A0h + r0 * TROW + c * 2) = pk_bf2(v00, v01);
        *(uint32_t*)(A0h + r1 * TROW + c * 2) = pk_bf2(v10, v11);
        *(uint32_t*)(A0l + r0 * TROW + c * 2) = pk_bf2(v00 - h00, v01 - h01);
        *(uint32_t*)(A0l + r1 * TROW + c * 2) = pk_bf2(v10 - h10, v11 - h11);
    }
    __syncthreads();
    // B <- Wh2t (m6)
    {
        const uint4* shi = (const uint4*)(WBhi + 6 * 16384);
        const uint4* slo = (const uint4*)(WBlo + 6 * 16384);
#pragma unroll
        for (int i = 0; i < 8; i++) {
            int p = tid + i * 256;
            int row = p >> 4, chunk = p & 15;
            *(uint4*)(Bh + row * TROW + chunk * 16) = shi[p];
            *(uint4*)(Bl + row * TROW + chunk * 16) = slo[p];
        }
    }
    __syncthreads();

    // GEMM2: Vraw = VH @ Wh2 + bh2
    wg3h(acc, A0hS, A0lS, BhS, BlS, aoff, boff, true);

    // epilogue 2: store Vraw + BN stats
    {
        const int gr0 = mb + r0, gr1 = mb + r1;
        const bool ok0 = (gr0 < M), ok1 = (gr1 < M);
#pragma unroll
        for (int nt = 0; nt < 8; nt++) {
            const int c = nh * 64 + nt * 8 + q * 2;
            float v00 = acc[nt][0] + bh2s[c];
            float v01 = acc[nt][1] + bh2s[c + 1];
            float v10 = acc[nt][2] + bh2s[c];
            float v11 = acc[nt][3] + bh2s[c + 1];
            float s0 = 0.f, s1 = 0.f, q0 = 0.f, q1 = 0.f;
            if (ok0) {
                *(float2*)(Vraw + (size_t)gr0 * 128 + c) = make_float2(v00, v01);
                float e0 = elu_f(v00), e1 = elu_f(v01);
                s0 += e0; s1 += e1; q0 += e0 * e0; q1 += e1 * e1;
            }
            if (ok1) {
                *(float2*)(Vraw + (size_t)gr1 * 128 + c) = make_float2(v10, v11);
                float e0 = elu_f(v10), e1 = elu_f(v11);
                s0 += e0; s1 += e1; q0 += e0 * e0; q1 += e1 * e1;
            }
#pragma unroll
            for (int o = 4; o < 32; o <<= 1) {
                s0 += __shfl_xor_sync(0xFFFFFFFF, s0, o);
                s1 += __shfl_xor_sync(0xFFFFFFFF, s1, o);
                q0 += __shfl_xor_sync(0xFFFFFFFF, q0, o);
                q1 += __shfl_xor_sync(0xFFFFFFFF, q1, o);
            }
            if (lane < 4) {
                atomicAdd(&es[c], s0);
                atomicAdd(&es[c + 1], s1);
                atomicAdd(&es[128 + c], q0);
                atomicAdd(&es[128 + c + 1], q1);
            }
        }
    }
    __syncthreads();
    if (tid < 128) {
        part[blockIdx.x * 128 + tid] = es[tid];
        part[(nblk + blockIdx.x) * 128 + tid] = es[128 + tid];
    }
}

// ---------------- small kernels ----------------
__global__ void init_nodes_k(const float* __restrict__ emb,
                             const float* __restrict__ Wn,
                             const float* __restrict__ bn)
{
    int idx = blockIdx.x * blockDim.x + threadIdx.x;
    if (idx < N_NODES * 3) g_coords[idx] = emb[idx];
    if (idx < N_NODES * HDIM) {
        int n = idx >> 7, j = idx & 127;
        g_V[idx] = emb[n * 3 + 0] * Wn[0 * 128 + j]
                 + emb[n * 3 + 1] * Wn[1 * 128 + j]
                 + emb[n * 3 + 2] * Wn[2 * 128 + j]
                 + bn[j];
    }
}

__global__ void coords_update_k()
{
    int idx = blockIdx.x * blockDim.x + threadIdx.x;
    if (idx < N_NODES * 3)
        g_coords[idx] += g_accum[idx] * (1.0f / (float)(N_NODES - 1));
}

__global__ void bn_stats2_k(const float* __restrict__ part, int B, int M)
{
    int j = threadIdx.x;
    double s = 0.0, q = 0.0;
    for (int b = 0; b < B; b++) {
        s += (double)part[b * 128 + j];
        q += (double)part[(B + b) * 128 + j];
    }
    double mu  = s / (double)M;
    double var = q / (double)M - mu * mu;
    g_muinv[j]       = (float)mu;
    g_muinv[128 + j] = (float)rsqrt(var + (double)BN_EPS);
}

__global__ void bn_norm_k(const float* __restrict__ X,
                          const float* __restrict__ gam,
                          const float* __restrict__ bet,
                          float* __restrict__ out, int M)
{
    int idx = blockIdx.x * blockDim.x + threadIdx.x;
    if (idx >= M * 128) return;
    int j = idx & 127;
    float x = elu_f(X[idx]);
    out[idx] = gam[j] * (x - g_muinv[j]) * g_muinv[128 + j] + bet[j];
}

// ---------------- host launcher ----------------
static void* sym_addr(const void* sym)
{
    void* p = nullptr;
    cudaGetSymbolAddress(&p, sym);
    return p;
}

extern "C" void kernel_launch(void* const* d_in, const int* in_sizes, int n_in,
                              void* d_out, int out_size)
{
    (void)in_sizes; (void)n_in; (void)out_size;

    const float* emb_nodes = (const float*)d_in[0];
    const float* emb_edges = (const float*)d_in[1];
    const int*   edge_idx  = (const int*)d_in[2];
    const float* pre_Wn    = (const float*)d_in[3];
    const float* pre_bn    = (const float*)d_in[4];
    const float* We1 = (const float*)d_in[7];
    const float* be1 = (const float*)d_in[8];
    const float* We2 = (const float*)d_in[9];
    const float* be2 = (const float*)d_in[10];
    const float* Wx1 = (const float*)d_in[11];
    const float* bx1 = (const float*)d_in[12];
    const float* Wx2 = (const float*)d_in[13];
    const float* bx2 = (const float*)d_in[14];
    const float* Wh1 = (const float*)d_in[15];
    const float* bh1 = (const float*)d_in[16];
    const float* Wh2 = (const float*)d_in[17];
    const float* bh2 = (const float*)d_in[18];
    const float* gam_n = (const float*)d_in[19];
    const float* bet_n = (const float*)d_in[20];
    const float* gam_e = (const float*)d_in[21];
    const float* bet_e = (const float*)d_in[22];

    float* out  = (float*)d_out;
    float* outV = out;
    float* outE = out + (size_t)N_NODES * HDIM;

    const int* srcv = edge_idx;
    const int* dstv = edge_idx + N_EDGES;

    float* pV     = (float*)sym_addr(g_V);
    float* pVraw  = (float*)sym_addr(g_Vraw);
    float* pVH    = (float*)sym_addr(g_VH);
    float* pMi    = (float*)sym_addr(g_mi);
    float* pMij   = (float*)sym_addr(g_mij);
    float* pPartE = (float*)sym_addr(g_partE);
    float* pPartN = (float*)sym_addr(g_partN);
    __nv_bfloat16* pWbhi = (__nv_bfloat16*)sym_addr(g_wbhi);
    __nv_bfloat16* pWblo = (__nv_bfloat16*)sym_addr(g_wblo);

    const int EDGE_SMEM = 12816 + 2 * A_TILE_BYTES + 2 * B_TILE_BYTES; // 221712
    const int PROJ_SMEM = 2 * A64_TILE + 4 * B_TILE_BYTES;             // 174080
    const int NODE_SMEM = 141312;
    cudaFuncSetAttribute(edge_mma_k,
                         cudaFuncAttributeMaxDynamicSharedMemorySize, EDGE_SMEM);
    cudaFuncSetAttribute(proj_tc_k,
                         cudaFuncAttributeMaxDynamicSharedMemorySize, PROJ_SMEM);
    cudaFuncSetAttribute(node_fused_tc_k,
                         cudaFuncAttributeMaxDynamicSharedMemorySize, NODE_SMEM);

    const int TB = 256;
    const int nodeHBlocks = (N_NODES * HDIM + TB - 1) / TB;
    const int edgeHBlocks = (N_EDGES * HDIM + TB - 1) / TB;

    init_nodes_k<<<nodeHBlocks, TB>>>(emb_nodes, pre_Wn, pre_bn);
    convw_k<<<(NLAYERS * NMAT * 16384 + 255) / 256, 256>>>(We2, Wx1, We1, Wh1, Wh2);

    for (int l = 0; l < NLAYERS; l++) {
        const float* We1l = We1 + (size_t)l * 259 * 128;
        const float* be1l = be1 + l * 128;
        const float* be2l = be2 + l * 128;
        const float* bx1l = bx1 + l * 128;
        const float* Wx2l = Wx2 + (size_t)l * 128 * 3;
        const float* bx2l = bx2 + l * 3;
        const float* bh1l = bh1 + l * 128;
        const float* bh2l = bh2 + l * 128;
        const __nv_bfloat16* wbhi_l = pWbhi + (size_t)l * NMAT * 16384;
        const __nv_bfloat16* wblo_l = pWblo + (size_t)l * NMAT * 16384;

        proj_tc_k<<<NODE_TILES, 256, PROJ_SMEM>>>(
            pV, wbhi_l + 2 * 16384, wblo_l + 2 * 16384, pVH, pVraw, N_NODES);

        edge_mma_k<<<EDGE_TILES, 512, EDGE_SMEM>>>(
            srcv, dstv, emb_edges, pVH, pVraw,
            We1l + 256 * 128, be1l, be2l, bx1l, Wx2l, bx2l,
            wbhi_l, wblo_l,
            (l == NLAYERS - 1) ? 1 : 0);

        coords_update_k<<<(N_NODES * 3 + TB - 1) / TB, TB>>>();

        node_fused_tc_k<<<NODE_TILES, 256, NODE_SMEM>>>(
            pV, pMi, wbhi_l, wblo_l, bh1l, bh2l,
            pVraw, pPartN, N_NODES, NODE_TILES);

        bn_stats2_k<<<1, 128>>>(pPartN, NODE_TILES, N_NODES);
        float* vdst = (l == NLAYERS - 1) ? outV : pV;
        bn_norm_k<<<nodeHBlocks, TB>>>(pVraw, gam_n + l * 128, bet_n + l * 128,
                                       vdst, N_NODES);

        if (l == NLAYERS - 1) {
            bn_stats2_k<<<1, 128>>>(pPartE, EDGE_TILES, N_EDGES);
            bn_norm_k<<<edgeHBlocks, TB>>>(pMij, gam_e + l * 128, bet_e + l * 128,
                                           outE, N_EDGES);
        }
    }
}

// round 16
// speedup vs baseline: 2.5788x; 1.1492x over previous
#include <cuda_runtime.h>
#include <cuda_bf16.h>
#include <math.h>
#include <stdint.h>

#define N_NODES 10000
#define N_EDGES 160000
#define HDIM    128
#define NLAYERS 3
#define BN_EPS  1e-5f

#define EDGE_CTA   256
#define EDGE_TILES (N_EDGES / EDGE_CTA)   // 625
#define NODE_TILES ((N_NODES + 63) / 64)  // 157
#define NMAT 7

#define TROW 272
#define A_TILE_BYTES (256 * TROW)
#define B_TILE_BYTES (128 * TROW)
#define A64_TILE     (64 * TROW)

// ---------------- device scratch ----------------
__device__ float g_coords[N_NODES * 3];
__device__ float g_V[N_NODES * HDIM];
__device__ float g_Vraw[N_NODES * HDIM];
__device__ float g_VH[N_NODES * HDIM];
__device__ float g_mi[N_NODES * HDIM];
__device__ float g_accum[N_NODES * 3];
__device__ float g_mij[N_EDGES * HDIM];
__device__ float g_partE[2 * EDGE_TILES * HDIM];
__device__ float g_partN[2 * 160 * HDIM];
__device__ float g_muinv[2 * HDIM];
__device__ __nv_bfloat16 g_wbhi[NLAYERS * NMAT * 16384];
__device__ __nv_bfloat16 g_wblo[NLAYERS * NMAT * 16384];

__device__ __forceinline__ float silu_f(float x) {
    return x * __fdividef(1.0f, 1.0f + __expf(-x));
}
__device__ __forceinline__ float elu_f(float x) {
    return x > 0.0f ? x : (__expf(x) - 1.0f);
}

__device__ __forceinline__ void red_add_v2(float* addr, float x, float y) {
    asm volatile("red.global.add.v2.f32 [%0], {%1,%2};"
                 :: "l"(addr), "f"(x), "f"(y) : "memory");
}
__device__ __forceinline__ uint32_t pk_bf2(float x, float y) {
    __nv_bfloat162 t = __floats2bfloat162_rn(x, y);
    return *(uint32_t*)&t;
}
__device__ __forceinline__ float bf_hi(float x) {
    return __bfloat162float(__float2bfloat16(x));
}

__device__ __forceinline__ void mma16816(float* d, uint32_t a0, uint32_t a1,
                                         uint32_t a2, uint32_t a3,
                                         uint32_t b0, uint32_t b1) {
    asm("mma.sync.aligned.m16n8k16.row.col.f32.bf16.bf16.f32 "
        "{%0,%1,%2,%3}, {%4,%5,%6,%7}, {%8,%9}, {%0,%1,%2,%3};"
        : "+f"(d[0]), "+f"(d[1]), "+f"(d[2]), "+f"(d[3])
        : "r"(a0), "r"(a1), "r"(a2), "r"(a3), "r"(b0), "r"(b1));
}
__device__ __forceinline__ void ldsm4(uint32_t* r, uint32_t addr) {
    asm volatile("ldmatrix.sync.aligned.m8n8.x4.shared.b16 {%0,%1,%2,%3}, [%4];"
        : "=r"(r[0]), "=r"(r[1]), "=r"(r[2]), "=r"(r[3]) : "r"(addr));
}
__device__ __forceinline__ void cp16(uint32_t dst, const void* src) {
    asm volatile("cp.async.cg.shared.global [%0], [%1], 16;"
                 :: "r"(dst), "l"(src) : "memory");
}
#define CP_COMMIT() asm volatile("cp.async.commit_group;" ::: "memory")
#define CP_WAIT0()  asm volatile("cp.async.wait_group 0;" ::: "memory")

// warp GEMM 16 rows x 128 cols, K=128, bf16 split-3
__device__ __forceinline__ void warp_gemm3(float (&acc)[16][4],
                                           uint32_t AhS, uint32_t AlS,
                                           uint32_t BhS, uint32_t BlS,
                                           int aoff, int boff)
{
#pragma unroll
    for (int i = 0; i < 16; i++)
#pragma unroll
        for (int j = 0; j < 4; j++) acc[i][j] = 0.f;

#pragma unroll 2
    for (int ks = 0; ks < 8; ks++) {
        uint32_t ah[4], al[4];
        ldsm4(ah, AhS + aoff + ks * 32);
        ldsm4(al, AlS + aoff + ks * 32);
        const uint32_t bhb = BhS + boff + ks * 32;
        const uint32_t blb = BlS + boff + ks * 32;
#pragma unroll
        for (int ntp = 0; ntp < 8; ntp++) {
            uint32_t bh[4], bl[4];
            ldsm4(bh, bhb + ntp * 16 * TROW);
            ldsm4(bl, blb + ntp * 16 * TROW);
            mma16816(acc[2 * ntp],     ah[0], ah[1], ah[2], ah[3], bh[0], bh[1]);
            mma16816(acc[2 * ntp + 1], ah[0], ah[1], ah[2], ah[3], bh[2], bh[3]);
            mma16816(acc[2 * ntp],     al[0], al[1], al[2], al[3], bh[0], bh[1]);
            mma16816(acc[2 * ntp + 1], al[0], al[1], al[2], al[3], bh[2], bh[3]);
            mma16816(acc[2 * ntp],     ah[0], ah[1], ah[2], ah[3], bl[0], bl[1]);
            mma16816(acc[2 * ntp + 1], ah[0], ah[1], ah[2], ah[3], bl[2], bl[3]);
        }
    }
}

// warp GEMM 16 rows x 64 cols, K=128, bf16 split-3, optional accumulate
__device__ __forceinline__ void wg3h(float (&acc)[8][4],
                                     uint32_t AhS, uint32_t AlS,
                                     uint32_t BhS, uint32_t BlS,
                                     int aoff, int boff, bool first)
{
    if (first) {
#pragma unroll
        for (int i = 0; i < 8; i++)
#pragma unroll
            for (int j = 0; j < 4; j++) acc[i][j] = 0.f;
    }
#pragma unroll 2
    for (int ks = 0; ks < 8; ks++) {
        uint32_t ah[4], al[4];
        ldsm4(ah, AhS + aoff + ks * 32);
        ldsm4(al, AlS + aoff + ks * 32);
        const uint32_t bhb = BhS + boff + ks * 32;
        const uint32_t blb = BlS + boff + ks * 32;
#pragma unroll
        for (int ntp = 0; ntp < 4; ntp++) {
            uint32_t bh[4], bl[4];
            ldsm4(bh, bhb + ntp * 16 * TROW);
            ldsm4(bl, blb + ntp * 16 * TROW);
            mma16816(acc[2 * ntp],     ah[0], ah[1], ah[2], ah[3], bh[0], bh[1]);
            mma16816(acc[2 * ntp + 1], ah[0], ah[1], ah[2], ah[3], bh[2], bh[3]);
            mma16816(acc[2 * ntp],     al[0], al[1], al[2], al[3], bh[0], bh[1]);
            mma16816(acc[2 * ntp + 1], al[0], al[1], al[2], al[3], bh[2], bh[3]);
            mma16816(acc[2 * ntp],     ah[0], ah[1], ah[2], ah[3], bl[0], bl[1]);
            mma16816(acc[2 * ntp + 1], ah[0], ah[1], ah[2], ah[3], bl[2], bl[3]);
        }
    }
}

// ---------------- weight pre-convert (7 mats/layer) ----------------
__global__ void convw_k(const float* __restrict__ We2, const float* __restrict__ Wx1,
                        const float* __restrict__ We1, const float* __restrict__ Wh1,
                        const float* __restrict__ Wh2)
{
    int idx = blockIdx.x * 256 + threadIdx.x;
    if (idx >= NLAYERS * NMAT * 16384) return;
    int l = idx / (NMAT * 16384);
    int rest = idx % (NMAT * 16384);
    int m = rest / 16384;
    int e = rest & 16383;
    int n = e >> 7, k = e & 127;
    float x;
    switch (m) {
        case 0: x = We2[(size_t)l * 16384 + k * 128 + n]; break;
        case 1: x = Wx1[(size_t)l * 16384 + k * 128 + n]; break;
        case 2: x = We1[(size_t)l * 259 * 128 + k * 128 + n]; break;
        case 3: x = We1[(size_t)l * 259 * 128 + (128 + k) * 128 + n]; break;
        case 4: x = Wh1[(size_t)l * 256 * 128 + k * 128 + n]; break;
        case 5: x = Wh1[(size_t)l * 256 * 128 + (128 + k) * 128 + n]; break;
        default: x = Wh2[(size_t)l * 16384 + k * 128 + n]; break;
    }
    __nv_bfloat16 h = __float2bfloat16(x);
    __nv_bfloat16 lo = __float2bfloat16(x - __bfloat162float(h));
    g_wbhi[(size_t)(l * NMAT + m) * 16384 + n * 128 + k] = h;
    g_wblo[(size_t)(l * NMAT + m) * 16384 + n * 128 + k] = lo;
}

// ---------------- fused edge pipeline ----------------
__global__ __launch_bounds__(512)
void edge_mma_k(const int* __restrict__ srcv, const int* __restrict__ dstv,
                const float* __restrict__ ee,
                const float* __restrict__ Ps, const float* __restrict__ Pd,
                const float* __restrict__ wex_g, const float* __restrict__ be1,
                const float* __restrict__ be2, const float* __restrict__ bx1,
                const float* __restrict__ Wx2, const float* __restrict__ bx2,
                const __nv_bfloat16* __restrict__ WBhi,
                const __nv_bfloat16* __restrict__ WBlo,
                int write_mij)
{
    extern __shared__ char smc[];
    float* smf = (float*)smc;
    float* diffs = smf + 0;
    float* dists = smf + 768;
    int*   dsts  = (int*)(smf + 1024);
    float* ee0s  = smf + 1280;
    float* ee1s  = smf + 1536;
    float* wex   = smf + 1792;
    float* be1s  = smf + 2176;
    float* be2s  = smf + 2304;
    float* bx1s  = smf + 2432;
    float* wx2s  = smf + 2560;
    float* bx2s  = smf + 2944;
    float* es    = smf + 2948;
    char* Ah = smc + 12816;
    char* Al = Ah + A_TILE_BYTES;
    char* Bh = Al + A_TILE_BYTES;
    char* Bl = Bh + B_TILE_BYTES;

    const int tid  = threadIdx.x;
    const int wid  = tid >> 5;
    const int lane = tid & 31;
    const int g    = lane >> 2;
    const int q    = lane & 3;
    const int m0   = blockIdx.x * EDGE_CTA;

    const uint32_t AhS = (uint32_t)__cvta_generic_to_shared(Ah);
    const uint32_t AlS = (uint32_t)__cvta_generic_to_shared(Al);
    const uint32_t BhS = (uint32_t)__cvta_generic_to_shared(Bh);
    const uint32_t BlS = (uint32_t)__cvta_generic_to_shared(Bl);

    // cp.async B1 tiles (overlaps with meta + T1 build)
    {
        const char* shi = (const char*)WBhi;
        const char* slo = (const char*)WBlo;
#pragma unroll
        for (int i = 0; i < 4; i++) {
            int p = tid + i * 512;
            int row = p >> 4, chunk = p & 15;
            uint32_t off = row * TROW + chunk * 16;
            cp16(BhS + off, shi + p * 16);
            cp16(BlS + off, slo + p * 16);
        }
        CP_COMMIT();
    }

    if (tid < 256) {
        int mm = m0 + tid;
        int s = srcv[mm], d = dstv[mm];
        float dx = g_coords[d * 3 + 0] - g_coords[s * 3 + 0];
        float dy = g_coords[d * 3 + 1] - g_coords[s * 3 + 1];
        float dz = g_coords[d * 3 + 2] - g_coords[s * 3 + 2];
        diffs[tid * 3 + 0] = dx;
        diffs[tid * 3 + 1] = dy;
        diffs[tid * 3 + 2] = dz;
        dists[tid] = sqrtf(dx * dx + dy * dy + dz * dz);
        dsts[tid] = d;
        ee0s[tid] = ee[mm * 2 + 0];
        ee1s[tid] = ee[mm * 2 + 1];
        es[tid] = 0.f;
    }
    if (tid < 128) { be1s[tid] = be1[tid]; be2s[tid] = be2[tid]; bx1s[tid] = bx1[tid]; }
    for (int i = tid; i < 384; i += 512) { wex[i] = wex_g[i]; wx2s[i] = Wx2[i]; }
    if (tid < 3) bx2s[tid] = bx2[tid];
    __syncthreads();

    // T1 build
    {
        const int r  = tid >> 1;
        const int cb = (tid & 1) * 64;
        const int mm = m0 + r;
        const int s  = srcv[mm];
        const float* psp = Ps + (size_t)s * 128;
        const float* pdp = Pd + (size_t)dsts[r] * 128;
        const float di = dists[r];
        const float e0 = ee0s[r], e1 = ee1s[r];
        for (int c = cb; c < cb + 64; c += 8) {
            float o[8];
#pragma unroll
            for (int h = 0; h < 8; h += 4) {
                float4 a = *(const float4*)(psp + c + h);
                float4 b = *(const float4*)(pdp + c + h);
                o[h+0] = silu_f(a.x + b.x + di * wex[c+h+0] + e0 * wex[128+c+h+0] + e1 * wex[256+c+h+0] + be1s[c+h+0]);
                o[h+1] = silu_f(a.y + b.y + di * wex[c+h+1] + e0 * wex[128+c+h+1] + e1 * wex[256+c+h+1] + be1s[c+h+1]);
                o[h+2] = silu_f(a.z + b.z + di * wex[c+h+2] + e0 * wex[128+c+h+2] + e1 * wex[256+c+h+2] + be1s[c+h+2]);
                o[h+3] = silu_f(a.w + b.w + di * wex[c+h+3] + e0 * wex[128+c+h+3] + e1 * wex[256+c+h+3] + be1s[c+h+3]);
            }
            uint32_t H[4], L[4];
#pragma unroll
            for (int j = 0; j < 4; j++) {
                float hx = bf_hi(o[2*j]), hy = bf_hi(o[2*j+1]);
                H[j] = pk_bf2(o[2*j], o[2*j+1]);
                L[j] = pk_bf2(o[2*j] - hx, o[2*j+1] - hy);
            }
            *(uint4*)(Ah + r * TROW + c * 2) = *(uint4*)H;
            *(uint4*)(Al + r * TROW + c * 2) = *(uint4*)L;
        }
    }
    CP_WAIT0();
    __syncthreads();

    const int arow = wid * 16 + (lane & 7) + ((lane & 8) ? 8 : 0);
    const int aoff = arow * TROW + ((lane >> 4) & 1) * 16;
    const int brow = (lane & 7) + (((lane >> 4) & 1) << 3);
    const int boff = brow * TROW + ((lane & 8) ? 16 : 0);

    const int r0 = wid * 16 + g, r1 = r0 + 8;

    float acc[16][4];

    warp_gemm3(acc, AhS, AlS, BhS, BlS, aoff, boff);

    {
        const int d0 = dsts[r0], d1 = dsts[r1];
#pragma unroll
        for (int nt = 0; nt < 16; nt++) {
            const int c = nt * 8 + q * 2;
            float v00 = silu_f(acc[nt][0] + be2s[c]);
            float v01 = silu_f(acc[nt][1] + be2s[c + 1]);
            float v10 = silu_f(acc[nt][2] + be2s[c]);
            float v11 = silu_f(acc[nt][3] + be2s[c + 1]);
            red_add_v2(&g_mi[(size_t)d0 * 128 + c], v00, v01);
            red_add_v2(&g_mi[(size_t)d1 * 128 + c], v10, v11);
            if (write_mij) {
                *(float2*)(g_mij + (size_t)(m0 + r0) * 128 + c) = make_float2(v00, v01);
                *(float2*)(g_mij + (size_t)(m0 + r1) * 128 + c) = make_float2(v10, v11);
                float e00 = elu_f(v00), e01 = elu_f(v01);
                float e10 = elu_f(v10), e11 = elu_f(v11);
                float s0 = e00 + e10, s1 = e01 + e11;
                float q0 = e00 * e00 + e10 * e10, q1 = e01 * e01 + e11 * e11;
#pragma unroll
                for (int o = 4; o < 32; o <<= 1) {
                    s0 += __shfl_xor_sync(0xFFFFFFFF, s0, o);
                    s1 += __shfl_xor_sync(0xFFFFFFFF, s1, o);
                    q0 += __shfl_xor_sync(0xFFFFFFFF, q0, o);
                    q1 += __shfl_xor_sync(0xFFFFFFFF, q1, o);
                }
                if (lane < 4) {
                    atomicAdd(&es[c], s0);
                    atomicAdd(&es[c + 1], s1);
                    atomicAdd(&es[128 + c], q0);
                    atomicAdd(&es[128 + c + 1], q1);
                }
            }
            float h00 = bf_hi(v00), h01 = bf_hi(v01);
            float h10 = bf_hi(v10), h11 = bf_hi(v11);
            *(uint32_t*)(Ah + r0 * TROW + c * 2) = pk_bf2(v00, v01);
            *(uint32_t*)(Ah + r1 * TROW + c * 2) = pk_bf2(v10, v11);
            *(uint32_t*)(Al + r0 * TROW + c * 2) = pk_bf2(v00 - h00, v01 - h01);
            *(uint32_t*)(Al + r1 * TROW + c * 2) = pk_bf2(v10 - h10, v11 - h11);
        }
    }
    __syncthreads();
    // cp.async B2 tiles (overlaps with partE store)
    {
        const char* shi = (const char*)(WBhi + 16384);
        const char* slo = (const char*)(WBlo + 16384);
#pragma unroll
        for (int i = 0; i < 4; i++) {
            int p = tid + i * 512;
            int row = p >> 4, chunk = p & 15;
            uint32_t off = row * TROW + chunk * 16;
            cp16(BhS + off, shi + p * 16);
            cp16(BlS + off, slo + p * 16);
        }
        CP_COMMIT();
    }
    if (write_mij && tid < 128) {
        g_partE[blockIdx.x * 128 + tid] = es[tid];
        g_partE[(EDGE_TILES + blockIdx.x) * 128 + tid] = es[128 + tid];
    }
    CP_WAIT0();
    __syncthreads();

    warp_gemm3(acc, AhS, AlS, BhS, BlS, aoff, boff);

    {
        float pa0 = 0.f, pa1 = 0.f, pa2 = 0.f;
        float pb0 = 0.f, pb1 = 0.f, pb2 = 0.f;
#pragma unroll
        for (int nt = 0; nt < 16; nt++) {
            const int c = nt * 8 + q * 2;
            float t00 = silu_f(acc[nt][0] + bx1s[c]);
            float t01 = silu_f(acc[nt][1] + bx1s[c + 1]);
            float t10 = silu_f(acc[nt][2] + bx1s[c]);
            float t11 = silu_f(acc[nt][3] + bx1s[c + 1]);
            float w00 = wx2s[c * 3 + 0], w01 = wx2s[c * 3 + 1], w02 = wx2s[c * 3 + 2];
            float w10 = wx2s[c * 3 + 3], w11 = wx2s[c * 3 + 4], w12 = wx2s[c * 3 + 5];
            pa0 += t00 * w00 + t01 * w10;
            pa1 += t00 * w01 + t01 * w11;
            pa2 += t00 * w02 + t01 * w12;
            pb0 += t10 * w00 + t11 * w10;
            pb1 += t10 * w01 + t11 * w11;
            pb2 += t10 * w02 + t11 * w12;
        }
#pragma unroll
        for (int o = 1; o < 4; o <<= 1) {
            pa0 += __shfl_xor_sync(0xFFFFFFFF, pa0, o);
            pa1 += __shfl_xor_sync(0xFFFFFFFF, pa1, o);
            pa2 += __shfl_xor_sync(0xFFFFFFFF, pa2, o);
            pb0 += __shfl_xor_sync(0xFFFFFFFF, pb0, o);
            pb1 += __shfl_xor_sync(0xFFFFFFFF, pb1, o);
            pb2 += __shfl_xor_sync(0xFFFFFFFF, pb2, o);
        }
        if (q == 0) {
            const int d0 = dsts[r0], d1 = dsts[r1];
            float x0 = pa0 + bx2s[0], x1 = pa1 + bx2s[1], x2 = pa2 + bx2s[2];
            atomicAdd(&g_accum[d0 * 3 + 0], diffs[r0 * 3 + 0] * x0);
            atomicAdd(&g_accum[d0 * 3 + 1], diffs[r0 * 3 + 1] * x1);
            atomicAdd(&g_accum[d0 * 3 + 2], diffs[r0 * 3 + 2] * x2);
            float y0 = pb0 + bx2s[0], y1 = pb1 + bx2s[1], y2 = pb2 + bx2s[2];
            atomicAdd(&g_accum[d1 * 3 + 0], diffs[r1 * 3 + 0] * y0);
            atomicAdd(&g_accum[d1 * 3 + 1], diffs[r1 * 3 + 1] * y1);
            atomicAdd(&g_accum[d1 * 3 + 2], diffs[r1 * 3 + 2] * y2);
        }
    }
}

// ---------------- proj_tc_k ----------------
__global__ __launch_bounds__(256)
void proj_tc_k(const float* __restrict__ V,
               const __nv_bfloat16* __restrict__ WBhi,
               const __nv_bfloat16* __restrict__ WBlo,
               float* __restrict__ Ps, float* __restrict__ Pd, int M)
{
    extern __shared__ char smc[];
    char* Ah = smc;
    char* Al = smc + A64_TILE;
    char* Bh = smc + 2 * A64_TILE;
    char* Bl = Bh + 2 * B_TILE_BYTES;

    const int tid  = threadIdx.x;
    const int wid  = tid >> 5;
    const int lane = tid & 31;
    const int g    = lane >> 2;
    const int q    = lane & 3;
    const int rg   = wid >> 1;
    const int out  = wid & 1;
    const int mb   = blockIdx.x * 64;

    const uint32_t AhS = (uint32_t)__cvta_generic_to_shared(Ah);
    const uint32_t AlS = (uint32_t)__cvta_generic_to_shared(Al);
    const uint32_t BhS = (uint32_t)__cvta_generic_to_shared(Bh);
    const uint32_t BlS = (uint32_t)__cvta_generic_to_shared(Bl);

    // cp.async B (256 rows hi+lo)
    {
        const char* shi = (const char*)WBhi;
        const char* slo = (const char*)WBlo;
#pragma unroll
        for (int i = 0; i < 16; i++) {
            int p = tid + i * 256;
            int row = p >> 4, chunk = p & 15;
            uint32_t off = row * TROW + chunk * 16;
            cp16(BhS + off, shi + p * 16);
            cp16(BlS + off, slo + p * 16);
        }
        CP_COMMIT();
    }

    {
        int r = tid >> 2, c = (tid & 3) * 32;
        if (mb + r < M) {
            float4 z = make_float4(0.f, 0.f, 0.f, 0.f);
            float* p = g_mi + (size_t)(mb + r) * 128 + c;
#pragma unroll
            for (int j = 0; j < 8; j++) *(float4*)(p + j * 4) = z;
        }
        if (tid < 192 && mb + tid / 3 < M)
            g_accum[(size_t)mb * 3 + tid] = 0.f;
    }

    {
        const int r  = tid >> 2;
        const int cb = (tid & 3) * 32;
        const int gm = mb + r;
        for (int c = cb; c < cb + 32; c += 8) {
            float o[8];
            if (gm < M) {
                *(float4*)o       = *(const float4*)(V + (size_t)gm * 128 + c);
                *(float4*)(o + 4) = *(const float4*)(V + (size_t)gm * 128 + c + 4);
            } else {
#pragma unroll
                for (int j = 0; j < 8; j++) o[j] = 0.f;
            }
            uint32_t H[4], L[4];
#pragma unroll
            for (int j = 0; j < 4; j++) {
                float hx = bf_hi(o[2*j]), hy = bf_hi(o[2*j+1]);
                H[j] = pk_bf2(o[2*j], o[2*j+1]);
                L[j] = pk_bf2(o[2*j] - hx, o[2*j+1] - hy);
            }
            *(uint4*)(Ah + r * TROW + c * 2) = *(uint4*)H;
            *(uint4*)(Al + r * TROW + c * 2) = *(uint4*)L;
        }
    }
    CP_WAIT0();
    __syncthreads();

    const int arow = rg * 16 + (lane & 7) + ((lane & 8) ? 8 : 0);
    const int aoff = arow * TROW + ((lane >> 4) & 1) * 16;
    const int brow = (lane & 7) + (((lane >> 4) & 1) << 3);
    const int boff = (out * 128 + brow) * TROW + ((lane & 8) ? 16 : 0);

    float acc[16][4];
    warp_gemm3(acc, AhS, AlS, BhS, BlS, aoff, boff);

    float* O = out ? Pd : Ps;
    const int gr0 = mb + rg * 16 + g, gr1 = gr0 + 8;
#pragma unroll
    for (int nt = 0; nt < 16; nt++) {
        const int c = nt * 8 + q * 2;
        if (gr0 < M) *(float2*)(O + (size_t)gr0 * 128 + c) = make_float2(acc[nt][0], acc[nt][1]);
        if (gr1 < M) *(float2*)(O + (size_t)gr1 * 128 + c) = make_float2(acc[nt][2], acc[nt][3]);
    }
}

// ---------------- node_fused_tc_k (+ fused coords update) ----------------
__global__ __launch_bounds__(256)
void node_fused_tc_k(const float* __restrict__ V, const float* __restrict__ mi,
                     const __nv_bfloat16* __restrict__ WBhi,
                     const __nv_bfloat16* __restrict__ WBlo,
                     const float* __restrict__ bh1, const float* __restrict__ bh2,
                     float* __restrict__ Vraw, float* __restrict__ part,
                     int M, int nblk)
{
    extern __shared__ char smc[];
    char* A0h = smc;
    char* A0l = smc + A64_TILE;
    char* A1h = smc + 2 * A64_TILE;
    char* A1l = smc + 3 * A64_TILE;
    char* Bh  = smc + 4 * A64_TILE;
    char* Bl  = Bh + B_TILE_BYTES;
    float* bh1s = (float*)(smc + 139264);
    float* bh2s = (float*)(smc + 139776);
    float* es   = (float*)(smc + 140288);

    const int tid  = threadIdx.x;
    const int wid  = tid >> 5;
    const int lane = tid & 31;
    const int g    = lane >> 2;
    const int q    = lane & 3;
    const int rg   = wid >> 1;
    const int nh   = wid & 1;
    const int mb   = blockIdx.x * 64;

    const uint32_t A0hS = (uint32_t)__cvta_generic_to_shared(A0h);
    const uint32_t A0lS = (uint32_t)__cvta_generic_to_shared(A0l);
    const uint32_t A1hS = (uint32_t)__cvta_generic_to_shared(A1h);
    const uint32_t A1lS = (uint32_t)__cvta_generic_to_shared(A1l);
    const uint32_t BhS  = (uint32_t)__cvta_generic_to_shared(Bh);
    const uint32_t BlS  = (uint32_t)__cvta_generic_to_shared(Bl);

    // cp.async Wh1t chunk0
    {
        const char* shi = (const char*)(WBhi + 4 * 16384);
        const char* slo = (const char*)(WBlo + 4 * 16384);
#pragma unroll
        for (int i = 0; i < 8; i++) {
            int p = tid + i * 256;
            int row = p >> 4, chunk = p & 15;
            uint32_t off = row * TROW + chunk * 16;
            cp16(BhS + off, shi + p * 16);
            cp16(BlS + off, slo + p * 16);
        }
        CP_COMMIT();
    }

    if (tid < 128) { bh1s[tid] = bh1[tid]; bh2s[tid] = bh2[tid]; }
    es[tid] = 0.f;

    // fused coords update (post-edge): coords += accum / (N-1)
    {
        int idx = blockIdx.x * 192 + tid;
        if (tid < 192 && idx < N_NODES * 3)
            g_coords[idx] += g_accum[idx] * (1.0f / (float)(N_NODES - 1));
    }

    // A0 <- V, A1 <- mi
    {
        const int r  = tid >> 2;
        const int cb = (tid & 3) * 32;
        const int gm = mb + r;
        for (int c = cb; c < cb + 32; c += 8) {
            float o0[8], o1[8];
            if (gm < M) {
                *(float4*)o0       = *(const float4*)(V + (size_t)gm * 128 + c);
                *(float4*)(o0 + 4) = *(const float4*)(V + (size_t)gm * 128 + c + 4);
                *(float4*)o1       = *(const float4*)(mi + (size_t)gm * 128 + c);
                *(float4*)(o1 + 4) = *(const float4*)(mi + (size_t)gm * 128 + c + 4);
            } else {
#pragma unroll
                for (int j = 0; j < 8; j++) { o0[j] = 0.f; o1[j] = 0.f; }
            }
            uint32_t H[4], L[4];
#pragma unroll
            for (int j = 0; j < 4; j++) {
                float hx = bf_hi(o0[2*j]), hy = bf_hi(o0[2*j+1]);
                H[j] = pk_bf2(o0[2*j], o0[2*j+1]);
                L[j] = pk_bf2(o0[2*j] - hx, o0[2*j+1] - hy);
            }
            *(uint4*)(A0h + r * TROW + c * 2) = *(uint4*)H;
            *(uint4*)(A0l + r * TROW + c * 2) = *(uint4*)L;
#pragma unroll
            for (int j = 0; j < 4; j++) {
                float hx = bf_hi(o1[2*j]), hy = bf_hi(o1[2*j+1]);
                H[j] = pk_bf2(o1[2*j], o1[2*j+1]);
                L[j] = pk_bf2(o1[2*j] - hx, o1[2*j+1] - hy);
            }
            *(uint4*)(A1h + r * TROW + c * 2) = *(uint4*)H;
            *(uint4*)(A1l + r * TROW + c * 2) = *(uint4*)L;
        }
    }
    CP_WAIT0();
    __syncthreads();

    const int arow = rg * 16 + (lane & 7) + ((lane & 8) ? 8 : 0);
    const int aoff = arow * TROW + ((lane >> 4) & 1) * 16;
    const int brow = (lane & 7) + (((lane >> 4) & 1) << 3);
    const int boff = (nh * 64 + brow) * TROW + ((lane & 8) ? 16 : 0);

    const int r0 = rg * 16 + g, r1 = r0 + 8;

    float acc[8][4];

    wg3h(acc, A0hS, A0lS, BhS, BlS, aoff, boff, true);
    __syncthreads();
    {
        const char* shi = (const char*)(WBhi + 5 * 16384);
        const char* slo = (const char*)(WBlo + 5 * 16384);
#pragma unroll
        for (int i = 0; i < 8; i++) {
            int p = tid + i * 256;
            int row = p >> 4, chunk = p & 15;
            uint32_t off = row * TROW + chunk * 16;
            cp16(BhS + off, shi + p * 16);
            cp16(BlS + off, slo + p * 16);
        }
        CP_COMMIT();
        CP_WAIT0();
    }
    __syncthreads();
    wg3h(acc, A1hS, A1lS, BhS, BlS, aoff, boff, false);

#pragma unroll
    for (int nt = 0; nt < 8; nt++) {
        const int c = nh * 64 + nt * 8 + q * 2;
        float v00 = silu_f(acc[nt][0] + bh1s[c]);
        float v01 = silu_f(acc[nt][1] + bh1s[c + 1]);
        float v10 = silu_f(acc[nt][2] + bh1s[c]);
        float v11 = silu_f(acc[nt][3] + bh1s[c + 1]);
        float h00 = bf_hi(v00), h01 = bf_hi(v01);
        float h10 = bf_hi(v10), h11 = bf_hi(v11);
        *(uint32_t*)(A0h + r0 * TROW + c * 2) = pk_bf2(v00, v01);
        *(uint32_t*)(A0h + r1 * TROW + c * 2) = pk_bf2(v10, v11);
        *(uint32_t*)(A0l + r0 * TROW + c * 2) = pk_bf2(v00 - h00, v01 - h01);
        *(uint32_t*)(A0l + r1 * TROW + c * 2) = pk_bf2(v10 - h10, v11 - h11);
    }
    __syncthreads();
    {
        const char* shi = (const char*)(WBhi + 6 * 16384);
        const char* slo = (const char*)(WBlo + 6 * 16384);
#pragma unroll
        for (int i = 0; i < 8; i++) {
            int p = tid + i * 256;
            int row = p >> 4, chunk = p & 15;
            uint32_t off = row * TROW + chunk * 16;
            cp16(BhS + off, shi + p * 16);
            cp16(BlS + off, slo + p * 16);
        }
        CP_COMMIT();
        CP_WAIT0();
    }
    __syncthreads();

    wg3h(acc, A0hS, A0lS, BhS, BlS, aoff, boff, true);

    {
        const int gr0 = mb + r0, gr1 = mb + r1;
        const bool ok0 = (gr0 < M), ok1 = (gr1 < M);
#pragma unroll
        for (int nt = 0; nt < 8; nt++) {
            const int c = nh * 64 + nt * 8 + q * 2;
            float v00 = acc[nt][0] + bh2s[c];
            float v01 = acc[nt][1] + bh2s[c + 1];
            float v10 = acc[nt][2] + bh2s[c];
            float v11 = acc[nt][3] + bh2s[c + 1];
            float s0 = 0.f, s1 = 0.f, q0 = 0.f, q1 = 0.f;
            if (ok0) {
                *(float2*)(Vraw + (size_t)gr0 * 128 + c) = make_float2(v00, v01);
                float e0 = elu_f(v00), e1 = elu_f(v01);
                s0 += e0; s1 += e1; q0 += e0 * e0; q1 += e1 * e1;
            }
            if (ok1) {
                *(float2*)(Vraw + (size_t)gr1 * 128 + c) = make_float2(v10, v11);
                float e0 = elu_f(v10), e1 = elu_f(v11);
                s0 += e0; s1 += e1; q0 += e0 * e0; q1 += e1 * e1;
            }
#pragma unroll
            for (int o = 4; o < 32; o <<= 1) {
                s0 += __shfl_xor_sync(0xFFFFFFFF, s0, o);
                s1 += __shfl_xor_sync(0xFFFFFFFF, s1, o);
                q0 += __shfl_xor_sync(0xFFFFFFFF, q0, o);
                q1 += __shfl_xor_sync(0xFFFFFFFF, q1, o);
            }
            if (lane < 4) {
                atomicAdd(&es[c], s0);
                atomicAdd(&es[c + 1], s1);
                atomicAdd(&es[128 + c], q0);
                atomicAdd(&es[128 + c + 1], q1);
            }
        }
    }
    __syncthreads();
    if (tid < 128) {
        part[blockIdx.x * 128 + tid] = es[tid];
        part[(nblk + blockIdx.x) * 128 + tid] = es[128 + tid];
    }
}

// ---------------- small kernels ----------------
__global__ void init_nodes_k(const float* __restrict__ emb,
                             const float* __restrict__ Wn,
                             const float* __restrict__ bn)
{
    int idx = blockIdx.x * blockDim.x + threadIdx.x;
    if (idx < N_NODES * 3) g_coords[idx] = emb[idx];
    if (idx < N_NODES * HDIM) {
        int n = idx >> 7, j = idx & 127;
        g_V[idx] = emb[n * 3 + 0] * Wn[0 * 128 + j]
                 + emb[n * 3 + 1] * Wn[1 * 128 + j]
                 + emb[n * 3 + 2] * Wn[2 * 128 + j]
                 + bn[j];
    }
}

__global__ void bn_stats2_k(const float* __restrict__ part, int B, int M)
{
    int j = threadIdx.x;
    double s = 0.0, q = 0.0;
    for (int b = 0; b < B; b++) {
        s += (double)part[b * 128 + j];
        q += (double)part[(B + b) * 128 + j];
    }
    double mu  = s / (double)M;
    double var = q / (double)M - mu * mu;
    g_muinv[j]       = (float)mu;
    g_muinv[128 + j] = (float)rsqrt(var + (double)BN_EPS);
}

__global__ void bn_norm_k(const float* __restrict__ X,
                          const float* __restrict__ gam,
                          const float* __restrict__ bet,
                          float* __restrict__ out, int M)
{
    int idx = blockIdx.x * blockDim.x + threadIdx.x;
    if (idx >= M * 128) return;
    int j = idx & 127;
    float x = elu_f(X[idx]);
    out[idx] = gam[j] * (x - g_muinv[j]) * g_muinv[128 + j] + bet[j];
}

// ---------------- host launcher ----------------
static void* sym_addr(const void* sym)
{
    void* p = nullptr;
    cudaGetSymbolAddress(&p, sym);
    return p;
}

extern "C" void kernel_launch(void* const* d_in, const int* in_sizes, int n_in,
                              void* d_out, int out_size)
{
    (void)in_sizes; (void)n_in; (void)out_size;

    const float* emb_nodes = (const float*)d_in[0];
    const float* emb_edges = (const float*)d_in[1];
    const int*   edge_idx  = (const int*)d_in[2];
    const float* pre_Wn    = (const float*)d_in[3];
    const float* pre_bn    = (const float*)d_in[4];
    const float* We1 = (const float*)d_in[7];
    const float* be1 = (const float*)d_in[8];
    const float* We2 = (const float*)d_in[9];
    const float* be2 = (const float*)d_in[10];
    const float* Wx1 = (const float*)d_in[11];
    const float* bx1 = (const float*)d_in[12];
    const float* Wx2 = (const float*)d_in[13];
    const float* bx2 = (const float*)d_in[14];
    const float* Wh1 = (const float*)d_in[15];
    const float* bh1 = (const float*)d_in[16];
    const float* Wh2 = (const float*)d_in[17];
    const float* bh2 = (const float*)d_in[18];
    const float* gam_n = (const float*)d_in[19];
    const float* bet_n = (const float*)d_in[20];
    const float* gam_e = (const float*)d_in[21];
    const float* bet_e = (const float*)d_in[22];

    float* out  = (float*)d_out;
    float* outV = out;
    float* outE = out + (size_t)N_NODES * HDIM;

    const int* srcv = edge_idx;
    const int* dstv = edge_idx + N_EDGES;

    float* pV     = (float*)sym_addr(g_V);
    float* pVraw  = (float*)sym_addr(g_Vraw);
    float* pVH    = (float*)sym_addr(g_VH);
    float* pMi    = (float*)sym_addr(g_mi);
    float* pMij   = (float*)sym_addr(g_mij);
    float* pPartE = (float*)sym_addr(g_partE);
    float* pPartN = (float*)sym_addr(g_partN);
    __nv_bfloat16* pWbhi = (__nv_bfloat16*)sym_addr(g_wbhi);
    __nv_bfloat16* pWblo = (__nv_bfloat16*)sym_addr(g_wblo);

    const int EDGE_SMEM = 12816 + 2 * A_TILE_BYTES + 2 * B_TILE_BYTES;
    const int PROJ_SMEM = 2 * A64_TILE + 4 * B_TILE_BYTES;
    const int NODE_SMEM = 141312;
    cudaFuncSetAttribute(edge_mma_k,
                         cudaFuncAttributeMaxDynamicSharedMemorySize, EDGE_SMEM);
    cudaFuncSetAttribute(proj_tc_k,
                         cudaFuncAttributeMaxDynamicSharedMemorySize, PROJ_SMEM);
    cudaFuncSetAttribute(node_fused_tc_k,
                         cudaFuncAttributeMaxDynamicSharedMemorySize, NODE_SMEM);

    const int TB = 256;
    const int nodeHBlocks = (N_NODES * HDIM + TB - 1) / TB;
    const int edgeHBlocks = (N_EDGES * HDIM + TB - 1) / TB;

    init_nodes_k<<<nodeHBlocks, TB>>>(emb_nodes, pre_Wn, pre_bn);
    convw_k<<<(NLAYERS * NMAT * 16384 + 255) / 256, 256>>>(We2, Wx1, We1, Wh1, Wh2);

    for (int l = 0; l < NLAYERS; l++) {
        const float* We1l = We1 + (size_t)l * 259 * 128;
        const float* be1l = be1 + l * 128;
        const float* be2l = be2 + l * 128;
        const float* bx1l = bx1 + l * 128;
        const float* Wx2l = Wx2 + (size_t)l * 128 * 3;
        const float* bx2l = bx2 + l * 3;
        const float* bh1l = bh1 + l * 128;
        const float* bh2l = bh2 + l * 128;
        const __nv_bfloat16* wbhi_l = pWbhi + (size_t)l * NMAT * 16384;
        const __nv_bfloat16* wblo_l = pWblo + (size_t)l * NMAT * 16384;

        proj_tc_k<<<NODE_TILES, 256, PROJ_SMEM>>>(
            pV, wbhi_l + 2 * 16384, wblo_l + 2 * 16384, pVH, pVraw, N_NODES);

        edge_mma_k<<<EDGE_TILES, 512, EDGE_SMEM>>>(
            srcv, dstv, emb_edges, pVH, pVraw,
            We1l + 256 * 128, be1l, be2l, bx1l, Wx2l, bx2l,
            wbhi_l, wblo_l,
            (l == NLAYERS - 1) ? 1 : 0);

        node_fused_tc_k<<<NODE_TILES, 256, NODE_SMEM>>>(
            pV, pMi, wbhi_l, wblo_l, bh1l, bh2l,
            pVraw, pPartN, N_NODES, NODE_TILES);

        bn_stats2_k<<<1, 128>>>(pPartN, NODE_TILES, N_NODES);
        float* vdst = (l == NLAYERS - 1) ? outV : pV;
        bn_norm_k<<<nodeHBlocks, TB>>>(pVraw, gam_n + l * 128, bet_n + l * 128,
                                       vdst, N_NODES);

        if (l == NLAYERS - 1) {
            bn_stats2_k<<<1, 128>>>(pPartE, EDGE_TILES, N_EDGES);
            bn_norm_k<<<edgeHBlocks, TB>>>(pMij, gam_e + l * 128, bet_e + l * 128,
                                           outE, N_EDGES);
        }
    }
}

// round 17
// speedup vs baseline: 2.7010x; 1.0474x over previous
#include <cuda_runtime.h>
#include <cuda_bf16.h>
#include <math.h>
#include <stdint.h>

#define N_NODES 10000
#define N_EDGES 160000
#define HDIM    128
#define NLAYERS 3
#define BN_EPS  1e-5f

#define EDGE_CTA   256
#define EDGE_TILES (N_EDGES / EDGE_CTA)    // 625
#define NODE_TILES ((N_NODES + 127) / 128) // 79
#define NMAT 7

#define TROW 272
#define A_TILE_BYTES  (256 * TROW)
#define B_TILE_BYTES  (128 * TROW)
#define A128_TILE     (128 * TROW)         // 34816

// ---------------- device scratch ----------------
__device__ float g_coords[N_NODES * 3];
__device__ float g_V[N_NODES * HDIM];
__device__ float g_Vraw[N_NODES * HDIM];
__device__ float g_VH[N_NODES * HDIM];
__device__ float g_mi[N_NODES * HDIM];
__device__ float g_accum[N_NODES * 3];
__device__ float g_mij[N_EDGES * HDIM];
__device__ float g_partE[2 * EDGE_TILES * HDIM];
__device__ float g_partN[2 * 80 * HDIM];
__device__ float g_muinv[2 * HDIM];
__device__ __nv_bfloat16 g_wbhi[NLAYERS * NMAT * 16384];
__device__ __nv_bfloat16 g_wblo[NLAYERS * NMAT * 16384];

__device__ __forceinline__ float silu_f(float x) {
    return x * __fdividef(1.0f, 1.0f + __expf(-x));
}
__device__ __forceinline__ float elu_f(float x) {
    return x > 0.0f ? x : (__expf(x) - 1.0f);
}

__device__ __forceinline__ void red_add_v2(float* addr, float x, float y) {
    asm volatile("red.global.add.v2.f32 [%0], {%1,%2};"
                 :: "l"(addr), "f"(x), "f"(y) : "memory");
}
__device__ __forceinline__ uint32_t pk_bf2(float x, float y) {
    __nv_bfloat162 t = __floats2bfloat162_rn(x, y);
    return *(uint32_t*)&t;
}
__device__ __forceinline__ float bf_hi(float x) {
    return __bfloat162float(__float2bfloat16(x));
}

__device__ __forceinline__ void mma16816(float* d, uint32_t a0, uint32_t a1,
                                         uint32_t a2, uint32_t a3,
                                         uint32_t b0, uint32_t b1) {
    asm("mma.sync.aligned.m16n8k16.row.col.f32.bf16.bf16.f32 "
        "{%0,%1,%2,%3}, {%4,%5,%6,%7}, {%8,%9}, {%0,%1,%2,%3};"
        : "+f"(d[0]), "+f"(d[1]), "+f"(d[2]), "+f"(d[3])
        : "r"(a0), "r"(a1), "r"(a2), "r"(a3), "r"(b0), "r"(b1));
}
__device__ __forceinline__ void ldsm4(uint32_t* r, uint32_t addr) {
    asm volatile("ldmatrix.sync.aligned.m8n8.x4.shared.b16 {%0,%1,%2,%3}, [%4];"
        : "=r"(r[0]), "=r"(r[1]), "=r"(r[2]), "=r"(r[3]) : "r"(addr));
}
__device__ __forceinline__ void cp16(uint32_t dst, const void* src) {
    asm volatile("cp.async.cg.shared.global [%0], [%1], 16;"
                 :: "r"(dst), "l"(src) : "memory");
}
#define CP_COMMIT() asm volatile("cp.async.commit_group;" ::: "memory")
#define CP_WAIT0()  asm volatile("cp.async.wait_group 0;" ::: "memory")

// warp GEMM 16 rows x 128 cols, K=128, bf16 split-3
__device__ __forceinline__ void warp_gemm3(float (&acc)[16][4],
                                           uint32_t AhS, uint32_t AlS,
                                           uint32_t BhS, uint32_t BlS,
                                           int aoff, int boff)
{
#pragma unroll
    for (int i = 0; i < 16; i++)
#pragma unroll
        for (int j = 0; j < 4; j++) acc[i][j] = 0.f;

#pragma unroll 2
    for (int ks = 0; ks < 8; ks++) {
        uint32_t ah[4], al[4];
        ldsm4(ah, AhS + aoff + ks * 32);
        ldsm4(al, AlS + aoff + ks * 32);
        const uint32_t bhb = BhS + boff + ks * 32;
        const uint32_t blb = BlS + boff + ks * 32;
#pragma unroll
        for (int ntp = 0; ntp < 8; ntp++) {
            uint32_t bh[4], bl[4];
            ldsm4(bh, bhb + ntp * 16 * TROW);
            ldsm4(bl, blb + ntp * 16 * TROW);
            mma16816(acc[2 * ntp],     ah[0], ah[1], ah[2], ah[3], bh[0], bh[1]);
            mma16816(acc[2 * ntp + 1], ah[0], ah[1], ah[2], ah[3], bh[2], bh[3]);
            mma16816(acc[2 * ntp],     al[0], al[1], al[2], al[3], bh[0], bh[1]);
            mma16816(acc[2 * ntp + 1], al[0], al[1], al[2], al[3], bh[2], bh[3]);
            mma16816(acc[2 * ntp],     ah[0], ah[1], ah[2], ah[3], bl[0], bl[1]);
            mma16816(acc[2 * ntp + 1], ah[0], ah[1], ah[2], ah[3], bl[2], bl[3]);
        }
    }
}

// warp GEMM 16 rows x 64 cols, K=128, bf16 split-3, optional accumulate
__device__ __forceinline__ void wg3h(float (&acc)[8][4],
                                     uint32_t AhS, uint32_t AlS,
                                     uint32_t BhS, uint32_t BlS,
                                     int aoff, int boff, bool first)
{
    if (first) {
#pragma unroll
        for (int i = 0; i < 8; i++)
#pragma unroll
            for (int j = 0; j < 4; j++) acc[i][j] = 0.f;
    }
#pragma unroll 2
    for (int ks = 0; ks < 8; ks++) {
        uint32_t ah[4], al[4];
        ldsm4(ah, AhS + aoff + ks * 32);
        ldsm4(al, AlS + aoff + ks * 32);
        const uint32_t bhb = BhS + boff + ks * 32;
        const uint32_t blb = BlS + boff + ks * 32;
#pragma unroll
        for (int ntp = 0; ntp < 4; ntp++) {
            uint32_t bh[4], bl[4];
            ldsm4(bh, bhb + ntp * 16 * TROW);
            ldsm4(bl, blb + ntp * 16 * TROW);
            mma16816(acc[2 * ntp],     ah[0], ah[1], ah[2], ah[3], bh[0], bh[1]);
            mma16816(acc[2 * ntp + 1], ah[0], ah[1], ah[2], ah[3], bh[2], bh[3]);
            mma16816(acc[2 * ntp],     al[0], al[1], al[2], al[3], bh[0], bh[1]);
            mma16816(acc[2 * ntp + 1], al[0], al[1], al[2], al[3], bh[2], bh[3]);
            mma16816(acc[2 * ntp],     ah[0], ah[1], ah[2], ah[3], bl[0], bl[1]);
            mma16816(acc[2 * ntp + 1], ah[0], ah[1], ah[2], ah[3], bl[2], bl[3]);
        }
    }
}

// ---------------- weight pre-convert (7 mats/layer) ----------------
__global__ void convw_k(const float* __restrict__ We2, const float* __restrict__ Wx1,
                        const float* __restrict__ We1, const float* __restrict__ Wh1,
                        const float* __restrict__ Wh2)
{
    int idx = blockIdx.x * 256 + threadIdx.x;
    if (idx >= NLAYERS * NMAT * 16384) return;
    int l = idx / (NMAT * 16384);
    int rest = idx % (NMAT * 16384);
    int m = rest / 16384;
    int e = rest & 16383;
    int n = e >> 7, k = e & 127;
    float x;
    switch (m) {
        case 0: x = We2[(size_t)l * 16384 + k * 128 + n]; break;
        case 1: x = Wx1[(size_t)l * 16384 + k * 128 + n]; break;
        case 2: x = We1[(size_t)l * 259 * 128 + k * 128 + n]; break;
        case 3: x = We1[(size_t)l * 259 * 128 + (128 + k) * 128 + n]; break;
        case 4: x = Wh1[(size_t)l * 256 * 128 + k * 128 + n]; break;
        case 5: x = Wh1[(size_t)l * 256 * 128 + (128 + k) * 128 + n]; break;
        default: x = Wh2[(size_t)l * 16384 + k * 128 + n]; break;
    }
    __nv_bfloat16 h = __float2bfloat16(x);
    __nv_bfloat16 lo = __float2bfloat16(x - __bfloat162float(h));
    g_wbhi[(size_t)(l * NMAT + m) * 16384 + n * 128 + k] = h;
    g_wblo[(size_t)(l * NMAT + m) * 16384 + n * 128 + k] = lo;
}

// ---------------- fused edge pipeline (unchanged from R16) ----------------
__global__ __launch_bounds__(512)
void edge_mma_k(const int* __restrict__ srcv, const int* __restrict__ dstv,
                const float* __restrict__ ee,
                const float* __restrict__ Ps, const float* __restrict__ Pd,
                const float* __restrict__ wex_g, const float* __restrict__ be1,
                const float* __restrict__ be2, const float* __restrict__ bx1,
                const float* __restrict__ Wx2, const float* __restrict__ bx2,
                const __nv_bfloat16* __restrict__ WBhi,
                const __nv_bfloat16* __restrict__ WBlo,
                int write_mij)
{
    extern __shared__ char smc[];
    float* smf = (float*)smc;
    float* diffs = smf + 0;
    float* dists = smf + 768;
    int*   dsts  = (int*)(smf + 1024);
    float* ee0s  = smf + 1280;
    float* ee1s  = smf + 1536;
    float* wex   = smf + 1792;
    float* be1s  = smf + 2176;
    float* be2s  = smf + 2304;
    float* bx1s  = smf + 2432;
    float* wx2s  = smf + 2560;
    float* bx2s  = smf + 2944;
    float* es    = smf + 2948;
    char* Ah = smc + 12816;
    char* Al = Ah + A_TILE_BYTES;
    char* Bh = Al + A_TILE_BYTES;
    char* Bl = Bh + B_TILE_BYTES;

    const int tid  = threadIdx.x;
    const int wid  = tid >> 5;
    const int lane = tid & 31;
    const int g    = lane >> 2;
    const int q    = lane & 3;
    const int m0   = blockIdx.x * EDGE_CTA;

    const uint32_t AhS = (uint32_t)__cvta_generic_to_shared(Ah);
    const uint32_t AlS = (uint32_t)__cvta_generic_to_shared(Al);
    const uint32_t BhS = (uint32_t)__cvta_generic_to_shared(Bh);
    const uint32_t BlS = (uint32_t)__cvta_generic_to_shared(Bl);

    {
        const char* shi = (const char*)WBhi;
        const char* slo = (const char*)WBlo;
#pragma unroll
        for (int i = 0; i < 4; i++) {
            int p = tid + i * 512;
            int row = p >> 4, chunk = p & 15;
            uint32_t off = row * TROW + chunk * 16;
            cp16(BhS + off, shi + p * 16);
            cp16(BlS + off, slo + p * 16);
        }
        CP_COMMIT();
    }

    if (tid < 256) {
        int mm = m0 + tid;
        int s = srcv[mm], d = dstv[mm];
        float dx = g_coords[d * 3 + 0] - g_coords[s * 3 + 0];
        float dy = g_coords[d * 3 + 1] - g_coords[s * 3 + 1];
        float dz = g_coords[d * 3 + 2] - g_coords[s * 3 + 2];
        diffs[tid * 3 + 0] = dx;
        diffs[tid * 3 + 1] = dy;
        diffs[tid * 3 + 2] = dz;
        dists[tid] = sqrtf(dx * dx + dy * dy + dz * dz);
        dsts[tid] = d;
        ee0s[tid] = ee[mm * 2 + 0];
        ee1s[tid] = ee[mm * 2 + 1];
        es[tid] = 0.f;
    }
    if (tid < 128) { be1s[tid] = be1[tid]; be2s[tid] = be2[tid]; bx1s[tid] = bx1[tid]; }
    for (int i = tid; i < 384; i += 512) { wex[i] = wex_g[i]; wx2s[i] = Wx2[i]; }
    if (tid < 3) bx2s[tid] = bx2[tid];
    __syncthreads();

    {
        const int r  = tid >> 1;
        const int cb = (tid & 1) * 64;
        const int mm = m0 + r;
        const int s  = srcv[mm];
        const float* psp = Ps + (size_t)s * 128;
        const float* pdp = Pd + (size_t)dsts[r] * 128;
        const float di = dists[r];
        const float e0 = ee0s[r], e1 = ee1s[r];
        for (int c = cb; c < cb + 64; c += 8) {
            float o[8];
#pragma unroll
            for (int h = 0; h < 8; h += 4) {
                float4 a = *(const float4*)(psp + c + h);
                float4 b = *(const float4*)(pdp + c + h);
                o[h+0] = silu_f(a.x + b.x + di * wex[c+h+0] + e0 * wex[128+c+h+0] + e1 * wex[256+c+h+0] + be1s[c+h+0]);
                o[h+1] = silu_f(a.y + b.y + di * wex[c+h+1] + e0 * wex[128+c+h+1] + e1 * wex[256+c+h+1] + be1s[c+h+1]);
                o[h+2] = silu_f(a.z + b.z + di * wex[c+h+2] + e0 * wex[128+c+h+2] + e1 * wex[256+c+h+2] + be1s[c+h+2]);
                o[h+3] = silu_f(a.w + b.w + di * wex[c+h+3] + e0 * wex[128+c+h+3] + e1 * wex[256+c+h+3] + be1s[c+h+3]);
            }
            uint32_t H[4], L[4];
#pragma unroll
            for (int j = 0; j < 4; j++) {
                float hx = bf_hi(o[2*j]), hy = bf_hi(o[2*j+1]);
                H[j] = pk_bf2(o[2*j], o[2*j+1]);
                L[j] = pk_bf2(o[2*j] - hx, o[2*j+1] - hy);
            }
            *(uint4*)(Ah + r * TROW + c * 2) = *(uint4*)H;
            *(uint4*)(Al + r * TROW + c * 2) = *(uint4*)L;
        }
    }
    CP_WAIT0();
    __syncthreads();

    const int arow = wid * 16 + (lane & 7) + ((lane & 8) ? 8 : 0);
    const int aoff = arow * TROW + ((lane >> 4) & 1) * 16;
    const int brow = (lane & 7) + (((lane >> 4) & 1) << 3);
    const int boff = brow * TROW + ((lane & 8) ? 16 : 0);

    const int r0 = wid * 16 + g, r1 = r0 + 8;

    float acc[16][4];

    warp_gemm3(acc, AhS, AlS, BhS, BlS, aoff, boff);

    {
        const int d0 = dsts[r0], d1 = dsts[r1];
#pragma unroll
        for (int nt = 0; nt < 16; nt++) {
            const int c = nt * 8 + q * 2;
            float v00 = silu_f(acc[nt][0] + be2s[c]);
            float v01 = silu_f(acc[nt][1] + be2s[c + 1]);
            float v10 = silu_f(acc[nt][2] + be2s[c]);
            float v11 = silu_f(acc[nt][3] + be2s[c + 1]);
            red_add_v2(&g_mi[(size_t)d0 * 128 + c], v00, v01);
            red_add_v2(&g_mi[(size_t)d1 * 128 + c], v10, v11);
            if (write_mij) {
                *(float2*)(g_mij + (size_t)(m0 + r0) * 128 + c) = make_float2(v00, v01);
                *(float2*)(g_mij + (size_t)(m0 + r1) * 128 + c) = make_float2(v10, v11);
                float e00 = elu_f(v00), e01 = elu_f(v01);
                float e10 = elu_f(v10), e11 = elu_f(v11);
                float s0 = e00 + e10, s1 = e01 + e11;
                float q0 = e00 * e00 + e10 * e10, q1 = e01 * e01 + e11 * e11;
#pragma unroll
                for (int o = 4; o < 32; o <<= 1) {
                    s0 += __shfl_xor_sync(0xFFFFFFFF, s0, o);
                    s1 += __shfl_xor_sync(0xFFFFFFFF, s1, o);
                    q0 += __shfl_xor_sync(0xFFFFFFFF, q0, o);
                    q1 += __shfl_xor_sync(0xFFFFFFFF, q1, o);
                }
                if (lane < 4) {
                    atomicAdd(&es[c], s0);
                    atomicAdd(&es[c + 1], s1);
                    atomicAdd(&es[128 + c], q0);
                    atomicAdd(&es[128 + c + 1], q1);
                }
            }
            float h00 = bf_hi(v00), h01 = bf_hi(v01);
            float h10 = bf_hi(v10), h11 = bf_hi(v11);
            *(uint32_t*)(Ah + r0 * TROW + c * 2) = pk_bf2(v00, v01);
            *(uint32_t*)(Ah + r1 * TROW + c * 2) = pk_bf2(v10, v11);
            *(uint32_t*)(Al + r0 * TROW + c * 2) = pk_bf2(v00 - h00, v01 - h01);
            *(uint32_t*)(Al + r1 * TROW + c * 2) = pk_bf2(v10 - h10, v11 - h11);
        }
    }
    __syncthreads();
    {
        const char* shi = (const char*)(WBhi + 16384);
        const char* slo = (const char*)(WBlo + 16384);
#pragma unroll
        for (int i = 0; i < 4; i++) {
            int p = tid + i * 512;
            int row = p >> 4, chunk = p & 15;
            uint32_t off = row * TROW + chunk * 16;
            cp16(BhS + off, shi + p * 16);
            cp16(BlS + off, slo + p * 16);
        }
        CP_COMMIT();
    }
    if (write_mij && tid < 128) {
        g_partE[blockIdx.x * 128 + tid] = es[tid];
        g_partE[(EDGE_TILES + blockIdx.x) * 128 + tid] = es[128 + tid];
    }
    CP_WAIT0();
    __syncthreads();

    warp_gemm3(acc, AhS, AlS, BhS, BlS, aoff, boff);

    {
        float pa0 = 0.f, pa1 = 0.f, pa2 = 0.f;
        float pb0 = 0.f, pb1 = 0.f, pb2 = 0.f;
#pragma unroll
        for (int nt = 0; nt < 16; nt++) {
            const int c = nt * 8 + q * 2;
            float t00 = silu_f(acc[nt][0] + bx1s[c]);
            float t01 = silu_f(acc[nt][1] + bx1s[c + 1]);
            float t10 = silu_f(acc[nt][2] + bx1s[c]);
            float t11 = silu_f(acc[nt][3] + bx1s[c + 1]);
            float w00 = wx2s[c * 3 + 0], w01 = wx2s[c * 3 + 1], w02 = wx2s[c * 3 + 2];
            float w10 = wx2s[c * 3 + 3], w11 = wx2s[c * 3 + 4], w12 = wx2s[c * 3 + 5];
            pa0 += t00 * w00 + t01 * w10;
            pa1 += t00 * w01 + t01 * w11;
            pa2 += t00 * w02 + t01 * w12;
            pb0 += t10 * w00 + t11 * w10;
            pb1 += t10 * w01 + t11 * w11;
            pb2 += t10 * w02 + t11 * w12;
        }
#pragma unroll
        for (int o = 1; o < 4; o <<= 1) {
            pa0 += __shfl_xor_sync(0xFFFFFFFF, pa0, o);
            pa1 += __shfl_xor_sync(0xFFFFFFFF, pa1, o);
            pa2 += __shfl_xor_sync(0xFFFFFFFF, pa2, o);
            pb0 += __shfl_xor_sync(0xFFFFFFFF, pb0, o);
            pb1 += __shfl_xor_sync(0xFFFFFFFF, pb1, o);
            pb2 += __shfl_xor_sync(0xFFFFFFFF, pb2, o);
        }
        if (q == 0) {
            const int d0 = dsts[r0], d1 = dsts[r1];
            float x0 = pa0 + bx2s[0], x1 = pa1 + bx2s[1], x2 = pa2 + bx2s[2];
            atomicAdd(&g_accum[d0 * 3 + 0], diffs[r0 * 3 + 0] * x0);
            atomicAdd(&g_accum[d0 * 3 + 1], diffs[r0 * 3 + 1] * x1);
            atomicAdd(&g_accum[d0 * 3 + 2], diffs[r0 * 3 + 2] * x2);
            float y0 = pb0 + bx2s[0], y1 = pb1 + bx2s[1], y2 = pb2 + bx2s[2];
            atomicAdd(&g_accum[d1 * 3 + 0], diffs[r1 * 3 + 0] * y0);
            atomicAdd(&g_accum[d1 * 3 + 1], diffs[r1 * 3 + 1] * y1);
            atomicAdd(&g_accum[d1 * 3 + 2], diffs[r1 * 3 + 2] * y2);
        }
    }
}

// ---------------- proj_tc_k: 512 thr, 128 rows/CTA, fused BN of prev layer --
// smem: Ah 0 | Al 34816 | Bh 69632 (256 rows) | Bl 139264 ; total 208896
__global__ __launch_bounds__(512)
void proj_tc_k(const float* __restrict__ Vin,   // V (bn=0) or Vraw (bn=1)
               const __nv_bfloat16* __restrict__ WBhi,
               const __nv_bfloat16* __restrict__ WBlo,
               float* __restrict__ Ps, float* __restrict__ Pd,
               float* __restrict__ Vout,        // written when bn=1
               const float* __restrict__ gam, const float* __restrict__ bet,
               int bn, int M)
{
    extern __shared__ char smc[];
    char* Ah = smc;
    char* Al = smc + A128_TILE;
    char* Bh = smc + 2 * A128_TILE;
    char* Bl = Bh + 2 * B_TILE_BYTES;

    const int tid  = threadIdx.x;
    const int wid  = tid >> 5;
    const int lane = tid & 31;
    const int g    = lane >> 2;
    const int q    = lane & 3;
    const int rg   = wid >> 1;   // 0..7
    const int out  = wid & 1;
    const int mb   = blockIdx.x * 128;

    const uint32_t AhS = (uint32_t)__cvta_generic_to_shared(Ah);
    const uint32_t AlS = (uint32_t)__cvta_generic_to_shared(Al);
    const uint32_t BhS = (uint32_t)__cvta_generic_to_shared(Bh);
    const uint32_t BlS = (uint32_t)__cvta_generic_to_shared(Bl);

    // cp.async B (256 rows hi+lo) = 4096 uint4 each
    {
        const char* shi = (const char*)WBhi;
        const char* slo = (const char*)WBlo;
#pragma unroll
        for (int i = 0; i < 8; i++) {
            int p = tid + i * 512;
            int row = p >> 4, chunk = p & 15;
            uint32_t off = row * TROW + chunk * 16;
            cp16(BhS + off, shi + p * 16);
            cp16(BlS + off, slo + p * 16);
        }
        CP_COMMIT();
    }

    // zero g_mi / g_accum for this CTA's 128 rows
    {
        int r = tid >> 2, c = (tid & 3) * 32;
        if (mb + r < M) {
            float4 z = make_float4(0.f, 0.f, 0.f, 0.f);
            float* p = g_mi + (size_t)(mb + r) * 128 + c;
#pragma unroll
            for (int j = 0; j < 8; j++) *(float4*)(p + j * 4) = z;
        }
        if (tid < 384 && mb + tid / 3 < M)
            g_accum[(size_t)mb * 3 + tid] = 0.f;
    }

    // A conversion (optionally applying BN of previous layer)
    {
        const int r  = tid >> 2;          // 0..127
        const int cb = (tid & 3) * 32;
        const int gm = mb + r;
        for (int c = cb; c < cb + 32; c += 8) {
            float o[8];
            if (gm < M) {
                *(float4*)o       = *(const float4*)(Vin + (size_t)gm * 128 + c);
                *(float4*)(o + 4) = *(const float4*)(Vin + (size_t)gm * 128 + c + 4);
                if (bn) {
#pragma unroll
                    for (int j = 0; j < 8; j++) {
                        int col = c + j;
                        float x = elu_f(o[j]);
                        x = gam[col] * (x - g_muinv[col]) * g_muinv[128 + col] + bet[col];
                        o[j] = x;
                    }
                    *(float4*)(Vout + (size_t)gm * 128 + c)     = *(float4*)o;
                    *(float4*)(Vout + (size_t)gm * 128 + c + 4) = *(float4*)(o + 4);
                }
            } else {
#pragma unroll
                for (int j = 0; j < 8; j++) o[j] = 0.f;
            }
            uint32_t H[4], L[4];
#pragma unroll
            for (int j = 0; j < 4; j++) {
                float hx = bf_hi(o[2*j]), hy = bf_hi(o[2*j+1]);
                H[j] = pk_bf2(o[2*j], o[2*j+1]);
                L[j] = pk_bf2(o[2*j] - hx, o[2*j+1] - hy);
            }
            *(uint4*)(Ah + r * TROW + c * 2) = *(uint4*)H;
            *(uint4*)(Al + r * TROW + c * 2) = *(uint4*)L;
        }
    }
    CP_WAIT0();
    __syncthreads();

    const int arow = rg * 16 + (lane & 7) + ((lane & 8) ? 8 : 0);
    const int aoff = arow * TROW + ((lane >> 4) & 1) * 16;
    const int brow = (lane & 7) + (((lane >> 4) & 1) << 3);
    const int boff = (out * 128 + brow) * TROW + ((lane & 8) ? 16 : 0);

    float acc[16][4];
    warp_gemm3(acc, AhS, AlS, BhS, BlS, aoff, boff);

    float* O = out ? Pd : Ps;
    const int gr0 = mb + rg * 16 + g, gr1 = gr0 + 8;
#pragma unroll
    for (int nt = 0; nt < 16; nt++) {
        const int c = nt * 8 + q * 2;
        if (gr0 < M) *(float2*)(O + (size_t)gr0 * 128 + c) = make_float2(acc[nt][0], acc[nt][1]);
        if (gr1 < M) *(float2*)(O + (size_t)gr1 * 128 + c) = make_float2(acc[nt][2], acc[nt][3]);
    }
}

// ---------------- node_fused_tc_k: 512 thr, 128 rows/CTA --------------------
// smem: A0h 0 | A0l | A1h | A1l (4 x 34816) | Bh 139264 | Bl 174080 |
//       bh1s @208896 | bh2s @209408 | es @209920 ; total 210944
__global__ __launch_bounds__(512)
void node_fused_tc_k(const float* __restrict__ V, const float* __restrict__ mi,
                     const __nv_bfloat16* __restrict__ WBhi,
                     const __nv_bfloat16* __restrict__ WBlo,
                     const float* __restrict__ bh1, const float* __restrict__ bh2,
                     float* __restrict__ Vraw, float* __restrict__ part,
                     int M, int nblk)
{
    extern __shared__ char smc[];
    char* A0h = smc;
    char* A0l = smc + A128_TILE;
    char* A1h = smc + 2 * A128_TILE;
    char* A1l = smc + 3 * A128_TILE;
    char* Bh  = smc + 4 * A128_TILE;
    char* Bl  = Bh + B_TILE_BYTES;
    float* bh1s = (float*)(smc + 208896);
    float* bh2s = (float*)(smc + 209408);
    float* es   = (float*)(smc + 209920);

    const int tid  = threadIdx.x;
    const int wid  = tid >> 5;       // 0..15
    const int lane = tid & 31;
    const int g    = lane >> 2;
    const int q    = lane & 3;
    const int rg   = wid >> 1;       // 0..7
    const int nh   = wid & 1;
    const int mb   = blockIdx.x * 128;

    const uint32_t A0hS = (uint32_t)__cvta_generic_to_shared(A0h);
    const uint32_t A0lS = (uint32_t)__cvta_generic_to_shared(A0l);
    const uint32_t A1hS = (uint32_t)__cvta_generic_to_shared(A1h);
    const uint32_t A1lS = (uint32_t)__cvta_generic_to_shared(A1l);
    const uint32_t BhS  = (uint32_t)__cvta_generic_to_shared(Bh);
    const uint32_t BlS  = (uint32_t)__cvta_generic_to_shared(Bl);

    // cp.async Wh1t chunk0 (2048 uint4 each)
    {
        const char* shi = (const char*)(WBhi + 4 * 16384);
        const char* slo = (const char*)(WBlo + 4 * 16384);
#pragma unroll
        for (int i = 0; i < 4; i++) {
            int p = tid + i * 512;
            int row = p >> 4, chunk = p & 15;
            uint32_t off = row * TROW + chunk * 16;
            cp16(BhS + off, shi + p * 16);
            cp16(BlS + off, slo + p * 16);
        }
        CP_COMMIT();
    }

    if (tid < 128) { bh1s[tid] = bh1[tid]; bh2s[tid] = bh2[tid]; }
    if (tid < 256) es[tid] = 0.f;

    // fused coords update: coords += accum / (N-1)
    {
        int idx = blockIdx.x * 384 + tid;
        if (tid < 384 && idx < N_NODES * 3)
            g_coords[idx] += g_accum[idx] * (1.0f / (float)(N_NODES - 1));
    }

    // A0 <- V, A1 <- mi
    {
        const int r  = tid >> 2;         // 0..127
        const int cb = (tid & 3) * 32;
        const int gm = mb + r;
        for (int c = cb; c < cb + 32; c += 8) {
            float o0[8], o1[8];
            if (gm < M) {
                *(float4*)o0       = *(const float4*)(V + (size_t)gm * 128 + c);
                *(float4*)(o0 + 4) = *(const float4*)(V + (size_t)gm * 128 + c + 4);
                *(float4*)o1       = *(const float4*)(mi + (size_t)gm * 128 + c);
                *(float4*)(o1 + 4) = *(const float4*)(mi + (size_t)gm * 128 + c + 4);
            } else {
#pragma unroll
                for (int j = 0; j < 8; j++) { o0[j] = 0.f; o1[j] = 0.f; }
            }
            uint32_t H[4], L[4];
#pragma unroll
            for (int j = 0; j < 4; j++) {
                float hx = bf_hi(o0[2*j]), hy = bf_hi(o0[2*j+1]);
                H[j] = pk_bf2(o0[2*j], o0[2*j+1]);
                L[j] = pk_bf2(o0[2*j] - hx, o0[2*j+1] - hy);
            }
            *(uint4*)(A0h + r * TROW + c * 2) = *(uint4*)H;
            *(uint4*)(A0l + r * TROW + c * 2) = *(uint4*)L;
#pragma unroll
            for (int j = 0; j < 4; j++) {
                float hx = bf_hi(o1[2*j]), hy = bf_hi(o1[2*j+1]);
                H[j] = pk_bf2(o1[2*j], o1[2*j+1]);
                L[j] = pk_bf2(o1[2*j] - hx, o1[2*j+1] - hy);
            }
            *(uint4*)(A1h + r * TROW + c * 2) = *(uint4*)H;
            *(uint4*)(A1l + r * TROW + c * 2) = *(uint4*)L;
        }
    }
    CP_WAIT0();
    __syncthreads();

    const int arow = rg * 16 + (lane & 7) + ((lane & 8) ? 8 : 0);
    const int aoff = arow * TROW + ((lane >> 4) & 1) * 16;
    const int brow = (lane & 7) + (((lane >> 4) & 1) << 3);
    const int boff = (nh * 64 + brow) * TROW + ((lane & 8) ? 16 : 0);

    const int r0 = rg * 16 + g, r1 = r0 + 8;

    float acc[8][4];

    wg3h(acc, A0hS, A0lS, BhS, BlS, aoff, boff, true);
    __syncthreads();
    {
        const char* shi = (const char*)(WBhi + 5 * 16384);
        const char* slo = (const char*)(WBlo + 5 * 16384);
#pragma unroll
        for (int i = 0; i < 4; i++) {
            int p = tid + i * 512;
            int row = p >> 4, chunk = p & 15;
            uint32_t off = row * TROW + chunk * 16;
            cp16(BhS + off, shi + p * 16);
            cp16(BlS + off, slo + p * 16);
        }
        CP_COMMIT();
        CP_WAIT0();
    }
    __syncthreads();
    wg3h(acc, A1hS, A1lS, BhS, BlS, aoff, boff, false);

#pragma unroll
    for (int nt = 0; nt < 8; nt++) {
        const int c = nh * 64 + nt * 8 + q * 2;
        float v00 = silu_f(acc[nt][0] + bh1s[c]);
        float v01 = silu_f(acc[nt][1] + bh1s[c + 1]);
        float v10 = silu_f(acc[nt][2] + bh1s[c]);
        float v11 = silu_f(acc[nt][3] + bh1s[c + 1]);
        float h00 = bf_hi(v00), h01 = bf_hi(v01);
        float h10 = bf_hi(v10), h11 = bf_hi(v11);
        *(uint32_t*)(A0h + r0 * TROW + c * 2) = pk_bf2(v00, v01);
        *(uint32_t*)(A0h + r1 * TROW + c * 2) = pk_bf2(v10, v11);
        *(uint32_t*)(A0l + r0 * TROW + c * 2) = pk_bf2(v00 - h00, v01 - h01);
        *(uint32_t*)(A0l + r1 * TROW + c * 2) = pk_bf2(v10 - h10, v11 - h11);
    }
    __syncthreads();
    {
        const char* shi = (const char*)(WBhi + 6 * 16384);
        const char* slo = (const char*)(WBlo + 6 * 16384);
#pragma unroll
        for (int i = 0; i < 4; i++) {
            int p = tid + i * 512;
            int row = p >> 4, chunk = p & 15;
            uint32_t off = row * TROW + chunk * 16;
            cp16(BhS + off, shi + p * 16);
            cp16(BlS + off, slo + p * 16);
        }
        CP_COMMIT();
        CP_WAIT0();
    }
    __syncthreads();

    wg3h(acc, A0hS, A0lS, BhS, BlS, aoff, boff, true);

    {
        const int gr0 = mb + r0, gr1 = mb + r1;
        const bool ok0 = (gr0 < M), ok1 = (gr1 < M);
#pragma unroll
        for (int nt = 0; nt < 8; nt++) {
            const int c = nh * 64 + nt * 8 + q * 2;
            float v00 = acc[nt][0] + bh2s[c];
            float v01 = acc[nt][1] + bh2s[c + 1];
            float v10 = acc[nt][2] + bh2s[c];
            float v11 = acc[nt][3] + bh2s[c + 1];
            float s0 = 0.f, s1 = 0.f, q0 = 0.f, q1 = 0.f;
            if (ok0) {
                *(float2*)(Vraw + (size_t)gr0 * 128 + c) = make_float2(v00, v01);
                float e0 = elu_f(v00), e1 = elu_f(v01);
                s0 += e0; s1 += e1; q0 += e0 * e0; q1 += e1 * e1;
            }
            if (ok1) {
                *(float2*)(Vraw + (size_t)gr1 * 128 + c) = make_float2(v10, v11);
                float e0 = elu_f(v10), e1 = elu_f(v11);
                s0 += e0; s1 += e1; q0 += e0 * e0; q1 += e1 * e1;
            }
#pragma unroll
            for (int o = 4; o < 32; o <<= 1) {
                s0 += __shfl_xor_sync(0xFFFFFFFF, s0, o);
                s1 += __shfl_xor_sync(0xFFFFFFFF, s1, o);
                q0 += __shfl_xor_sync(0xFFFFFFFF, q0, o);
                q1 += __shfl_xor_sync(0xFFFFFFFF, q1, o);
            }
            if (lane < 4) {
                atomicAdd(&es[c], s0);
                atomicAdd(&es[c + 1], s1);
                atomicAdd(&es[128 + c], q0);
                atomicAdd(&es[128 + c + 1], q1);
            }
        }
    }
    __syncthreads();
    if (tid < 128) {
        part[blockIdx.x * 128 + tid] = es[tid];
        part[(nblk + blockIdx.x) * 128 + tid] = es[128 + tid];
    }
}

// ---------------- small kernels ----------------
__global__ void init_nodes_k(const float* __restrict__ emb,
                             const float* __restrict__ Wn,
                             const float* __restrict__ bn)
{
    int idx = blockIdx.x * blockDim.x + threadIdx.x;
    if (idx < N_NODES * 3) g_coords[idx] = emb[idx];
    if (idx < N_NODES * HDIM) {
        int n = idx >> 7, j = idx & 127;
        g_V[idx] = emb[n * 3 + 0] * Wn[0 * 128 + j]
                 + emb[n * 3 + 1] * Wn[1 * 128 + j]
                 + emb[n * 3 + 2] * Wn[2 * 128 + j]
                 + bn[j];
    }
}

__global__ void bn_stats2_k(const float* __restrict__ part, int B, int M)
{
    int j = threadIdx.x;
    double s = 0.0, q = 0.0;
    for (int b = 0; b < B; b++) {
        s += (double)part[b * 128 + j];
        q += (double)part[(B + b) * 128 + j];
    }
    double mu  = s / (double)M;
    double var = q / (double)M - mu * mu;
    g_muinv[j]       = (float)mu;
    g_muinv[128 + j] = (float)rsqrt(var + (double)BN_EPS);
}

__global__ void bn_norm_k(const float* __restrict__ X,
                          const float* __restrict__ gam,
                          const float* __restrict__ bet,
                          float* __restrict__ out, int M)
{
    int idx = blockIdx.x * blockDim.x + threadIdx.x;
    if (idx >= M * 128) return;
    int j = idx & 127;
    float x = elu_f(X[idx]);
    out[idx] = gam[j] * (x - g_muinv[j]) * g_muinv[128 + j] + bet[j];
}

// ---------------- host launcher ----------------
static void* sym_addr(const void* sym)
{
    void* p = nullptr;
    cudaGetSymbolAddress(&p, sym);
    return p;
}

extern "C" void kernel_launch(void* const* d_in, const int* in_sizes, int n_in,
                              void* d_out, int out_size)
{
    (void)in_sizes; (void)n_in; (void)out_size;

    const float* emb_nodes = (const float*)d_in[0];
    const float* emb_edges = (const float*)d_in[1];
    const int*   edge_idx  = (const int*)d_in[2];
    const float* pre_Wn    = (const float*)d_in[3];
    const float* pre_bn    = (const float*)d_in[4];
    const float* We1 = (const float*)d_in[7];
    const float* be1 = (const float*)d_in[8];
    const float* We2 = (const float*)d_in[9];
    const float* be2 = (const float*)d_in[10];
    const float* Wx1 = (const float*)d_in[11];
    const float* bx1 = (const float*)d_in[12];
    const float* Wx2 = (const float*)d_in[13];
    const float* bx2 = (const float*)d_in[14];
    const float* Wh1 = (const float*)d_in[15];
    const float* bh1 = (const float*)d_in[16];
    const float* Wh2 = (const float*)d_in[17];
    const float* bh2 = (const float*)d_in[18];
    const float* gam_n = (const float*)d_in[19];
    const float* bet_n = (const float*)d_in[20];
    const float* gam_e = (const float*)d_in[21];
    const float* bet_e = (const float*)d_in[22];

    float* out  = (float*)d_out;
    float* outV = out;
    float* outE = out + (size_t)N_NODES * HDIM;

    const int* srcv = edge_idx;
    const int* dstv = edge_idx + N_EDGES;

    float* pV     = (float*)sym_addr(g_V);
    float* pVraw  = (float*)sym_addr(g_Vraw);
    float* pVH    = (float*)sym_addr(g_VH);
    float* pMi    = (float*)sym_addr(g_mi);
    float* pMij   = (float*)sym_addr(g_mij);
    float* pPartE = (float*)sym_addr(g_partE);
    float* pPartN = (float*)sym_addr(g_partN);
    __nv_bfloat16* pWbhi = (__nv_bfloat16*)sym_addr(g_wbhi);
    __nv_bfloat16* pWblo = (__nv_bfloat16*)sym_addr(g_wblo);

    const int EDGE_SMEM = 12816 + 2 * A_TILE_BYTES + 2 * B_TILE_BYTES;
    const int PROJ_SMEM = 2 * A128_TILE + 4 * B_TILE_BYTES;   // 208896
    const int NODE_SMEM = 210944;
    cudaFuncSetAttribute(edge_mma_k,
                         cudaFuncAttributeMaxDynamicSharedMemorySize, EDGE_SMEM);
    cudaFuncSetAttribute(proj_tc_k,
                         cudaFuncAttributeMaxDynamicSharedMemorySize, PROJ_SMEM);
    cudaFuncSetAttribute(node_fused_tc_k,
                         cudaFuncAttributeMaxDynamicSharedMemorySize, NODE_SMEM);

    const int TB = 256;
    const int nodeHBlocks = (N_NODES * HDIM + TB - 1) / TB;
    const int edgeHBlocks = (N_EDGES * HDIM + TB - 1) / TB;

    init_nodes_k<<<nodeHBlocks, TB>>>(emb_nodes, pre_Wn, pre_bn);
    convw_k<<<(NLAYERS * NMAT * 16384 + 255) / 256, 256>>>(We2, Wx1, We1, Wh1, Wh2);

    for (int l = 0; l < NLAYERS; l++) {
        const float* We1l = We1 + (size_t)l * 259 * 128;
        const float* be1l = be1 + l * 128;
        const float* be2l = be2 + l * 128;
        const float* bx1l = bx1 + l * 128;
        const float* Wx2l = Wx2 + (size_t)l * 128 * 3;
        const float* bx2l = bx2 + l * 3;
        const float* bh1l = bh1 + l * 128;
        const float* bh2l = bh2 + l * 128;
        const __nv_bfloat16* wbhi_l = pWbhi + (size_t)l * NMAT * 16384;
        const __nv_bfloat16* wblo_l = pWblo + (size_t)l * NMAT * 16384;

        if (l == 0) {
            proj_tc_k<<<NODE_TILES, 512, PROJ_SMEM>>>(
                pV, wbhi_l + 2 * 16384, wblo_l + 2 * 16384,
                pVH, pVraw, nullptr, nullptr, nullptr, 0, N_NODES);
        } else {
            // fused: V = BN_{l-1}(elu(Vraw)); Ps/Pd = V @ We1
            proj_tc_k<<<NODE_TILES, 512, PROJ_SMEM>>>(
                pVraw, wbhi_l + 2 * 16384, wblo_l + 2 * 16384,
                pVH, pVraw /*Pd written after read? no: see note*/, pV,
                gam_n + (l - 1) * 128, bet_n + (l - 1) * 128, 1, N_NODES);
        }

        edge_mma_k<<<EDGE_TILES, 512, EDGE_SMEM>>>(
            srcv, dstv, emb_edges, pVH, pVraw,
            We1l + 256 * 128, be1l, be2l, bx1l, Wx2l, bx2l,
            wbhi_l, wblo_l,
            (l == NLAYERS - 1) ? 1 : 0);

        node_fused_tc_k<<<NODE_TILES, 512, NODE_SMEM>>>(
            pV, pMi, wbhi_l, wblo_l, bh1l, bh2l,
            pVraw, pPartN, N_NODES, NODE_TILES);

        bn_stats2_k<<<1, 128>>>(pPartN, NODE_TILES, N_NODES);

        if (l == NLAYERS - 1) {
            bn_norm_k<<<nodeHBlocks, TB>>>(pVraw, gam_n + l * 128, bet_n + l * 128,
                                           outV, N_NODES);
            bn_stats2_k<<<1, 128>>>(pPartE, EDGE_TILES, N_EDGES);
            bn_norm_k<<<edgeHBlocks, TB>>>(pMij, gam_e + l * 128, bet_e + l * 128,
                                           outE, N_EDGES);
        }
    }
}